// round 9
// baseline (speedup 1.0000x reference)
#include <cuda_runtime.h>
#include <cstdint>
#include <math.h>

// ---------------- problem constants ----------------
#define NB   128
#define CCH  256
#define MH_  28
#define MW_  28
#define HW_  784
#define KCLS 80
#define PP   196
#define SH__ 200
#define SW__ 200
#define SPIX 40000          // 200*200
#define SPIXP 40192         // padded to 157*256
#define FCIN 416            // C + 2K
#define NCOL (NB*PP)        // 25088 point-columns
#define NPIX (NB*HW_)       // 100352 instance pixels

// ---------------- scratch (static device globals; no allocation) ----------------
__device__ float g_semFT[(size_t)SPIXP*CCH];   // transposed semantic feat [pix][c]; pad rows stay 0
__device__ float g_semT [(size_t)SPIX*CCH];    // relu(sem conv) [pix][o]
__device__ float g_Ft [(size_t)NPIX*CCH];      // instance feats pixel-major
__device__ float g_X0 [(size_t)NCOL*FCIN];     // MLP ping
__device__ float g_X1 [(size_t)NCOL*FCIN];     // MLP pong
__device__ float g_P  [(size_t)NCOL*CCH];      // point logits
__device__ float g_F  [(size_t)CCH*NPIX];      // fused, channel-major
__device__ int   g_idx[NB*PP];
__device__ int   g_map[NPIX];
__device__ float g_Wid[256*CCH];               // stacked [w_inst; w_det; zeros]
__device__ float g_Bid[256];

// ---------------- tf32 helpers ----------------
__device__ __forceinline__ uint32_t cvt_tf32(float f) {
    uint32_t r; asm("cvt.rna.tf32.f32 %0, %1;" : "=r"(r) : "f"(f)); return r;
}
__device__ __forceinline__ void mma8(float* c,
                                     uint32_t a0, uint32_t a1, uint32_t a2, uint32_t a3,
                                     uint32_t b0, uint32_t b1) {
    asm volatile("mma.sync.aligned.m16n8k8.row.col.f32.tf32.tf32.f32 "
                 "{%0,%1,%2,%3}, {%4,%5,%6,%7}, {%8,%9}, {%0,%1,%2,%3};"
                 : "+f"(c[0]), "+f"(c[1]), "+f"(c[2]), "+f"(c[3])
                 : "r"(a0), "r"(a1), "r"(a2), "r"(a3), "r"(b0), "r"(b1));
}

// ================= tf32 tensor-core TN GEMM v3 =================
// CTA tile 128(M) x 256(N), 8 warps of 64x64, BK=16 (2 k8 groups), double-buffered.
// A row-major [>=128*gridDim.y rows][Kd]; B modes:
//   0: B[col][Kd] stride ldb (rows up to 256*gridDim.x readable)
//   2: row gathered: aux=g_idx, B=g_Ft
//   3: row select: aux=g_map, P=g_P, B=g_Ft
// Kd % 16 == 0, M % 4 == 0.
// STORE_T: C[n*ldc+m] (m,n guarded; C2 optional dup). else C[m*ldc+n] (m guarded, Ncols%256==0).
// SMEM stage (6152 words): A: s*1028 + r*8 + (pos ^ xr), pos(k)=((k&3)<<1)|(k>>2), xr=((r>>2)&1)<<2
//                          B: 2056 + s*2048 + r*8 + (pos ^ xr)
#define STAGE_W 6152
#define MG_SMEM (2*STAGE_W*4)   // 49216 bytes

template<int BMODE, bool STORE_T, bool RELU>
__global__ void __launch_bounds__(256, 1)
mgemm(const float* __restrict__ A, const float* __restrict__ B,
      float* __restrict__ C, float* __restrict__ C2,
      const float* __restrict__ bias,
      const float* __restrict__ P, const int* __restrict__ aux,
      int M, int Kd, int Ncols, int ldb, int ldc)
{
    extern __shared__ uint32_t sh[];
    const int t = threadIdx.x;
    const int rowTile = blockIdx.y * 128;
    const int colTile = blockIdx.x * 256;
    const int lane = t & 31, wid = t >> 5;
    const int wr = wid & 1, wc = wid >> 1;          // warp grid 2(m) x 4(n)
    const int g = lane >> 2, q = lane & 3;
    const uint32_t xq = (uint32_t)(2*q) ^ ((uint32_t)((lane >> 4) & 1) << 2);

    // A: thread covers row t>>1, k8-group t&1
    const int rA = t >> 1;
    const int sA = t & 1;
    const uint32_t aXr = ((rA >> 2) & 1) << 2;
    const float* aPtr = A + (size_t)(rowTile + rA) * Kd + sA * 8;

    // B: thread covers full row t (both k8 groups)
    const int rB = t;
    const uint32_t bXr = ((rB >> 2) & 1) << 2;
    const float* bPtr;
    if (BMODE == 2) {
        int col = colTile + rB;
        bPtr = B + ((size_t)(col / PP) * HW_ + aux[col]) * CCH;
    } else if (BMODE == 3) {
        int px = colTile + rB;
        int c2 = aux[px];
        bPtr = (c2 >= 0) ? (P + (size_t)c2 * CCH) : (B + (size_t)px * CCH);
    } else {
        bPtr = B + (size_t)(colTile + rB) * ldb;
    }

    float acc[4][8][4];
    #pragma unroll
    for (int i = 0; i < 4; i++)
        #pragma unroll
        for (int j = 0; j < 8; j++)
            #pragma unroll
            for (int r = 0; r < 4; r++) acc[i][j][r] = 0.f;

    const int nCh = Kd >> 4;
    float4 ra0 = *reinterpret_cast<const float4*>(aPtr);
    float4 ra1 = *reinterpret_cast<const float4*>(aPtr + 4);
    float4 rb0 = *reinterpret_cast<const float4*>(bPtr);
    float4 rb1 = *reinterpret_cast<const float4*>(bPtr + 4);
    float4 rb2 = *reinterpret_cast<const float4*>(bPtr + 8);
    float4 rb3 = *reinterpret_cast<const float4*>(bPtr + 12);

    for (int ch = 0; ch < nCh; ch++) {
        const uint32_t S = (uint32_t)(ch & 1) * STAGE_W;
        // ---- stores (permuted pairs (k, k+4); conflict-free STS.128) ----
        uint32_t* ap = sh + S + (uint32_t)sA * 1028u + (uint32_t)rA * 8u;
        *reinterpret_cast<uint4*>(ap + aXr) =
            make_uint4(cvt_tf32(ra0.x), cvt_tf32(ra1.x), cvt_tf32(ra0.y), cvt_tf32(ra1.y));
        *reinterpret_cast<uint4*>(ap + (4u ^ aXr)) =
            make_uint4(cvt_tf32(ra0.z), cvt_tf32(ra1.z), cvt_tf32(ra0.w), cvt_tf32(ra1.w));
        uint32_t* bp = sh + S + 2056u + (uint32_t)rB * 8u;
        *reinterpret_cast<uint4*>(bp + bXr) =
            make_uint4(cvt_tf32(rb0.x), cvt_tf32(rb1.x), cvt_tf32(rb0.y), cvt_tf32(rb1.y));
        *reinterpret_cast<uint4*>(bp + (4u ^ bXr)) =
            make_uint4(cvt_tf32(rb0.z), cvt_tf32(rb1.z), cvt_tf32(rb0.w), cvt_tf32(rb1.w));
        bp += 2048u;
        *reinterpret_cast<uint4*>(bp + bXr) =
            make_uint4(cvt_tf32(rb2.x), cvt_tf32(rb3.x), cvt_tf32(rb2.y), cvt_tf32(rb3.y));
        *reinterpret_cast<uint4*>(bp + (4u ^ bXr)) =
            make_uint4(cvt_tf32(rb2.z), cvt_tf32(rb3.z), cvt_tf32(rb2.w), cvt_tf32(rb3.w));
        // ---- prefetch next chunk ----
        if (ch + 1 < nCh) {
            aPtr += 16; bPtr += 16;
            ra0 = *reinterpret_cast<const float4*>(aPtr);
            ra1 = *reinterpret_cast<const float4*>(aPtr + 4);
            rb0 = *reinterpret_cast<const float4*>(bPtr);
            rb1 = *reinterpret_cast<const float4*>(bPtr + 4);
            rb2 = *reinterpret_cast<const float4*>(bPtr + 8);
            rb3 = *reinterpret_cast<const float4*>(bPtr + 12);
        }
        __syncthreads();
        // ---- compute 2 k8 groups ----
        #pragma unroll
        for (int s = 0; s < 2; s++) {
            const uint32_t* Ab = sh + S + (uint32_t)s * 1028u;
            const uint32_t* Bb = sh + S + 2056u + (uint32_t)s * 2048u;
            uint2 aF[4][2];
            #pragma unroll
            for (int i = 0; i < 4; i++) {
                const uint32_t r0 = (uint32_t)(wr * 64 + i * 16 + g);
                aF[i][0] = *reinterpret_cast<const uint2*>(Ab + r0 * 8u + xq);
                aF[i][1] = *reinterpret_cast<const uint2*>(Ab + (r0 + 8u) * 8u + xq);
            }
            #pragma unroll
            for (int j = 0; j < 8; j++) {
                const uint32_t n0 = (uint32_t)(wc * 64 + j * 8 + g);
                uint2 bF = *reinterpret_cast<const uint2*>(Bb + n0 * 8u + xq);
                #pragma unroll
                for (int i = 0; i < 4; i++)
                    mma8(acc[i][j], aF[i][0].x, aF[i][1].x, aF[i][0].y, aF[i][1].y,
                         bF.x, bF.y);
            }
        }
    }

    // ---- bias + relu ----
    #pragma unroll
    for (int i = 0; i < 4; i++) {
        const int m0 = rowTile + wr * 64 + i * 16 + g;
        const float bv0 = bias[m0], bv1 = bias[m0 + 8];
        #pragma unroll
        for (int j = 0; j < 8; j++) {
            acc[i][j][0] += bv0; acc[i][j][1] += bv0;
            acc[i][j][2] += bv1; acc[i][j][3] += bv1;
            if (RELU) {
                acc[i][j][0] = fmaxf(acc[i][j][0], 0.f);
                acc[i][j][1] = fmaxf(acc[i][j][1], 0.f);
                acc[i][j][2] = fmaxf(acc[i][j][2], 0.f);
                acc[i][j][3] = fmaxf(acc[i][j][3], 0.f);
            }
        }
    }

    // ---- SMEM-staged coalesced epilogue ----
    float* stg = reinterpret_cast<float*>(sh);
    if (STORE_T) {
        // 8 passes of 32 n-cols x 128 m (stride 132)
        #pragma unroll
        for (int pass = 0; pass < 8; pass++) {
            __syncthreads();
            if (wc == (pass >> 1)) {
                const int jb = (pass & 1) * 4;
                #pragma unroll
                for (int jj = 0; jj < 4; jj++) {
                    const int j = jb + jj;
                    const int nl = jj * 8 + 2 * q;
                    #pragma unroll
                    for (int i = 0; i < 4; i++) {
                        const int ml = wr * 64 + i * 16 + g;
                        stg[nl * 132 + ml]           = acc[i][j][0];
                        stg[(nl + 1) * 132 + ml]     = acc[i][j][1];
                        stg[nl * 132 + ml + 8]       = acc[i][j][2];
                        stg[(nl + 1) * 132 + ml + 8] = acc[i][j][3];
                    }
                }
            }
            __syncthreads();
            const int cc = t >> 3;
            const int n = colTile + pass * 32 + cc;
            if (n < Ncols) {
                #pragma unroll
                for (int it = 0; it < 4; it++) {
                    const int ml = (t & 7) * 4 + it * 32;
                    const int m = rowTile + ml;
                    if (m < M) {
                        float4 v = *reinterpret_cast<float4*>(&stg[cc * 132 + ml]);
                        *reinterpret_cast<float4*>(C + (size_t)n * ldc + m) = v;
                        if (C2) *reinterpret_cast<float4*>(C2 + (size_t)n * ldc + m) = v;
                    }
                }
            }
        }
    } else {
        // 4 passes of 32 m-rows x 256 n (stride 260)
        #pragma unroll
        for (int pass = 0; pass < 4; pass++) {
            __syncthreads();
            if (wr == (pass >> 1)) {
                #pragma unroll
                for (int ii = 0; ii < 2; ii++) {
                    const int i = (pass & 1) * 2 + ii;
                    const int rl = ii * 16 + g;
                    #pragma unroll
                    for (int j = 0; j < 8; j++) {
                        const int nl = wc * 64 + j * 8 + 2 * q;
                        stg[rl * 260 + nl]           = acc[i][j][0];
                        stg[rl * 260 + nl + 1]       = acc[i][j][1];
                        stg[(rl + 8) * 260 + nl]     = acc[i][j][2];
                        stg[(rl + 8) * 260 + nl + 1] = acc[i][j][3];
                    }
                }
            }
            __syncthreads();
            const int rr = t >> 3;
            const int m = rowTile + pass * 32 + rr;
            if (m < M) {
                #pragma unroll
                for (int it = 0; it < 8; it++) {
                    const int nl = (t & 7) * 4 + it * 32;
                    float4 v = *reinterpret_cast<float4*>(&stg[rr * 260 + nl]);
                    *reinterpret_cast<float4*>(C + (size_t)m * ldc + colTile + nl) = v;
                }
            }
        }
    }
}

// ---------------- batched 2D transpose [b][R][Cc] -> [b][Cc][R] ----------------
__global__ void transpose_k(const float* __restrict__ in, float* __restrict__ out,
                            int R, int Cc)
{
    __shared__ float tile[32][33];
    const int b = blockIdx.z;
    const float* ip = in  + (size_t)b*R*Cc;
    float*       op = out + (size_t)b*R*Cc;
    int x = blockIdx.x*32 + threadIdx.x;
    #pragma unroll
    for (int j = 0; j < 32; j += 8) {
        int y = blockIdx.y*32 + threadIdx.y + j;
        if (y < R && x < Cc) tile[threadIdx.y+j][threadIdx.x] = ip[(size_t)y*Cc + x];
    }
    __syncthreads();
    int x2 = blockIdx.y*32 + threadIdx.x;
    #pragma unroll
    for (int j = 0; j < 32; j += 8) {
        int y2 = blockIdx.x*32 + threadIdx.y + j;
        if (y2 < Cc && x2 < R) op[(size_t)y2*R + x2] = tile[threadIdx.x][threadIdx.y+j];
    }
}

// sem transpose into padded pixel-major buffer (pad rows stay zero-initialized)
__global__ void transposeS_k(const float* __restrict__ in)
{
    __shared__ float tile[32][33];
    int x = blockIdx.x*32 + threadIdx.x;
    #pragma unroll
    for (int j = 0; j < 32; j += 8) {
        int y = blockIdx.y*32 + threadIdx.y + j;
        if (x < SPIX) tile[threadIdx.y+j][threadIdx.x] = in[(size_t)y*SPIX + x];
    }
    __syncthreads();
    int pix = blockIdx.x*32 + threadIdx.y;
    int c   = blockIdx.y*32 + threadIdx.x;
    #pragma unroll
    for (int j = 0; j < 32; j += 8) {
        if (pix + j < SPIX)
            g_semFT[(size_t)(pix + j)*CCH + c] = tile[threadIdx.x][threadIdx.y+j];
    }
}

// ---------------- stack class weights (zero-padded to 256 rows) ----------------
__global__ void wid_k(const float* __restrict__ wi, const float* __restrict__ bi,
                      const float* __restrict__ wd, const float* __restrict__ bd)
{
    for (int i = threadIdx.x + blockIdx.x*blockDim.x; i < 256*CCH; i += blockDim.x*gridDim.x) {
        int r = i >> 8, c = i & 255;
        g_Wid[i] = (r < KCLS) ? wi[r*CCH + c] : (r < 160 ? wd[(r-KCLS)*CCH + c] : 0.f);
    }
    if (blockIdx.x == 0)
        for (int i = threadIdx.x; i < 256; i += blockDim.x)
            g_Bid[i] = (i < KCLS) ? bi[i] : (i < 160 ? bd[i-KCLS] : 0.f);
}

// ---------------- per-ROI label-selected maps (fp32 exact; feeds topk) ----------------
__global__ void class_select_k(const float* __restrict__ w_inst, const float* __restrict__ b_inst,
                               const float* __restrict__ w_det,  const float* __restrict__ b_det,
                               const int* __restrict__ labels, float* __restrict__ out)
{
    __shared__ float swi[CCH], swd[CCH];
    const int n = blockIdx.x;
    const int part = blockIdx.y;
    const int lab = labels[n];
    const int t = threadIdx.x;
    if (t < CCH) { swi[t] = w_inst[lab*CCH + t]; swd[t] = w_det[lab*CCH + t]; }
    __syncthreads();
    const float bi = b_inst[lab], bd = b_det[lab];
    const int lane = t & 31, w = t >> 5;
    const int pend = (part + 1) * 112;
    for (int p = part*112 + w; p < pend; p += 8) {
        const float* f = g_Ft + ((size_t)n*HW_ + p)*CCH;
        float si = 0.f, sd = 0.f;
        for (int c = lane; c < CCH; c += 32) {
            float v = f[c];
            si = fmaf(v, swi[c], si);
            sd = fmaf(v, swd[c], sd);
        }
        #pragma unroll
        for (int o = 16; o; o >>= 1) {
            si += __shfl_down_sync(0xffffffffu, si, o);
            sd += __shfl_down_sync(0xffffffffu, sd, o);
        }
        if (lane == 0) {
            out[n*HW_ + p]        = si + bi;
            out[NPIX + n*HW_ + p] = sd + bd;
        }
    }
}

// ---------------- top-196 of 784 per ROI ----------------
__global__ void topk_k(const float* __restrict__ det)
{
    __shared__ float sv[1024];
    __shared__ int   si[1024];
    const int n = blockIdx.x, t = threadIdx.x;
    for (int i = t; i < 1024; i += 512) {
        sv[i] = (i < HW_) ? det[NPIX + n*HW_ + i] : -3.4e38f;
        si[i] = i;
    }
    __syncthreads();
    for (int k2 = 2; k2 <= 1024; k2 <<= 1)
        for (int j = k2 >> 1; j > 0; j >>= 1) {
            int i = 2*t - (t & (j-1));
            int r = i + j;
            bool desc = ((i & k2) == 0);
            float vl = sv[i], vr = sv[r];
            bool sw = desc ? (vl < vr) : (vl > vr);
            if (sw) {
                sv[i] = vr; sv[r] = vl;
                int tmp = si[i]; si[i] = si[r]; si[r] = tmp;
            }
            __syncthreads();
        }
    if (t < PP) g_idx[n*PP + t] = si[t];
}

// ---------------- per-point: bilinear 'fine' into X0 rows 0..255 ----------------
__global__ void gather_k(const float* __restrict__ rois)
{
    const int col = blockIdx.x;
    const int n = col / PP;
    const int c = threadIdx.x;
    const int pix = g_idx[col];
    const float x1 = __ldg(rois + n*5 + 1), y1 = __ldg(rois + n*5 + 2);
    const float x2 = __ldg(rois + n*5 + 3), y2 = __ldg(rois + n*5 + 4);
    const float relx = ((pix % MW_) + 0.5f) / (float)MW_;
    const float rely = ((pix / MW_) + 0.5f) / (float)MH_;
    const float px = (x1 + relx*(x2 - x1)) * 0.25f - 0.5f;
    const float py = (y1 + rely*(y2 - y1)) * 0.25f - 0.5f;
    const float x0f = floorf(px), y0f = floorf(py);
    const float wx = px - x0f, wy = py - y0f;
    const int ix0 = (int)x0f, iy0 = (int)y0f;
    const int x0c = min(max(ix0, 0), SW__-1),   x1c = min(max(ix0+1, 0), SW__-1);
    const int y0c = min(max(iy0, 0), SH__-1),   y1c = min(max(iy0+1, 0), SH__-1);
    const float vx0 = (ix0   >= 0 && ix0   < SW__) ? 1.f : 0.f;
    const float vx1 = (ix0+1 >= 0 && ix0+1 < SW__) ? 1.f : 0.f;
    const float vy0 = (iy0   >= 0 && iy0   < SH__) ? 1.f : 0.f;
    const float vy1 = (iy0+1 >= 0 && iy0+1 < SH__) ? 1.f : 0.f;
    const float w00 = (1.f-wx)*(1.f-wy)*vx0*vy0;
    const float w10 = wx*(1.f-wy)*vx1*vy0;
    const float w01 = (1.f-wx)*wy*vx0*vy1;
    const float w11 = wx*wy*vx1*vy1;
    float v = w00 * g_semT[(size_t)(y0c*SW__ + x0c)*CCH + c]
            + w10 * g_semT[(size_t)(y0c*SW__ + x1c)*CCH + c]
            + w01 * g_semT[(size_t)(y1c*SW__ + x0c)*CCH + c]
            + w11 * g_semT[(size_t)(y1c*SW__ + x1c)*CCH + c];
    g_X0[(size_t)col*FCIN + c] = v;
}

// ---------------- pixel -> point-column map ----------------
__global__ void mapinit_k()
{
    for (int i = blockIdx.x*blockDim.x + threadIdx.x; i < NPIX; i += gridDim.x*blockDim.x)
        g_map[i] = -1;
}
__global__ void mapset_k()
{
    int col = blockIdx.x*blockDim.x + threadIdx.x;
    if (col < NCOL) {
        int n = col / PP;
        g_map[n*HW_ + g_idx[col]] = col;
    }
}

// ---------------- x2 bilinear upsample + relu (SMEM plane cache) ----------------
__global__ void upsample_k(float* __restrict__ out)
{
    __shared__ float sf[HW_];
    const int plane = blockIdx.x;
    const int n = plane >> 8, c = plane & 255;
    const float* f = g_F + (size_t)c*NPIX + (size_t)n*HW_;
    const int t = threadIdx.x;
    for (int i = t; i < HW_; i += blockDim.x) sf[i] = f[i];
    __syncthreads();
    float* o = out + 2*(size_t)NPIX + (size_t)plane*3136;
    for (int q4 = t; q4 < 784; q4 += blockDim.x) {
        const int oy = q4 / 14;
        const int xb = (q4 - oy*14) * 4;
        const float sy = oy*0.5f - 0.25f;
        const int iy = (int)floorf(sy);
        const float fy = sy - iy;
        const int y0c = max(iy, 0), y1c = min(iy+1, MH_-1);
        float4 v;
        float* vp = &v.x;
        #pragma unroll
        for (int j = 0; j < 4; j++) {
            const int ox = xb + j;
            const float sx = ox*0.5f - 0.25f;
            const int ix = (int)floorf(sx);
            const float fx = sx - ix;
            const int x0c = max(ix, 0), x1c = min(ix+1, MW_-1);
            float v0 = sf[y0c*MW_ + x0c]*(1.f-fx) + sf[y0c*MW_ + x1c]*fx;
            float v1 = sf[y1c*MW_ + x0c]*(1.f-fx) + sf[y1c*MW_ + x1c]*fx;
            vp[j] = fmaxf(v0*(1.f-fy) + v1*fy, 0.f);
        }
        *reinterpret_cast<float4*>(o + oy*56 + xb) = v;
    }
}

// ---------------- host orchestration ----------------
extern "C" void kernel_launch(void* const* d_in, const int* in_sizes, int n_in,
                              void* d_out, int out_size)
{
    (void)out_size;
    const bool has_np = (n_in >= 21);
    auto IN = [&](int i) -> const void* {
        int j = (i >= 5 && !has_np) ? i - 1 : i;
        return d_in[j];
    };
    const float* inst_feats = (const float*)IN(0);
    const float* sem_feat   = (const float*)IN(1);
    const float* rois       = (const float*)IN(2);
    const int*   labels     = (const int*)  IN(3);
    const float* w_sem  = (const float*)IN(5);  const float* b_sem  = (const float*)IN(6);
    const float* w_inst = (const float*)IN(7);  const float* b_inst = (const float*)IN(8);
    const float* w_det  = (const float*)IN(9);  const float* b_det  = (const float*)IN(10);
    const float* fc_w0  = (const float*)IN(11); const float* fc_b0  = (const float*)IN(12);
    const float* fc_w1  = (const float*)IN(13); const float* fc_b1  = (const float*)IN(14);
    const float* fc_w2  = (const float*)IN(15); const float* fc_b2  = (const float*)IN(16);
    const float* w_log  = (const float*)IN(17); const float* b_log  = (const float*)IN(18);
    const float* w_fuse = (const float*)IN(19); const float* b_fuse = (const float*)IN(20);
    float* out = (float*)d_out;

    float *p_semFT, *p_semT, *p_Ft, *p_X0, *p_X1, *p_P, *p_F, *p_Wid, *p_Bid;
    int *p_idx, *p_map;
    cudaGetSymbolAddress((void**)&p_semFT, g_semFT);
    cudaGetSymbolAddress((void**)&p_semT,  g_semT);
    cudaGetSymbolAddress((void**)&p_Ft,    g_Ft);
    cudaGetSymbolAddress((void**)&p_X0,    g_X0);
    cudaGetSymbolAddress((void**)&p_X1,    g_X1);
    cudaGetSymbolAddress((void**)&p_P,     g_P);
    cudaGetSymbolAddress((void**)&p_F,     g_F);
    cudaGetSymbolAddress((void**)&p_Wid,   g_Wid);
    cudaGetSymbolAddress((void**)&p_Bid,   g_Bid);
    cudaGetSymbolAddress((void**)&p_idx,   g_idx);
    cudaGetSymbolAddress((void**)&p_map,   g_map);

    cudaFuncSetAttribute(mgemm<0, true, true >, cudaFuncAttributeMaxDynamicSharedMemorySize, MG_SMEM);
    cudaFuncSetAttribute(mgemm<0, true, false>, cudaFuncAttributeMaxDynamicSharedMemorySize, MG_SMEM);
    cudaFuncSetAttribute(mgemm<2, true, false>, cudaFuncAttributeMaxDynamicSharedMemorySize, MG_SMEM);
    cudaFuncSetAttribute(mgemm<3, false, true>, cudaFuncAttributeMaxDynamicSharedMemorySize, MG_SMEM);

    // 0. stacked class weights + map init
    wid_k<<<64, 256>>>(w_inst, b_inst, w_det, b_det);
    mapinit_k<<<392, 256>>>();
    // 1. transposes to pixel-major
    transpose_k<<<dim3(25, 8, NB), dim3(32, 8)>>>(inst_feats, p_Ft, CCH, HW_);
    transposeS_k<<<dim3(1250, 8), dim3(32, 8)>>>(sem_feat);
    // 2. sem = relu(W_sem @ semantic + b)
    mgemm<0, true, true><<<dim3(157, 2), 256, MG_SMEM>>>(w_sem, p_semFT, p_semT, nullptr, b_sem,
                                                         nullptr, nullptr, 256, 256, SPIX, 256, 256);
    // 3. label-selected maps -> d_out[0:2*NPIX] (fp32 exact, feeds topk)
    class_select_k<<<dim3(NB, 7), 256>>>(w_inst, b_inst, w_det, b_det, labels, out);
    // 4. per-ROI top-196 points
    topk_k<<<NB, 512>>>(out);
    mapset_k<<<(NCOL + 255)/256, 256>>>();
    // 5. bilinear fine -> X0 rows 0..255
    gather_k<<<NCOL, 256>>>(rois);
    // 6. c_inst/c_det -> X0 & X1 rows 256..415 (B gathered via g_idx, dual store)
    mgemm<2, true, false><<<dim3(98, 2), 256, MG_SMEM>>>(p_Wid, p_Ft, p_X0 + 256, p_X1 + 256, p_Bid,
                                                         nullptr, p_idx, 160, 256, NCOL, 0, FCIN);
    // 7. MLP layers
    mgemm<0, true, true ><<<dim3(98, 2), 256, MG_SMEM>>>(fc_w0, p_X0, p_X1, nullptr, fc_b0,
                                                         nullptr, nullptr, 256, FCIN, NCOL, FCIN, FCIN);
    mgemm<0, true, true ><<<dim3(98, 2), 256, MG_SMEM>>>(fc_w1, p_X1, p_X0, nullptr, fc_b1,
                                                         nullptr, nullptr, 256, FCIN, NCOL, FCIN, FCIN);
    mgemm<0, true, true ><<<dim3(98, 2), 256, MG_SMEM>>>(fc_w2, p_X0, p_X1, nullptr, fc_b2,
                                                         nullptr, nullptr, 256, FCIN, NCOL, FCIN, FCIN);
    // 8. point logits
    mgemm<0, true, false><<<dim3(98, 2), 256, MG_SMEM>>>(w_log, p_X1, p_P, nullptr, b_log,
                                                         nullptr, nullptr, 256, FCIN, NCOL, FCIN, CCH);
    // 9. fused = relu(W_fuse @ refined + b); refine folded into B row select
    mgemm<3, false, true><<<dim3(392, 2), 256, MG_SMEM>>>(w_fuse, p_Ft, p_F, nullptr, b_fuse,
                                                          p_P, p_map, 256, 256, NPIX, 0, NPIX);
    // 10. x2 bilinear upsample + relu
    upsample_k<<<NB*CCH, 256>>>(out);
}

// round 10
// speedup vs baseline: 1.2056x; 1.2056x over previous
#include <cuda_runtime.h>
#include <cstdint>
#include <math.h>

// ---------------- problem constants ----------------
#define NB   128
#define CCH  256
#define MH_  28
#define MW_  28
#define HW_  784
#define KCLS 80
#define PP   196
#define SH__ 200
#define SW__ 200
#define SPIX 40000          // 200*200
#define SPIXP 40192         // >= 313*128 (N-tile pad; pad rows stay zero)
#define FCIN 416            // C + 2K
#define NCOL (NB*PP)        // 25088 point-columns
#define NPIX (NB*HW_)       // 100352 instance pixels

// ---------------- scratch (static device globals; no allocation) ----------------
__device__ float g_semFT[(size_t)SPIXP*CCH];   // transposed semantic feat [pix][c]
__device__ float g_semT [(size_t)SPIX*CCH];    // relu(sem conv) [pix][o]
__device__ float g_Ft [(size_t)NPIX*CCH];      // instance feats pixel-major
__device__ float g_X0 [(size_t)NCOL*FCIN];     // MLP ping
__device__ float g_X1 [(size_t)NCOL*FCIN];     // MLP pong
__device__ float g_P  [(size_t)NCOL*CCH];      // point logits
__device__ float g_F  [(size_t)CCH*NPIX];      // fused, channel-major
__device__ int   g_idx[NB*PP];
__device__ int   g_map[NPIX];
__device__ float g_Wid[256*CCH];               // stacked [w_inst; w_det; zeros]
__device__ float g_Bid[256];

// ---------------- tf32 helpers ----------------
__device__ __forceinline__ uint32_t cvt_tf32(float f) {
    uint32_t r; asm("cvt.rna.tf32.f32 %0, %1;" : "=r"(r) : "f"(f)); return r;
}
__device__ __forceinline__ void mma8(float* c,
                                     uint32_t a0, uint32_t a1, uint32_t a2, uint32_t a3,
                                     uint32_t b0, uint32_t b1) {
    asm volatile("mma.sync.aligned.m16n8k8.row.col.f32.tf32.tf32.f32 "
                 "{%0,%1,%2,%3}, {%4,%5,%6,%7}, {%8,%9}, {%0,%1,%2,%3};"
                 : "+f"(c[0]), "+f"(c[1]), "+f"(c[2]), "+f"(c[3])
                 : "r"(a0), "r"(a1), "r"(a2), "r"(a3), "r"(b0), "r"(b1));
}

// ================= tf32 tensor-core TN GEMM v4 =================
// CTA tile 128(M) x 128(N), 8 warps (2m x 4n grid, warp tile 64x32), BK=16,
// 2-stage SMEM double buffer, one __syncthreads per k16, 2 CTAs/SM.
// A row-major [>=128*gridDim.y rows][Kd]; B modes:
//   0: B[col][Kd] stride ldb (rows up to 128*gridDim.x readable)
//   2: row gathered: aux=g_idx, B=g_Ft
//   3: row select: aux=g_map, P=g_P, B=g_Ft
// Kd % 16 == 0, M % 4 == 0.
// STORE_T: C[n*ldc+m] (m,n guarded; C2 optional dup). else C[m*ldc+n] (m guarded, Ncols%128==0).
// SMEM swizzle: word = base + group*1028 + r*8 + (pos ^ xr),
//   pos(k8)=((k&3)<<1)|(k>>2), xr=((r>>2)&1)<<2.  Conflict-free STS.128 / LDS.64.
#define STG_W   1028
#define STAGE_W (4*STG_W)        // A(2 groups) + B(2 groups) = 4112 words
#define MG_SMEM (2*STAGE_W*4)    // 32896 bytes

template<int BMODE, bool STORE_T, bool RELU>
__global__ void __launch_bounds__(256, 2)
mgemm(const float* __restrict__ A, const float* __restrict__ B,
      float* __restrict__ C, float* __restrict__ C2,
      const float* __restrict__ bias,
      const float* __restrict__ P, const int* __restrict__ aux,
      int M, int Kd, int Ncols, int ldb, int ldc)
{
    extern __shared__ uint32_t sh[];
    const int t = threadIdx.x;
    const int rowTile = blockIdx.y * 128;
    const int colTile = blockIdx.x * 128;
    const int lane = t & 31, wid = t >> 5;
    const int wr = wid & 1, wc = wid >> 1;          // warp grid 2(m) x 4(n)
    const int g = lane >> 2, q = lane & 3;
    const uint32_t xq = (uint32_t)(2*q) ^ ((uint32_t)((lane >> 4) & 1) << 2);

    // load mapping: row r = t>>1 (0..127), k8-group s = t&1
    const int r = t >> 1;
    const int s = t & 1;
    const uint32_t xr = ((r >> 2) & 1) << 2;
    const float* aPtr = A + (size_t)(rowTile + r) * Kd + s * 8;
    const float* bPtr;
    if (BMODE == 2) {
        int col = colTile + r;
        bPtr = B + ((size_t)(col / PP) * HW_ + aux[col]) * CCH + s * 8;
    } else if (BMODE == 3) {
        int px = colTile + r;
        int c2 = aux[px];
        bPtr = ((c2 >= 0) ? (P + (size_t)c2 * CCH) : (B + (size_t)px * CCH)) + s * 8;
    } else {
        bPtr = B + (size_t)(colTile + r) * ldb + s * 8;
    }

    float acc[4][4][4];
    #pragma unroll
    for (int i = 0; i < 4; i++)
        #pragma unroll
        for (int j = 0; j < 4; j++)
            #pragma unroll
            for (int rr = 0; rr < 4; rr++) acc[i][j][rr] = 0.f;

    const int nCh = Kd >> 4;
    const uint32_t sOffA = (uint32_t)s * STG_W + (uint32_t)r * 8u;
    const uint32_t sOffB = 2u * STG_W + sOffA;

    float4 ra0 = *reinterpret_cast<const float4*>(aPtr);
    float4 ra1 = *reinterpret_cast<const float4*>(aPtr + 4);
    float4 rb0 = *reinterpret_cast<const float4*>(bPtr);
    float4 rb1 = *reinterpret_cast<const float4*>(bPtr + 4);

    // ---- store chunk 0 -> stage 0 ----
    {
        uint32_t* ap = sh + sOffA;
        *reinterpret_cast<uint4*>(ap + xr) =
            make_uint4(cvt_tf32(ra0.x), cvt_tf32(ra1.x), cvt_tf32(ra0.y), cvt_tf32(ra1.y));
        *reinterpret_cast<uint4*>(ap + (4u ^ xr)) =
            make_uint4(cvt_tf32(ra0.z), cvt_tf32(ra1.z), cvt_tf32(ra0.w), cvt_tf32(ra1.w));
        uint32_t* bp = sh + sOffB;
        *reinterpret_cast<uint4*>(bp + xr) =
            make_uint4(cvt_tf32(rb0.x), cvt_tf32(rb1.x), cvt_tf32(rb0.y), cvt_tf32(rb1.y));
        *reinterpret_cast<uint4*>(bp + (4u ^ xr)) =
            make_uint4(cvt_tf32(rb0.z), cvt_tf32(rb1.z), cvt_tf32(rb0.w), cvt_tf32(rb1.w));
    }
    // ---- prefetch chunk 1 ----
    if (nCh > 1) {
        aPtr += 16; bPtr += 16;
        ra0 = *reinterpret_cast<const float4*>(aPtr);
        ra1 = *reinterpret_cast<const float4*>(aPtr + 4);
        rb0 = *reinterpret_cast<const float4*>(bPtr);
        rb1 = *reinterpret_cast<const float4*>(bPtr + 4);
    }
    __syncthreads();

    for (int ch = 0; ch < nCh; ch++) {
        // store prefetched chunk ch+1 into the other stage, then prefetch ch+2
        if (ch + 1 < nCh) {
            const uint32_t Sn = (uint32_t)((ch + 1) & 1) * STAGE_W;
            uint32_t* ap = sh + Sn + sOffA;
            *reinterpret_cast<uint4*>(ap + xr) =
                make_uint4(cvt_tf32(ra0.x), cvt_tf32(ra1.x), cvt_tf32(ra0.y), cvt_tf32(ra1.y));
            *reinterpret_cast<uint4*>(ap + (4u ^ xr)) =
                make_uint4(cvt_tf32(ra0.z), cvt_tf32(ra1.z), cvt_tf32(ra0.w), cvt_tf32(ra1.w));
            uint32_t* bp = sh + Sn + sOffB;
            *reinterpret_cast<uint4*>(bp + xr) =
                make_uint4(cvt_tf32(rb0.x), cvt_tf32(rb1.x), cvt_tf32(rb0.y), cvt_tf32(rb1.y));
            *reinterpret_cast<uint4*>(bp + (4u ^ xr)) =
                make_uint4(cvt_tf32(rb0.z), cvt_tf32(rb1.z), cvt_tf32(rb0.w), cvt_tf32(rb1.w));
            if (ch + 2 < nCh) {
                aPtr += 16; bPtr += 16;
                ra0 = *reinterpret_cast<const float4*>(aPtr);
                ra1 = *reinterpret_cast<const float4*>(aPtr + 4);
                rb0 = *reinterpret_cast<const float4*>(bPtr);
                rb1 = *reinterpret_cast<const float4*>(bPtr + 4);
            }
        }
        // compute from stage ch&1
        const uint32_t S = (uint32_t)(ch & 1) * STAGE_W;
        #pragma unroll
        for (int ss = 0; ss < 2; ss++) {
            const uint32_t* Ab = sh + S + (uint32_t)ss * STG_W;
            const uint32_t* Bb = sh + S + 2u * STG_W + (uint32_t)ss * STG_W;
            uint2 aF[4][2];
            #pragma unroll
            for (int i = 0; i < 4; i++) {
                const uint32_t r0 = (uint32_t)(wr * 64 + i * 16 + g);
                aF[i][0] = *reinterpret_cast<const uint2*>(Ab + r0 * 8u + xq);
                aF[i][1] = *reinterpret_cast<const uint2*>(Ab + (r0 + 8u) * 8u + xq);
            }
            #pragma unroll
            for (int j = 0; j < 4; j++) {
                const uint32_t n0 = (uint32_t)(wc * 32 + j * 8 + g);
                uint2 bF = *reinterpret_cast<const uint2*>(Bb + n0 * 8u + xq);
                #pragma unroll
                for (int i = 0; i < 4; i++)
                    mma8(acc[i][j], aF[i][0].x, aF[i][1].x, aF[i][0].y, aF[i][1].y,
                         bF.x, bF.y);
            }
        }
        __syncthreads();
    }

    // ---- bias + relu ----
    #pragma unroll
    for (int i = 0; i < 4; i++) {
        const int m0 = rowTile + wr * 64 + i * 16 + g;
        const float bv0 = bias[m0], bv1 = bias[m0 + 8];
        #pragma unroll
        for (int j = 0; j < 4; j++) {
            acc[i][j][0] += bv0; acc[i][j][1] += bv0;
            acc[i][j][2] += bv1; acc[i][j][3] += bv1;
            if (RELU) {
                acc[i][j][0] = fmaxf(acc[i][j][0], 0.f);
                acc[i][j][1] = fmaxf(acc[i][j][1], 0.f);
                acc[i][j][2] = fmaxf(acc[i][j][2], 0.f);
                acc[i][j][3] = fmaxf(acc[i][j][3], 0.f);
            }
        }
    }

    // ---- SMEM-staged coalesced epilogue ----
    float* stg = reinterpret_cast<float*>(sh);
    if (STORE_T) {
        // 4 passes of 32 n-cols x 128 m (stride 132)
        #pragma unroll
        for (int pass = 0; pass < 4; pass++) {
            __syncthreads();
            if (wc == pass) {
                #pragma unroll
                for (int j = 0; j < 4; j++) {
                    const int nl = j * 8 + 2 * q;
                    #pragma unroll
                    for (int i = 0; i < 4; i++) {
                        const int ml = wr * 64 + i * 16 + g;
                        stg[nl * 132 + ml]           = acc[i][j][0];
                        stg[(nl + 1) * 132 + ml]     = acc[i][j][1];
                        stg[nl * 132 + ml + 8]       = acc[i][j][2];
                        stg[(nl + 1) * 132 + ml + 8] = acc[i][j][3];
                    }
                }
            }
            __syncthreads();
            const int cc = t >> 3;
            const int n = colTile + pass * 32 + cc;
            if (n < Ncols) {
                #pragma unroll
                for (int it = 0; it < 4; it++) {
                    const int ml = (t & 7) * 4 + it * 32;
                    const int m = rowTile + ml;
                    if (m < M) {
                        float4 v = *reinterpret_cast<float4*>(&stg[cc * 132 + ml]);
                        *reinterpret_cast<float4*>(C + (size_t)n * ldc + m) = v;
                        if (C2) *reinterpret_cast<float4*>(C2 + (size_t)n * ldc + m) = v;
                    }
                }
            }
        }
    } else {
        // 4 passes of 32 m-rows x 128 n (stride 132)
        #pragma unroll
        for (int pass = 0; pass < 4; pass++) {
            __syncthreads();
            if (wr == (pass >> 1)) {
                #pragma unroll
                for (int ii = 0; ii < 2; ii++) {
                    const int i = (pass & 1) * 2 + ii;
                    const int rl = ii * 16 + g;
                    #pragma unroll
                    for (int j = 0; j < 4; j++) {
                        const int nl = wc * 32 + j * 8 + 2 * q;
                        stg[rl * 132 + nl]           = acc[i][j][0];
                        stg[rl * 132 + nl + 1]       = acc[i][j][1];
                        stg[(rl + 8) * 132 + nl]     = acc[i][j][2];
                        stg[(rl + 8) * 132 + nl + 1] = acc[i][j][3];
                    }
                }
            }
            __syncthreads();
            const int rr = t >> 3;
            const int m = rowTile + pass * 32 + rr;
            if (m < M) {
                #pragma unroll
                for (int it = 0; it < 4; it++) {
                    const int nl = (t & 7) * 4 + it * 32;
                    float4 v = *reinterpret_cast<float4*>(&stg[rr * 132 + nl]);
                    *reinterpret_cast<float4*>(C + (size_t)m * ldc + colTile + nl) = v;
                }
            }
        }
    }
}

// ---------------- batched 2D transpose [b][R][Cc] -> [b][Cc][R] ----------------
__global__ void transpose_k(const float* __restrict__ in, float* __restrict__ out,
                            int R, int Cc)
{
    __shared__ float tile[32][33];
    const int b = blockIdx.z;
    const float* ip = in  + (size_t)b*R*Cc;
    float*       op = out + (size_t)b*R*Cc;
    int x = blockIdx.x*32 + threadIdx.x;
    #pragma unroll
    for (int j = 0; j < 32; j += 8) {
        int y = blockIdx.y*32 + threadIdx.y + j;
        if (y < R && x < Cc) tile[threadIdx.y+j][threadIdx.x] = ip[(size_t)y*Cc + x];
    }
    __syncthreads();
    int x2 = blockIdx.y*32 + threadIdx.x;
    #pragma unroll
    for (int j = 0; j < 32; j += 8) {
        int y2 = blockIdx.x*32 + threadIdx.y + j;
        if (y2 < Cc && x2 < R) op[(size_t)y2*R + x2] = tile[threadIdx.x][threadIdx.y+j];
    }
}

// sem transpose into padded pixel-major buffer (pad rows stay zero-initialized)
__global__ void transposeS_k(const float* __restrict__ in)
{
    __shared__ float tile[32][33];
    int x = blockIdx.x*32 + threadIdx.x;
    #pragma unroll
    for (int j = 0; j < 32; j += 8) {
        int y = blockIdx.y*32 + threadIdx.y + j;
        if (x < SPIX) tile[threadIdx.y+j][threadIdx.x] = in[(size_t)y*SPIX + x];
    }
    __syncthreads();
    int pix = blockIdx.x*32 + threadIdx.y;
    int c   = blockIdx.y*32 + threadIdx.x;
    #pragma unroll
    for (int j = 0; j < 32; j += 8) {
        if (pix + j < SPIX)
            g_semFT[(size_t)(pix + j)*CCH + c] = tile[threadIdx.x][threadIdx.y+j];
    }
}

// ---------------- stack class weights (zero-padded to 256 rows) ----------------
__global__ void wid_k(const float* __restrict__ wi, const float* __restrict__ bi,
                      const float* __restrict__ wd, const float* __restrict__ bd)
{
    for (int i = threadIdx.x + blockIdx.x*blockDim.x; i < 256*CCH; i += blockDim.x*gridDim.x) {
        int r = i >> 8, c = i & 255;
        g_Wid[i] = (r < KCLS) ? wi[r*CCH + c] : (r < 160 ? wd[(r-KCLS)*CCH + c] : 0.f);
    }
    if (blockIdx.x == 0)
        for (int i = threadIdx.x; i < 256; i += blockDim.x)
            g_Bid[i] = (i < KCLS) ? bi[i] : (i < 160 ? bd[i-KCLS] : 0.f);
}

// ---------------- per-ROI label-selected maps (fp32 exact; feeds topk) ----------------
__global__ void class_select_k(const float* __restrict__ w_inst, const float* __restrict__ b_inst,
                               const float* __restrict__ w_det,  const float* __restrict__ b_det,
                               const int* __restrict__ labels, float* __restrict__ out)
{
    __shared__ float swi[CCH], swd[CCH];
    const int n = blockIdx.x;
    const int part = blockIdx.y;
    const int lab = labels[n];
    const int t = threadIdx.x;
    if (t < CCH) { swi[t] = w_inst[lab*CCH + t]; swd[t] = w_det[lab*CCH + t]; }
    __syncthreads();
    const float bi = b_inst[lab], bd = b_det[lab];
    const int lane = t & 31, w = t >> 5;
    const int pend = (part + 1) * 112;
    for (int p = part*112 + w; p < pend; p += 8) {
        const float* f = g_Ft + ((size_t)n*HW_ + p)*CCH;
        float si = 0.f, sd = 0.f;
        for (int c = lane; c < CCH; c += 32) {
            float v = f[c];
            si = fmaf(v, swi[c], si);
            sd = fmaf(v, swd[c], sd);
        }
        #pragma unroll
        for (int o = 16; o; o >>= 1) {
            si += __shfl_down_sync(0xffffffffu, si, o);
            sd += __shfl_down_sync(0xffffffffu, sd, o);
        }
        if (lane == 0) {
            out[n*HW_ + p]        = si + bi;
            out[NPIX + n*HW_ + p] = sd + bd;
        }
    }
}

// ---------------- top-196 of 784 per ROI ----------------
__global__ void topk_k(const float* __restrict__ det)
{
    __shared__ float sv[1024];
    __shared__ int   si[1024];
    const int n = blockIdx.x, t = threadIdx.x;
    for (int i = t; i < 1024; i += 512) {
        sv[i] = (i < HW_) ? det[NPIX + n*HW_ + i] : -3.4e38f;
        si[i] = i;
    }
    __syncthreads();
    for (int k2 = 2; k2 <= 1024; k2 <<= 1)
        for (int j = k2 >> 1; j > 0; j >>= 1) {
            int i = 2*t - (t & (j-1));
            int r = i + j;
            bool desc = ((i & k2) == 0);
            float vl = sv[i], vr = sv[r];
            bool sw = desc ? (vl < vr) : (vl > vr);
            if (sw) {
                sv[i] = vr; sv[r] = vl;
                int tmp = si[i]; si[i] = si[r]; si[r] = tmp;
            }
            __syncthreads();
        }
    if (t < PP) g_idx[n*PP + t] = si[t];
}

// ---------------- per-point: bilinear 'fine' into X0 rows 0..255 ----------------
__global__ void gather_k(const float* __restrict__ rois)
{
    const int col = blockIdx.x;
    const int n = col / PP;
    const int c = threadIdx.x;
    const int pix = g_idx[col];
    const float x1 = __ldg(rois + n*5 + 1), y1 = __ldg(rois + n*5 + 2);
    const float x2 = __ldg(rois + n*5 + 3), y2 = __ldg(rois + n*5 + 4);
    const float relx = ((pix % MW_) + 0.5f) / (float)MW_;
    const float rely = ((pix / MW_) + 0.5f) / (float)MH_;
    const float px = (x1 + relx*(x2 - x1)) * 0.25f - 0.5f;
    const float py = (y1 + rely*(y2 - y1)) * 0.25f - 0.5f;
    const float x0f = floorf(px), y0f = floorf(py);
    const float wx = px - x0f, wy = py - y0f;
    const int ix0 = (int)x0f, iy0 = (int)y0f;
    const int x0c = min(max(ix0, 0), SW__-1),   x1c = min(max(ix0+1, 0), SW__-1);
    const int y0c = min(max(iy0, 0), SH__-1),   y1c = min(max(iy0+1, 0), SH__-1);
    const float vx0 = (ix0   >= 0 && ix0   < SW__) ? 1.f : 0.f;
    const float vx1 = (ix0+1 >= 0 && ix0+1 < SW__) ? 1.f : 0.f;
    const float vy0 = (iy0   >= 0 && iy0   < SH__) ? 1.f : 0.f;
    const float vy1 = (iy0+1 >= 0 && iy0+1 < SH__) ? 1.f : 0.f;
    const float w00 = (1.f-wx)*(1.f-wy)*vx0*vy0;
    const float w10 = wx*(1.f-wy)*vx1*vy0;
    const float w01 = (1.f-wx)*wy*vx0*vy1;
    const float w11 = wx*wy*vx1*vy1;
    float v = w00 * g_semT[(size_t)(y0c*SW__ + x0c)*CCH + c]
            + w10 * g_semT[(size_t)(y0c*SW__ + x1c)*CCH + c]
            + w01 * g_semT[(size_t)(y1c*SW__ + x0c)*CCH + c]
            + w11 * g_semT[(size_t)(y1c*SW__ + x1c)*CCH + c];
    g_X0[(size_t)col*FCIN + c] = v;
}

// ---------------- pixel -> point-column map ----------------
__global__ void mapinit_k()
{
    for (int i = blockIdx.x*blockDim.x + threadIdx.x; i < NPIX; i += gridDim.x*blockDim.x)
        g_map[i] = -1;
}
__global__ void mapset_k()
{
    int col = blockIdx.x*blockDim.x + threadIdx.x;
    if (col < NCOL) {
        int n = col / PP;
        g_map[n*HW_ + g_idx[col]] = col;
    }
}

// ---------------- x2 bilinear upsample + relu (SMEM plane cache) ----------------
__global__ void upsample_k(float* __restrict__ out)
{
    __shared__ float sf[HW_];
    const int plane = blockIdx.x;
    const int n = plane >> 8, c = plane & 255;
    const float* f = g_F + (size_t)c*NPIX + (size_t)n*HW_;
    const int t = threadIdx.x;
    for (int i = t; i < HW_; i += blockDim.x) sf[i] = f[i];
    __syncthreads();
    float* o = out + 2*(size_t)NPIX + (size_t)plane*3136;
    for (int q4 = t; q4 < 784; q4 += blockDim.x) {
        const int oy = q4 / 14;
        const int xb = (q4 - oy*14) * 4;
        const float sy = oy*0.5f - 0.25f;
        const int iy = (int)floorf(sy);
        const float fy = sy - iy;
        const int y0c = max(iy, 0), y1c = min(iy+1, MH_-1);
        float4 v;
        float* vp = &v.x;
        #pragma unroll
        for (int j = 0; j < 4; j++) {
            const int ox = xb + j;
            const float sx = ox*0.5f - 0.25f;
            const int ix = (int)floorf(sx);
            const float fx = sx - ix;
            const int x0c = max(ix, 0), x1c = min(ix+1, MW_-1);
            float v0 = sf[y0c*MW_ + x0c]*(1.f-fx) + sf[y0c*MW_ + x1c]*fx;
            float v1 = sf[y1c*MW_ + x0c]*(1.f-fx) + sf[y1c*MW_ + x1c]*fx;
            vp[j] = fmaxf(v0*(1.f-fy) + v1*fy, 0.f);
        }
        *reinterpret_cast<float4*>(o + oy*56 + xb) = v;
    }
}

// ---------------- host orchestration ----------------
extern "C" void kernel_launch(void* const* d_in, const int* in_sizes, int n_in,
                              void* d_out, int out_size)
{
    (void)out_size;
    const bool has_np = (n_in >= 21);
    auto IN = [&](int i) -> const void* {
        int j = (i >= 5 && !has_np) ? i - 1 : i;
        return d_in[j];
    };
    const float* inst_feats = (const float*)IN(0);
    const float* sem_feat   = (const float*)IN(1);
    const float* rois       = (const float*)IN(2);
    const int*   labels     = (const int*)  IN(3);
    const float* w_sem  = (const float*)IN(5);  const float* b_sem  = (const float*)IN(6);
    const float* w_inst = (const float*)IN(7);  const float* b_inst = (const float*)IN(8);
    const float* w_det  = (const float*)IN(9);  const float* b_det  = (const float*)IN(10);
    const float* fc_w0  = (const float*)IN(11); const float* fc_b0  = (const float*)IN(12);
    const float* fc_w1  = (const float*)IN(13); const float* fc_b1  = (const float*)IN(14);
    const float* fc_w2  = (const float*)IN(15); const float* fc_b2  = (const float*)IN(16);
    const float* w_log  = (const float*)IN(17); const float* b_log  = (const float*)IN(18);
    const float* w_fuse = (const float*)IN(19); const float* b_fuse = (const float*)IN(20);
    float* out = (float*)d_out;

    float *p_semFT, *p_semT, *p_Ft, *p_X0, *p_X1, *p_P, *p_F, *p_Wid, *p_Bid;
    int *p_idx, *p_map;
    cudaGetSymbolAddress((void**)&p_semFT, g_semFT);
    cudaGetSymbolAddress((void**)&p_semT,  g_semT);
    cudaGetSymbolAddress((void**)&p_Ft,    g_Ft);
    cudaGetSymbolAddress((void**)&p_X0,    g_X0);
    cudaGetSymbolAddress((void**)&p_X1,    g_X1);
    cudaGetSymbolAddress((void**)&p_P,     g_P);
    cudaGetSymbolAddress((void**)&p_F,     g_F);
    cudaGetSymbolAddress((void**)&p_Wid,   g_Wid);
    cudaGetSymbolAddress((void**)&p_Bid,   g_Bid);
    cudaGetSymbolAddress((void**)&p_idx,   g_idx);
    cudaGetSymbolAddress((void**)&p_map,   g_map);

    cudaFuncSetAttribute(mgemm<0, true, true >, cudaFuncAttributeMaxDynamicSharedMemorySize, MG_SMEM);
    cudaFuncSetAttribute(mgemm<0, true, false>, cudaFuncAttributeMaxDynamicSharedMemorySize, MG_SMEM);
    cudaFuncSetAttribute(mgemm<2, true, false>, cudaFuncAttributeMaxDynamicSharedMemorySize, MG_SMEM);
    cudaFuncSetAttribute(mgemm<3, false, true>, cudaFuncAttributeMaxDynamicSharedMemorySize, MG_SMEM);

    // 0. stacked class weights + map init
    wid_k<<<64, 256>>>(w_inst, b_inst, w_det, b_det);
    mapinit_k<<<392, 256>>>();
    // 1. transposes to pixel-major
    transpose_k<<<dim3(25, 8, NB), dim3(32, 8)>>>(inst_feats, p_Ft, CCH, HW_);
    transposeS_k<<<dim3(1250, 8), dim3(32, 8)>>>(sem_feat);
    // 2. sem = relu(W_sem @ semantic + b)
    mgemm<0, true, true><<<dim3(313, 2), 256, MG_SMEM>>>(w_sem, p_semFT, p_semT, nullptr, b_sem,
                                                         nullptr, nullptr, 256, 256, SPIX, 256, 256);
    // 3. label-selected maps -> d_out[0:2*NPIX] (fp32 exact, feeds topk)
    class_select_k<<<dim3(NB, 7), 256>>>(w_inst, b_inst, w_det, b_det, labels, out);
    // 4. per-ROI top-196 points
    topk_k<<<NB, 512>>>(out);
    mapset_k<<<(NCOL + 255)/256, 256>>>();
    // 5. bilinear fine -> X0 rows 0..255
    gather_k<<<NCOL, 256>>>(rois);
    // 6. c_inst/c_det -> X0 & X1 rows 256..415 (B gathered via g_idx, dual store)
    mgemm<2, true, false><<<dim3(196, 2), 256, MG_SMEM>>>(p_Wid, p_Ft, p_X0 + 256, p_X1 + 256, p_Bid,
                                                          nullptr, p_idx, 160, 256, NCOL, 0, FCIN);
    // 7. MLP layers
    mgemm<0, true, true ><<<dim3(196, 2), 256, MG_SMEM>>>(fc_w0, p_X0, p_X1, nullptr, fc_b0,
                                                          nullptr, nullptr, 256, FCIN, NCOL, FCIN, FCIN);
    mgemm<0, true, true ><<<dim3(196, 2), 256, MG_SMEM>>>(fc_w1, p_X1, p_X0, nullptr, fc_b1,
                                                          nullptr, nullptr, 256, FCIN, NCOL, FCIN, FCIN);
    mgemm<0, true, true ><<<dim3(196, 2), 256, MG_SMEM>>>(fc_w2, p_X0, p_X1, nullptr, fc_b2,
                                                          nullptr, nullptr, 256, FCIN, NCOL, FCIN, FCIN);
    // 8. point logits
    mgemm<0, true, false><<<dim3(196, 2), 256, MG_SMEM>>>(w_log, p_X1, p_P, nullptr, b_log,
                                                          nullptr, nullptr, 256, FCIN, NCOL, FCIN, CCH);
    // 9. fused = relu(W_fuse @ refined + b); refine folded into B row select
    mgemm<3, false, true><<<dim3(784, 2), 256, MG_SMEM>>>(w_fuse, p_Ft, p_F, nullptr, b_fuse,
                                                          p_P, p_map, 256, 256, NPIX, 0, NPIX);
    // 10. x2 bilinear upsample + relu
    upsample_k<<<NB*CCH, 256>>>(out);
}

// round 11
// speedup vs baseline: 1.2303x; 1.0206x over previous
#include <cuda_runtime.h>
#include <cstdint>
#include <math.h>

// ---------------- problem constants ----------------
#define NB   128
#define CCH  256
#define MH_  28
#define MW_  28
#define HW_  784
#define KCLS 80
#define PP   196
#define SH__ 200
#define SW__ 200
#define SPIX 40000          // 200*200
#define SPIXP 40192         // >= 313*128 (N-tile pad; pad rows stay zero)
#define FCIN 416            // C + 2K
#define NCOL (NB*PP)        // 25088 point-columns
#define NPIX (NB*HW_)       // 100352 instance pixels
#define HALFPIX (NPIX/2)    // 50176 (64 images)

// ---------------- scratch (static device globals; no allocation) ----------------
__device__ float g_semFT[(size_t)SPIXP*CCH];   // transposed semantic feat [pix][c]
__device__ float g_semT [(size_t)SPIX*CCH];    // relu(sem conv) [pix][o]
__device__ float g_Ft [(size_t)NPIX*CCH];      // instance feats pixel-major
__device__ float g_X0 [(size_t)NCOL*FCIN];     // MLP ping
__device__ float g_X1 [(size_t)NCOL*FCIN];     // MLP pong
__device__ float g_P  [(size_t)NCOL*CCH];      // point logits
__device__ float g_F  [(size_t)CCH*NPIX];      // fused, channel-major
__device__ int   g_idx[NB*PP];
__device__ int   g_map[NPIX];
__device__ float g_Wid[256*CCH];               // stacked [w_inst; w_det; zeros]
__device__ float g_Bid[256];

// ---------------- tf32 helpers ----------------
__device__ __forceinline__ uint32_t cvt_tf32(float f) {
    uint32_t r; asm("cvt.rna.tf32.f32 %0, %1;" : "=r"(r) : "f"(f)); return r;
}
__device__ __forceinline__ void mma8(float* c,
                                     uint32_t a0, uint32_t a1, uint32_t a2, uint32_t a3,
                                     uint32_t b0, uint32_t b1) {
    asm volatile("mma.sync.aligned.m16n8k8.row.col.f32.tf32.tf32.f32 "
                 "{%0,%1,%2,%3}, {%4,%5,%6,%7}, {%8,%9}, {%0,%1,%2,%3};"
                 : "+f"(c[0]), "+f"(c[1]), "+f"(c[2]), "+f"(c[3])
                 : "r"(a0), "r"(a1), "r"(a2), "r"(a3), "r"(b0), "r"(b1));
}

// ================= tf32 tensor-core TN GEMM v4 (unchanged from R10 win) =================
#define STG_W   1028
#define STAGE_W (4*STG_W)        // 4112 words
#define MG_SMEM (2*STAGE_W*4)    // 32896 bytes

template<int BMODE, bool STORE_T, bool RELU>
__global__ void __launch_bounds__(256, 2)
mgemm(const float* __restrict__ A, const float* __restrict__ B,
      float* __restrict__ C, float* __restrict__ C2,
      const float* __restrict__ bias,
      const float* __restrict__ P, const int* __restrict__ aux,
      int M, int Kd, int Ncols, int ldb, int ldc)
{
    extern __shared__ uint32_t sh[];
    const int t = threadIdx.x;
    const int rowTile = blockIdx.y * 128;
    const int colTile = blockIdx.x * 128;
    const int lane = t & 31, wid = t >> 5;
    const int wr = wid & 1, wc = wid >> 1;
    const int g = lane >> 2, q = lane & 3;
    const uint32_t xq = (uint32_t)(2*q) ^ ((uint32_t)((lane >> 4) & 1) << 2);

    const int r = t >> 1;
    const int s = t & 1;
    const uint32_t xr = ((r >> 2) & 1) << 2;
    const float* aPtr = A + (size_t)(rowTile + r) * Kd + s * 8;
    const float* bPtr;
    if (BMODE == 2) {
        int col = colTile + r;
        bPtr = B + ((size_t)(col / PP) * HW_ + aux[col]) * CCH + s * 8;
    } else if (BMODE == 3) {
        int px = colTile + r;
        int c2 = aux[px];
        bPtr = ((c2 >= 0) ? (P + (size_t)c2 * CCH) : (B + (size_t)px * CCH)) + s * 8;
    } else {
        bPtr = B + (size_t)(colTile + r) * ldb + s * 8;
    }

    float acc[4][4][4];
    #pragma unroll
    for (int i = 0; i < 4; i++)
        #pragma unroll
        for (int j = 0; j < 4; j++)
            #pragma unroll
            for (int rr = 0; rr < 4; rr++) acc[i][j][rr] = 0.f;

    const int nCh = Kd >> 4;
    const uint32_t sOffA = (uint32_t)s * STG_W + (uint32_t)r * 8u;
    const uint32_t sOffB = 2u * STG_W + sOffA;

    float4 ra0 = *reinterpret_cast<const float4*>(aPtr);
    float4 ra1 = *reinterpret_cast<const float4*>(aPtr + 4);
    float4 rb0 = *reinterpret_cast<const float4*>(bPtr);
    float4 rb1 = *reinterpret_cast<const float4*>(bPtr + 4);

    {
        uint32_t* ap = sh + sOffA;
        *reinterpret_cast<uint4*>(ap + xr) =
            make_uint4(cvt_tf32(ra0.x), cvt_tf32(ra1.x), cvt_tf32(ra0.y), cvt_tf32(ra1.y));
        *reinterpret_cast<uint4*>(ap + (4u ^ xr)) =
            make_uint4(cvt_tf32(ra0.z), cvt_tf32(ra1.z), cvt_tf32(ra0.w), cvt_tf32(ra1.w));
        uint32_t* bp = sh + sOffB;
        *reinterpret_cast<uint4*>(bp + xr) =
            make_uint4(cvt_tf32(rb0.x), cvt_tf32(rb1.x), cvt_tf32(rb0.y), cvt_tf32(rb1.y));
        *reinterpret_cast<uint4*>(bp + (4u ^ xr)) =
            make_uint4(cvt_tf32(rb0.z), cvt_tf32(rb1.z), cvt_tf32(rb0.w), cvt_tf32(rb1.w));
    }
    if (nCh > 1) {
        aPtr += 16; bPtr += 16;
        ra0 = *reinterpret_cast<const float4*>(aPtr);
        ra1 = *reinterpret_cast<const float4*>(aPtr + 4);
        rb0 = *reinterpret_cast<const float4*>(bPtr);
        rb1 = *reinterpret_cast<const float4*>(bPtr + 4);
    }
    __syncthreads();

    for (int ch = 0; ch < nCh; ch++) {
        if (ch + 1 < nCh) {
            const uint32_t Sn = (uint32_t)((ch + 1) & 1) * STAGE_W;
            uint32_t* ap = sh + Sn + sOffA;
            *reinterpret_cast<uint4*>(ap + xr) =
                make_uint4(cvt_tf32(ra0.x), cvt_tf32(ra1.x), cvt_tf32(ra0.y), cvt_tf32(ra1.y));
            *reinterpret_cast<uint4*>(ap + (4u ^ xr)) =
                make_uint4(cvt_tf32(ra0.z), cvt_tf32(ra1.z), cvt_tf32(ra0.w), cvt_tf32(ra1.w));
            uint32_t* bp = sh + Sn + sOffB;
            *reinterpret_cast<uint4*>(bp + xr) =
                make_uint4(cvt_tf32(rb0.x), cvt_tf32(rb1.x), cvt_tf32(rb0.y), cvt_tf32(rb1.y));
            *reinterpret_cast<uint4*>(bp + (4u ^ xr)) =
                make_uint4(cvt_tf32(rb0.z), cvt_tf32(rb1.z), cvt_tf32(rb0.w), cvt_tf32(rb1.w));
            if (ch + 2 < nCh) {
                aPtr += 16; bPtr += 16;
                ra0 = *reinterpret_cast<const float4*>(aPtr);
                ra1 = *reinterpret_cast<const float4*>(aPtr + 4);
                rb0 = *reinterpret_cast<const float4*>(bPtr);
                rb1 = *reinterpret_cast<const float4*>(bPtr + 4);
            }
        }
        const uint32_t S = (uint32_t)(ch & 1) * STAGE_W;
        #pragma unroll
        for (int ss = 0; ss < 2; ss++) {
            const uint32_t* Ab = sh + S + (uint32_t)ss * STG_W;
            const uint32_t* Bb = sh + S + 2u * STG_W + (uint32_t)ss * STG_W;
            uint2 aF[4][2];
            #pragma unroll
            for (int i = 0; i < 4; i++) {
                const uint32_t r0 = (uint32_t)(wr * 64 + i * 16 + g);
                aF[i][0] = *reinterpret_cast<const uint2*>(Ab + r0 * 8u + xq);
                aF[i][1] = *reinterpret_cast<const uint2*>(Ab + (r0 + 8u) * 8u + xq);
            }
            #pragma unroll
            for (int j = 0; j < 4; j++) {
                const uint32_t n0 = (uint32_t)(wc * 32 + j * 8 + g);
                uint2 bF = *reinterpret_cast<const uint2*>(Bb + n0 * 8u + xq);
                #pragma unroll
                for (int i = 0; i < 4; i++)
                    mma8(acc[i][j], aF[i][0].x, aF[i][1].x, aF[i][0].y, aF[i][1].y,
                         bF.x, bF.y);
            }
        }
        __syncthreads();
    }

    #pragma unroll
    for (int i = 0; i < 4; i++) {
        const int m0 = rowTile + wr * 64 + i * 16 + g;
        const float bv0 = bias[m0], bv1 = bias[m0 + 8];
        #pragma unroll
        for (int j = 0; j < 4; j++) {
            acc[i][j][0] += bv0; acc[i][j][1] += bv0;
            acc[i][j][2] += bv1; acc[i][j][3] += bv1;
            if (RELU) {
                acc[i][j][0] = fmaxf(acc[i][j][0], 0.f);
                acc[i][j][1] = fmaxf(acc[i][j][1], 0.f);
                acc[i][j][2] = fmaxf(acc[i][j][2], 0.f);
                acc[i][j][3] = fmaxf(acc[i][j][3], 0.f);
            }
        }
    }

    float* stg = reinterpret_cast<float*>(sh);
    if (STORE_T) {
        #pragma unroll
        for (int pass = 0; pass < 4; pass++) {
            __syncthreads();
            if (wc == pass) {
                #pragma unroll
                for (int j = 0; j < 4; j++) {
                    const int nl = j * 8 + 2 * q;
                    #pragma unroll
                    for (int i = 0; i < 4; i++) {
                        const int ml = wr * 64 + i * 16 + g;
                        stg[nl * 132 + ml]           = acc[i][j][0];
                        stg[(nl + 1) * 132 + ml]     = acc[i][j][1];
                        stg[nl * 132 + ml + 8]       = acc[i][j][2];
                        stg[(nl + 1) * 132 + ml + 8] = acc[i][j][3];
                    }
                }
            }
            __syncthreads();
            const int cc = t >> 3;
            const int n = colTile + pass * 32 + cc;
            if (n < Ncols) {
                #pragma unroll
                for (int it = 0; it < 4; it++) {
                    const int ml = (t & 7) * 4 + it * 32;
                    const int m = rowTile + ml;
                    if (m < M) {
                        float4 v = *reinterpret_cast<float4*>(&stg[cc * 132 + ml]);
                        *reinterpret_cast<float4*>(C + (size_t)n * ldc + m) = v;
                        if (C2) *reinterpret_cast<float4*>(C2 + (size_t)n * ldc + m) = v;
                    }
                }
            }
        }
    } else {
        #pragma unroll
        for (int pass = 0; pass < 4; pass++) {
            __syncthreads();
            if (wr == (pass >> 1)) {
                #pragma unroll
                for (int ii = 0; ii < 2; ii++) {
                    const int i = (pass & 1) * 2 + ii;
                    const int rl = ii * 16 + g;
                    #pragma unroll
                    for (int j = 0; j < 4; j++) {
                        const int nl = wc * 32 + j * 8 + 2 * q;
                        stg[rl * 132 + nl]           = acc[i][j][0];
                        stg[rl * 132 + nl + 1]       = acc[i][j][1];
                        stg[(rl + 8) * 132 + nl]     = acc[i][j][2];
                        stg[(rl + 8) * 132 + nl + 1] = acc[i][j][3];
                    }
                }
            }
            __syncthreads();
            const int rr = t >> 3;
            const int m = rowTile + pass * 32 + rr;
            if (m < M) {
                #pragma unroll
                for (int it = 0; it < 4; it++) {
                    const int nl = (t & 7) * 4 + it * 32;
                    float4 v = *reinterpret_cast<float4*>(&stg[rr * 132 + nl]);
                    *reinterpret_cast<float4*>(C + (size_t)m * ldc + colTile + nl) = v;
                }
            }
        }
    }
}

// ---------------- batched 2D transpose [b][R][Cc] -> [b][Cc][R] ----------------
__global__ void transpose_k(const float* __restrict__ in, float* __restrict__ out,
                            int R, int Cc)
{
    __shared__ float tile[32][33];
    const int b = blockIdx.z;
    const float* ip = in  + (size_t)b*R*Cc;
    float*       op = out + (size_t)b*R*Cc;
    int x = blockIdx.x*32 + threadIdx.x;
    #pragma unroll
    for (int j = 0; j < 32; j += 8) {
        int y = blockIdx.y*32 + threadIdx.y + j;
        if (y < R && x < Cc) tile[threadIdx.y+j][threadIdx.x] = ip[(size_t)y*Cc + x];
    }
    __syncthreads();
    int x2 = blockIdx.y*32 + threadIdx.x;
    #pragma unroll
    for (int j = 0; j < 32; j += 8) {
        int y2 = blockIdx.x*32 + threadIdx.y + j;
        if (y2 < Cc && x2 < R) op[(size_t)y2*R + x2] = tile[threadIdx.x][threadIdx.y+j];
    }
}

// sem transpose into padded pixel-major buffer (pad rows stay zero-initialized)
__global__ void transposeS_k(const float* __restrict__ in)
{
    __shared__ float tile[32][33];
    int x = blockIdx.x*32 + threadIdx.x;
    #pragma unroll
    for (int j = 0; j < 32; j += 8) {
        int y = blockIdx.y*32 + threadIdx.y + j;
        if (x < SPIX) tile[threadIdx.y+j][threadIdx.x] = in[(size_t)y*SPIX + x];
    }
    __syncthreads();
    int pix = blockIdx.x*32 + threadIdx.y;
    int c   = blockIdx.y*32 + threadIdx.x;
    #pragma unroll
    for (int j = 0; j < 32; j += 8) {
        if (pix + j < SPIX)
            g_semFT[(size_t)(pix + j)*CCH + c] = tile[threadIdx.x][threadIdx.y+j];
    }
}

// ---------------- stack class weights (zero-padded to 256 rows) ----------------
__global__ void wid_k(const float* __restrict__ wi, const float* __restrict__ bi,
                      const float* __restrict__ wd, const float* __restrict__ bd)
{
    for (int i = threadIdx.x + blockIdx.x*blockDim.x; i < 256*CCH; i += blockDim.x*gridDim.x) {
        int r = i >> 8, c = i & 255;
        g_Wid[i] = (r < KCLS) ? wi[r*CCH + c] : (r < 160 ? wd[(r-KCLS)*CCH + c] : 0.f);
    }
    if (blockIdx.x == 0)
        for (int i = threadIdx.x; i < 256; i += blockDim.x)
            g_Bid[i] = (i < KCLS) ? bi[i] : (i < 160 ? bd[i-KCLS] : 0.f);
}

// ---------------- per-ROI label-selected maps (fp32 exact; feeds topk) ----------------
__global__ void class_select_k(const float* __restrict__ w_inst, const float* __restrict__ b_inst,
                               const float* __restrict__ w_det,  const float* __restrict__ b_det,
                               const int* __restrict__ labels, float* __restrict__ out)
{
    __shared__ float swi[CCH], swd[CCH];
    const int n = blockIdx.x;
    const int part = blockIdx.y;
    const int lab = labels[n];
    const int t = threadIdx.x;
    if (t < CCH) { swi[t] = w_inst[lab*CCH + t]; swd[t] = w_det[lab*CCH + t]; }
    __syncthreads();
    const float bi = b_inst[lab], bd = b_det[lab];
    const int lane = t & 31, w = t >> 5;
    const int pend = (part + 1) * 112;
    for (int p = part*112 + w; p < pend; p += 8) {
        const float* f = g_Ft + ((size_t)n*HW_ + p)*CCH;
        float si = 0.f, sd = 0.f;
        for (int c = lane; c < CCH; c += 32) {
            float v = f[c];
            si = fmaf(v, swi[c], si);
            sd = fmaf(v, swd[c], sd);
        }
        #pragma unroll
        for (int o = 16; o; o >>= 1) {
            si += __shfl_down_sync(0xffffffffu, si, o);
            sd += __shfl_down_sync(0xffffffffu, sd, o);
        }
        if (lane == 0) {
            out[n*HW_ + p]        = si + bi;
            out[NPIX + n*HW_ + p] = sd + bd;
        }
    }
}

// ---------------- top-196 of 784 per ROI ----------------
__global__ void topk_k(const float* __restrict__ det)
{
    __shared__ float sv[1024];
    __shared__ int   si[1024];
    const int n = blockIdx.x, t = threadIdx.x;
    for (int i = t; i < 1024; i += 512) {
        sv[i] = (i < HW_) ? det[NPIX + n*HW_ + i] : -3.4e38f;
        si[i] = i;
    }
    __syncthreads();
    for (int k2 = 2; k2 <= 1024; k2 <<= 1)
        for (int j = k2 >> 1; j > 0; j >>= 1) {
            int i = 2*t - (t & (j-1));
            int r = i + j;
            bool desc = ((i & k2) == 0);
            float vl = sv[i], vr = sv[r];
            bool sw = desc ? (vl < vr) : (vl > vr);
            if (sw) {
                sv[i] = vr; sv[r] = vl;
                int tmp = si[i]; si[i] = si[r]; si[r] = tmp;
            }
            __syncthreads();
        }
    if (t < PP) g_idx[n*PP + t] = si[t];
}

// ---------------- per-point: bilinear 'fine' into X0 rows 0..255 ----------------
__global__ void gather_k(const float* __restrict__ rois)
{
    const int col = blockIdx.x;
    const int n = col / PP;
    const int c = threadIdx.x;
    const int pix = g_idx[col];
    const float x1 = __ldg(rois + n*5 + 1), y1 = __ldg(rois + n*5 + 2);
    const float x2 = __ldg(rois + n*5 + 3), y2 = __ldg(rois + n*5 + 4);
    const float relx = ((pix % MW_) + 0.5f) / (float)MW_;
    const float rely = ((pix / MW_) + 0.5f) / (float)MH_;
    const float px = (x1 + relx*(x2 - x1)) * 0.25f - 0.5f;
    const float py = (y1 + rely*(y2 - y1)) * 0.25f - 0.5f;
    const float x0f = floorf(px), y0f = floorf(py);
    const float wx = px - x0f, wy = py - y0f;
    const int ix0 = (int)x0f, iy0 = (int)y0f;
    const int x0c = min(max(ix0, 0), SW__-1),   x1c = min(max(ix0+1, 0), SW__-1);
    const int y0c = min(max(iy0, 0), SH__-1),   y1c = min(max(iy0+1, 0), SH__-1);
    const float vx0 = (ix0   >= 0 && ix0   < SW__) ? 1.f : 0.f;
    const float vx1 = (ix0+1 >= 0 && ix0+1 < SW__) ? 1.f : 0.f;
    const float vy0 = (iy0   >= 0 && iy0   < SH__) ? 1.f : 0.f;
    const float vy1 = (iy0+1 >= 0 && iy0+1 < SH__) ? 1.f : 0.f;
    const float w00 = (1.f-wx)*(1.f-wy)*vx0*vy0;
    const float w10 = wx*(1.f-wy)*vx1*vy0;
    const float w01 = (1.f-wx)*wy*vx0*vy1;
    const float w11 = wx*wy*vx1*vy1;
    float v = w00 * g_semT[(size_t)(y0c*SW__ + x0c)*CCH + c]
            + w10 * g_semT[(size_t)(y0c*SW__ + x1c)*CCH + c]
            + w01 * g_semT[(size_t)(y1c*SW__ + x0c)*CCH + c]
            + w11 * g_semT[(size_t)(y1c*SW__ + x1c)*CCH + c];
    g_X0[(size_t)col*FCIN + c] = v;
}

// ---------------- pixel -> point-column map ----------------
__global__ void mapinit_k()
{
    for (int i = blockIdx.x*blockDim.x + threadIdx.x; i < NPIX; i += gridDim.x*blockDim.x)
        g_map[i] = -1;
}
__global__ void mapset_k()
{
    int col = blockIdx.x*blockDim.x + threadIdx.x;
    if (col < NCOL) {
        int n = col / PP;
        g_map[n*HW_ + g_idx[col]] = col;
    }
}

// ---------------- x2 bilinear upsample + relu (SMEM plane cache, plane offset) ----------------
__global__ void upsample_k(float* __restrict__ out, int planeOff)
{
    __shared__ float sf[HW_];
    const int plane = blockIdx.x + planeOff;
    const int n = plane >> 8, c = plane & 255;
    const float* f = g_F + (size_t)c*NPIX + (size_t)n*HW_;
    const int t = threadIdx.x;
    for (int i = t; i < HW_; i += blockDim.x) sf[i] = f[i];
    __syncthreads();
    float* o = out + 2*(size_t)NPIX + (size_t)plane*3136;
    for (int q4 = t; q4 < 784; q4 += blockDim.x) {
        const int oy = q4 / 14;
        const int xb = (q4 - oy*14) * 4;
        const float sy = oy*0.5f - 0.25f;
        const int iy = (int)floorf(sy);
        const float fy = sy - iy;
        const int y0c = max(iy, 0), y1c = min(iy+1, MH_-1);
        float4 v;
        float* vp = &v.x;
        #pragma unroll
        for (int j = 0; j < 4; j++) {
            const int ox = xb + j;
            const float sx = ox*0.5f - 0.25f;
            const int ix = (int)floorf(sx);
            const float fx = sx - ix;
            const int x0c = max(ix, 0), x1c = min(ix+1, MW_-1);
            float v0 = sf[y0c*MW_ + x0c]*(1.f-fx) + sf[y0c*MW_ + x1c]*fx;
            float v1 = sf[y1c*MW_ + x0c]*(1.f-fx) + sf[y1c*MW_ + x1c]*fx;
            vp[j] = fmaxf(v0*(1.f-fy) + v1*fy, 0.f);
        }
        *reinterpret_cast<float4*>(o + oy*56 + xb) = v;
    }
}

// ---------------- host orchestration (stream-forked for graph parallelism) ----------------
extern "C" void kernel_launch(void* const* d_in, const int* in_sizes, int n_in,
                              void* d_out, int out_size)
{
    (void)out_size;
    const bool has_np = (n_in >= 21);
    auto IN = [&](int i) -> const void* {
        int j = (i >= 5 && !has_np) ? i - 1 : i;
        return d_in[j];
    };
    const float* inst_feats = (const float*)IN(0);
    const float* sem_feat   = (const float*)IN(1);
    const float* rois       = (const float*)IN(2);
    const int*   labels     = (const int*)  IN(3);
    const float* w_sem  = (const float*)IN(5);  const float* b_sem  = (const float*)IN(6);
    const float* w_inst = (const float*)IN(7);  const float* b_inst = (const float*)IN(8);
    const float* w_det  = (const float*)IN(9);  const float* b_det  = (const float*)IN(10);
    const float* fc_w0  = (const float*)IN(11); const float* fc_b0  = (const float*)IN(12);
    const float* fc_w1  = (const float*)IN(13); const float* fc_b1  = (const float*)IN(14);
    const float* fc_w2  = (const float*)IN(15); const float* fc_b2  = (const float*)IN(16);
    const float* w_log  = (const float*)IN(17); const float* b_log  = (const float*)IN(18);
    const float* w_fuse = (const float*)IN(19); const float* b_fuse = (const float*)IN(20);
    float* out = (float*)d_out;

    float *p_semFT, *p_semT, *p_Ft, *p_X0, *p_X1, *p_P, *p_F, *p_Wid, *p_Bid;
    int *p_idx, *p_map;
    cudaGetSymbolAddress((void**)&p_semFT, g_semFT);
    cudaGetSymbolAddress((void**)&p_semT,  g_semT);
    cudaGetSymbolAddress((void**)&p_Ft,    g_Ft);
    cudaGetSymbolAddress((void**)&p_X0,    g_X0);
    cudaGetSymbolAddress((void**)&p_X1,    g_X1);
    cudaGetSymbolAddress((void**)&p_P,     g_P);
    cudaGetSymbolAddress((void**)&p_F,     g_F);
    cudaGetSymbolAddress((void**)&p_Wid,   g_Wid);
    cudaGetSymbolAddress((void**)&p_Bid,   g_Bid);
    cudaGetSymbolAddress((void**)&p_idx,   g_idx);
    cudaGetSymbolAddress((void**)&p_map,   g_map);

    cudaFuncSetAttribute(mgemm<0, true, true >, cudaFuncAttributeMaxDynamicSharedMemorySize, MG_SMEM);
    cudaFuncSetAttribute(mgemm<0, true, false>, cudaFuncAttributeMaxDynamicSharedMemorySize, MG_SMEM);
    cudaFuncSetAttribute(mgemm<2, true, false>, cudaFuncAttributeMaxDynamicSharedMemorySize, MG_SMEM);
    cudaFuncSetAttribute(mgemm<3, false, true>, cudaFuncAttributeMaxDynamicSharedMemorySize, MG_SMEM);

    // side stream + events (created per call; not destroyed — destroying forked
    // streams/events mid-capture would invalidate the capture)
    cudaStream_t s1;
    cudaStreamCreateWithFlags(&s1, cudaStreamNonBlocking);
    cudaEvent_t eFork, eIdx, eG, eFA, eJoin;
    cudaEventCreateWithFlags(&eFork, cudaEventDisableTiming);
    cudaEventCreateWithFlags(&eIdx,  cudaEventDisableTiming);
    cudaEventCreateWithFlags(&eG,    cudaEventDisableTiming);
    cudaEventCreateWithFlags(&eFA,   cudaEventDisableTiming);
    cudaEventCreateWithFlags(&eJoin, cudaEventDisableTiming);

    // ---- s0: prep + instance branch ----
    wid_k<<<64, 256>>>(w_inst, b_inst, w_det, b_det);
    mapinit_k<<<392, 256>>>();
    transpose_k<<<dim3(25, 8, NB), dim3(32, 8)>>>(inst_feats, p_Ft, CCH, HW_);
    cudaEventRecord(eFork, 0);

    // ---- s1 (forked): semantic branch ----
    cudaStreamWaitEvent(s1, eFork, 0);
    transposeS_k<<<dim3(1250, 8), dim3(32, 8), 0, s1>>>(sem_feat);
    mgemm<0, true, true><<<dim3(313, 2), 256, MG_SMEM, s1>>>(w_sem, p_semFT, p_semT, nullptr, b_sem,
                                                             nullptr, nullptr, 256, 256, SPIX, 256, 256);

    // ---- s0: class select + topk (concurrent with sem GEMM) ----
    class_select_k<<<dim3(NB, 7), 256>>>(w_inst, b_inst, w_det, b_det, labels, out);
    topk_k<<<NB, 512>>>(out);
    mapset_k<<<(NCOL + 255)/256, 256>>>();
    cudaEventRecord(eIdx, 0);

    // ---- s1: bilinear fine (needs semT + idx); concurrent with GEMM6 on s0 ----
    cudaStreamWaitEvent(s1, eIdx, 0);
    gather_k<<<NCOL, 256, 0, s1>>>(rois);
    cudaEventRecord(eG, s1);

    // ---- s0: c_inst/c_det tails (disjoint X0/X1 rows from gather's) ----
    mgemm<2, true, false><<<dim3(196, 2), 256, MG_SMEM>>>(p_Wid, p_Ft, p_X0 + 256, p_X1 + 256, p_Bid,
                                                          nullptr, p_idx, 160, 256, NCOL, 0, FCIN);
    cudaStreamWaitEvent(0, eG, 0);

    // ---- s0: MLP chain + logits (serial dependencies) ----
    mgemm<0, true, true ><<<dim3(196, 2), 256, MG_SMEM>>>(fc_w0, p_X0, p_X1, nullptr, fc_b0,
                                                          nullptr, nullptr, 256, FCIN, NCOL, FCIN, FCIN);
    mgemm<0, true, true ><<<dim3(196, 2), 256, MG_SMEM>>>(fc_w1, p_X1, p_X0, nullptr, fc_b1,
                                                          nullptr, nullptr, 256, FCIN, NCOL, FCIN, FCIN);
    mgemm<0, true, true ><<<dim3(196, 2), 256, MG_SMEM>>>(fc_w2, p_X0, p_X1, nullptr, fc_b2,
                                                          nullptr, nullptr, 256, FCIN, NCOL, FCIN, FCIN);
    mgemm<0, true, false><<<dim3(196, 2), 256, MG_SMEM>>>(w_log, p_X1, p_P, nullptr, b_log,
                                                          nullptr, nullptr, 256, FCIN, NCOL, FCIN, CCH);

    // ---- fuse GEMM split by image halves; upsample(first) overlaps fuse(second) ----
    // first half: images 0..63 (pixels [0, HALFPIX))
    mgemm<3, false, true><<<dim3(392, 2), 256, MG_SMEM>>>(w_fuse, p_Ft, p_F, nullptr, b_fuse,
                                                          p_P, p_map, 256, 256, HALFPIX, 0, NPIX);
    cudaEventRecord(eFA, 0);
    // second half on s0
    mgemm<3, false, true><<<dim3(392, 2), 256, MG_SMEM>>>(w_fuse, p_Ft + (size_t)HALFPIX*CCH,
                                                          p_F + HALFPIX, nullptr, b_fuse,
                                                          p_P, p_map + HALFPIX, 256, 256, HALFPIX, 0, NPIX);
    // upsample first half on s1 (concurrent with second fuse half)
    cudaStreamWaitEvent(s1, eFA, 0);
    upsample_k<<<64*CCH, 256, 0, s1>>>(out, 0);
    // upsample second half on s0
    upsample_k<<<64*CCH, 256>>>(out, 64*CCH);

    // ---- join s1 back into s0 before returning ----
    cudaEventRecord(eJoin, s1);
    cudaStreamWaitEvent(0, eJoin, 0);
}

// round 12
// speedup vs baseline: 1.4269x; 1.1597x over previous
#include <cuda_runtime.h>
#include <cstdint>
#include <math.h>

// ---------------- problem constants ----------------
#define NB   128
#define CCH  256
#define MH_  28
#define MW_  28
#define HW_  784
#define KCLS 80
#define PP   196
#define SH__ 200
#define SW__ 200
#define SPIX 40000          // 200*200
#define SPIXP 40192         // >= 313*128 (N-tile pad; pad rows stay zero)
#define FCIN 416            // C + 2K
#define NCOL (NB*PP)        // 25088 point-columns
#define NPIX (NB*HW_)       // 100352 instance pixels
#define HALFPIX (NPIX/2)    // 50176 (64 images)

// ---------------- scratch (static device globals; no allocation) ----------------
__device__ float g_semFT[(size_t)SPIXP*CCH];   // transposed semantic feat [pix][c]
__device__ float g_semT [(size_t)SPIX*CCH];    // relu(sem conv) [pix][o]
__device__ float g_Ft [(size_t)NPIX*CCH];      // instance feats pixel-major
__device__ float g_X0 [(size_t)NCOL*FCIN];     // MLP ping
__device__ float g_X1 [(size_t)NCOL*FCIN];     // MLP pong
__device__ float g_P  [(size_t)NCOL*CCH];      // point logits
__device__ float g_F  [(size_t)CCH*NPIX];      // fused, channel-major
__device__ int   g_idx[NB*PP];
__device__ int   g_map[NPIX];
__device__ float g_Wid[256*CCH];               // stacked [w_inst; w_det; zeros]
__device__ float g_Bid[256];

// ---------------- fp16 helpers ----------------
__device__ __forceinline__ uint32_t pack_h2(float lo, float hi) {
    uint32_t r; asm("cvt.rn.f16x2.f32 %0, %1, %2;" : "=r"(r) : "f"(hi), "f"(lo)); return r;
}
// m16n8k16 f16 MMA, fp32 accumulate. Fragment layout matches the k8 pattern:
// a0=(row g, k 2q..2q+1), a1=(row g+8, same), a2=(row g, k 8+2q..), a3=(row g+8, ..);
// b0=(k 2q.., col n), b1=(k 8+2q.., col n); acc layout identical to m16n8k8.
__device__ __forceinline__ void mma16(float* c,
                                      uint32_t a0, uint32_t a1, uint32_t a2, uint32_t a3,
                                      uint32_t b0, uint32_t b1) {
    asm volatile("mma.sync.aligned.m16n8k16.row.col.f32.f16.f16.f32 "
                 "{%0,%1,%2,%3}, {%4,%5,%6,%7}, {%8,%9}, {%0,%1,%2,%3};"
                 : "+f"(c[0]), "+f"(c[1]), "+f"(c[2]), "+f"(c[3])
                 : "r"(a0), "r"(a1), "r"(a2), "r"(a3), "r"(b0), "r"(b1));
}
// load 16 floats, pack to 8 f16x2 words arranged in permuted order
// word w = f16x2(k=2w, 2w+1); permuted layout pos = [w0,w4,w1,w5 | w2,w6,w3,w7]
__device__ __forceinline__ void ldpack(const float* p, uint4& u0, uint4& u1) {
    float4 f0 = *reinterpret_cast<const float4*>(p);
    float4 f1 = *reinterpret_cast<const float4*>(p + 4);
    float4 f2 = *reinterpret_cast<const float4*>(p + 8);
    float4 f3 = *reinterpret_cast<const float4*>(p + 12);
    u0 = make_uint4(pack_h2(f0.x, f0.y), pack_h2(f2.x, f2.y),
                    pack_h2(f0.z, f0.w), pack_h2(f2.z, f2.w));
    u1 = make_uint4(pack_h2(f1.x, f1.y), pack_h2(f3.x, f3.y),
                    pack_h2(f1.z, f1.w), pack_h2(f3.z, f3.w));
}

// ================= fp16 tensor-core TN GEMM v5 =================
// CTA tile 128(M) x 128(N), 8 warps (2m x 4n, warp tile 64x32), BK=32 (2 k16 groups),
// 2-stage SMEM double buffer, one __syncthreads per chunk, 2 CTAs/SM.
// Same SMEM geometry as tf32 v4 (8-word rows; data width halved, BK doubled).
// A row-major [>=128*gridDim.y rows][Kd]; B modes: 0 = B[col][Kd] stride ldb,
// 2 = gathered rows (aux=g_idx, B=g_Ft), 3 = refine select (aux=g_map, P=g_P, B=g_Ft).
// Kd % 32 == 0, M % 4 == 0.
// STORE_T: C[n*ldc+m] (m,n guarded; C2 optional dup). else C[m*ldc+n] (m guarded, Ncols%128==0).
#define STG_W   1028
#define STAGE_W (4*STG_W)        // 4112 words
#define MG_SMEM (2*STAGE_W*4)    // 32896 bytes

template<int BMODE, bool STORE_T, bool RELU>
__global__ void __launch_bounds__(256, 2)
mgemm(const float* __restrict__ A, const float* __restrict__ B,
      float* __restrict__ C, float* __restrict__ C2,
      const float* __restrict__ bias,
      const float* __restrict__ P, const int* __restrict__ aux,
      int M, int Kd, int Ncols, int ldb, int ldc)
{
    extern __shared__ uint32_t sh[];
    const int t = threadIdx.x;
    const int rowTile = blockIdx.y * 128;
    const int colTile = blockIdx.x * 128;
    const int lane = t & 31, wid = t >> 5;
    const int wr = wid & 1, wc = wid >> 1;
    const int g = lane >> 2, q = lane & 3;
    const uint32_t xq = (uint32_t)(2*q) ^ ((uint32_t)((lane >> 4) & 1) << 2);

    // load mapping: row r = t>>1 (0..127), k16-group s = t&1 (16 floats each)
    const int r = t >> 1;
    const int s = t & 1;
    const uint32_t xr = ((r >> 2) & 1) << 2;
    const float* aPtr = A + (size_t)(rowTile + r) * Kd + s * 16;
    const float* bPtr;
    if (BMODE == 2) {
        int col = colTile + r;
        bPtr = B + ((size_t)(col / PP) * HW_ + aux[col]) * CCH + s * 16;
    } else if (BMODE == 3) {
        int px = colTile + r;
        int c2 = aux[px];
        bPtr = ((c2 >= 0) ? (P + (size_t)c2 * CCH) : (B + (size_t)px * CCH)) + s * 16;
    } else {
        bPtr = B + (size_t)(colTile + r) * ldb + s * 16;
    }

    float acc[4][4][4];
    #pragma unroll
    for (int i = 0; i < 4; i++)
        #pragma unroll
        for (int j = 0; j < 4; j++)
            #pragma unroll
            for (int rr = 0; rr < 4; rr++) acc[i][j][rr] = 0.f;

    const int nCh = Kd >> 5;   // BK = 32
    const uint32_t sOffA = (uint32_t)s * STG_W + (uint32_t)r * 8u;
    const uint32_t sOffB = 2u * STG_W + sOffA;

    uint4 ua0, ua1, ub0, ub1;
    ldpack(aPtr, ua0, ua1);
    ldpack(bPtr, ub0, ub1);

    // ---- store chunk 0 -> stage 0 ----
    {
        uint32_t* ap = sh + sOffA;
        *reinterpret_cast<uint4*>(ap + xr)        = ua0;
        *reinterpret_cast<uint4*>(ap + (4u ^ xr)) = ua1;
        uint32_t* bp = sh + sOffB;
        *reinterpret_cast<uint4*>(bp + xr)        = ub0;
        *reinterpret_cast<uint4*>(bp + (4u ^ xr)) = ub1;
    }
    // ---- prefetch chunk 1 ----
    if (nCh > 1) {
        aPtr += 32; bPtr += 32;
        ldpack(aPtr, ua0, ua1);
        ldpack(bPtr, ub0, ub1);
    }
    __syncthreads();

    for (int ch = 0; ch < nCh; ch++) {
        if (ch + 1 < nCh) {
            const uint32_t Sn = (uint32_t)((ch + 1) & 1) * STAGE_W;
            uint32_t* ap = sh + Sn + sOffA;
            *reinterpret_cast<uint4*>(ap + xr)        = ua0;
            *reinterpret_cast<uint4*>(ap + (4u ^ xr)) = ua1;
            uint32_t* bp = sh + Sn + sOffB;
            *reinterpret_cast<uint4*>(bp + xr)        = ub0;
            *reinterpret_cast<uint4*>(bp + (4u ^ xr)) = ub1;
            if (ch + 2 < nCh) {
                aPtr += 32; bPtr += 32;
                ldpack(aPtr, ua0, ua1);
                ldpack(bPtr, ub0, ub1);
            }
        }
        const uint32_t S = (uint32_t)(ch & 1) * STAGE_W;
        #pragma unroll
        for (int ss = 0; ss < 2; ss++) {
            const uint32_t* Ab = sh + S + (uint32_t)ss * STG_W;
            const uint32_t* Bb = sh + S + 2u * STG_W + (uint32_t)ss * STG_W;
            uint2 aF[4][2];
            #pragma unroll
            for (int i = 0; i < 4; i++) {
                const uint32_t r0 = (uint32_t)(wr * 64 + i * 16 + g);
                aF[i][0] = *reinterpret_cast<const uint2*>(Ab + r0 * 8u + xq);
                aF[i][1] = *reinterpret_cast<const uint2*>(Ab + (r0 + 8u) * 8u + xq);
            }
            #pragma unroll
            for (int j = 0; j < 4; j++) {
                const uint32_t n0 = (uint32_t)(wc * 32 + j * 8 + g);
                uint2 bF = *reinterpret_cast<const uint2*>(Bb + n0 * 8u + xq);
                #pragma unroll
                for (int i = 0; i < 4; i++)
                    mma16(acc[i][j], aF[i][0].x, aF[i][1].x, aF[i][0].y, aF[i][1].y,
                          bF.x, bF.y);
            }
        }
        __syncthreads();
    }

    // ---- bias + relu ----
    #pragma unroll
    for (int i = 0; i < 4; i++) {
        const int m0 = rowTile + wr * 64 + i * 16 + g;
        const float bv0 = bias[m0], bv1 = bias[m0 + 8];
        #pragma unroll
        for (int j = 0; j < 4; j++) {
            acc[i][j][0] += bv0; acc[i][j][1] += bv0;
            acc[i][j][2] += bv1; acc[i][j][3] += bv1;
            if (RELU) {
                acc[i][j][0] = fmaxf(acc[i][j][0], 0.f);
                acc[i][j][1] = fmaxf(acc[i][j][1], 0.f);
                acc[i][j][2] = fmaxf(acc[i][j][2], 0.f);
                acc[i][j][3] = fmaxf(acc[i][j][3], 0.f);
            }
        }
    }

    // ---- SMEM-staged coalesced epilogue (unchanged) ----
    float* stg = reinterpret_cast<float*>(sh);
    if (STORE_T) {
        #pragma unroll
        for (int pass = 0; pass < 4; pass++) {
            __syncthreads();
            if (wc == pass) {
                #pragma unroll
                for (int j = 0; j < 4; j++) {
                    const int nl = j * 8 + 2 * q;
                    #pragma unroll
                    for (int i = 0; i < 4; i++) {
                        const int ml = wr * 64 + i * 16 + g;
                        stg[nl * 132 + ml]           = acc[i][j][0];
                        stg[(nl + 1) * 132 + ml]     = acc[i][j][1];
                        stg[nl * 132 + ml + 8]       = acc[i][j][2];
                        stg[(nl + 1) * 132 + ml + 8] = acc[i][j][3];
                    }
                }
            }
            __syncthreads();
            const int cc = t >> 3;
            const int n = colTile + pass * 32 + cc;
            if (n < Ncols) {
                #pragma unroll
                for (int it = 0; it < 4; it++) {
                    const int ml = (t & 7) * 4 + it * 32;
                    const int m = rowTile + ml;
                    if (m < M) {
                        float4 v = *reinterpret_cast<float4*>(&stg[cc * 132 + ml]);
                        *reinterpret_cast<float4*>(C + (size_t)n * ldc + m) = v;
                        if (C2) *reinterpret_cast<float4*>(C2 + (size_t)n * ldc + m) = v;
                    }
                }
            }
        }
    } else {
        #pragma unroll
        for (int pass = 0; pass < 4; pass++) {
            __syncthreads();
            if (wr == (pass >> 1)) {
                #pragma unroll
                for (int ii = 0; ii < 2; ii++) {
                    const int i = (pass & 1) * 2 + ii;
                    const int rl = ii * 16 + g;
                    #pragma unroll
                    for (int j = 0; j < 4; j++) {
                        const int nl = wc * 32 + j * 8 + 2 * q;
                        stg[rl * 132 + nl]           = acc[i][j][0];
                        stg[rl * 132 + nl + 1]       = acc[i][j][1];
                        stg[(rl + 8) * 132 + nl]     = acc[i][j][2];
                        stg[(rl + 8) * 132 + nl + 1] = acc[i][j][3];
                    }
                }
            }
            __syncthreads();
            const int rr = t >> 3;
            const int m = rowTile + pass * 32 + rr;
            if (m < M) {
                #pragma unroll
                for (int it = 0; it < 4; it++) {
                    const int nl = (t & 7) * 4 + it * 32;
                    float4 v = *reinterpret_cast<float4*>(&stg[rr * 132 + nl]);
                    *reinterpret_cast<float4*>(C + (size_t)m * ldc + colTile + nl) = v;
                }
            }
        }
    }
}

// ---------------- batched 2D transpose [b][R][Cc] -> [b][Cc][R] ----------------
__global__ void transpose_k(const float* __restrict__ in, float* __restrict__ out,
                            int R, int Cc)
{
    __shared__ float tile[32][33];
    const int b = blockIdx.z;
    const float* ip = in  + (size_t)b*R*Cc;
    float*       op = out + (size_t)b*R*Cc;
    int x = blockIdx.x*32 + threadIdx.x;
    #pragma unroll
    for (int j = 0; j < 32; j += 8) {
        int y = blockIdx.y*32 + threadIdx.y + j;
        if (y < R && x < Cc) tile[threadIdx.y+j][threadIdx.x] = ip[(size_t)y*Cc + x];
    }
    __syncthreads();
    int x2 = blockIdx.y*32 + threadIdx.x;
    #pragma unroll
    for (int j = 0; j < 32; j += 8) {
        int y2 = blockIdx.x*32 + threadIdx.y + j;
        if (y2 < Cc && x2 < R) op[(size_t)y2*R + x2] = tile[threadIdx.x][threadIdx.y+j];
    }
}

// sem transpose into padded pixel-major buffer (pad rows stay zero-initialized)
__global__ void transposeS_k(const float* __restrict__ in)
{
    __shared__ float tile[32][33];
    int x = blockIdx.x*32 + threadIdx.x;
    #pragma unroll
    for (int j = 0; j < 32; j += 8) {
        int y = blockIdx.y*32 + threadIdx.y + j;
        if (x < SPIX) tile[threadIdx.y+j][threadIdx.x] = in[(size_t)y*SPIX + x];
    }
    __syncthreads();
    int pix = blockIdx.x*32 + threadIdx.y;
    int c   = blockIdx.y*32 + threadIdx.x;
    #pragma unroll
    for (int j = 0; j < 32; j += 8) {
        if (pix + j < SPIX)
            g_semFT[(size_t)(pix + j)*CCH + c] = tile[threadIdx.x][threadIdx.y+j];
    }
}

// ---------------- stack class weights (zero-padded to 256 rows) ----------------
__global__ void wid_k(const float* __restrict__ wi, const float* __restrict__ bi,
                      const float* __restrict__ wd, const float* __restrict__ bd)
{
    for (int i = threadIdx.x + blockIdx.x*blockDim.x; i < 256*CCH; i += blockDim.x*gridDim.x) {
        int r = i >> 8, c = i & 255;
        g_Wid[i] = (r < KCLS) ? wi[r*CCH + c] : (r < 160 ? wd[(r-KCLS)*CCH + c] : 0.f);
    }
    if (blockIdx.x == 0)
        for (int i = threadIdx.x; i < 256; i += blockDim.x)
            g_Bid[i] = (i < KCLS) ? bi[i] : (i < 160 ? bd[i-KCLS] : 0.f);
}

// ---------------- per-ROI label-selected maps (fp32 exact; feeds topk) ----------------
__global__ void class_select_k(const float* __restrict__ w_inst, const float* __restrict__ b_inst,
                               const float* __restrict__ w_det,  const float* __restrict__ b_det,
                               const int* __restrict__ labels, float* __restrict__ out)
{
    __shared__ float swi[CCH], swd[CCH];
    const int n = blockIdx.x;
    const int part = blockIdx.y;
    const int lab = labels[n];
    const int t = threadIdx.x;
    if (t < CCH) { swi[t] = w_inst[lab*CCH + t]; swd[t] = w_det[lab*CCH + t]; }
    __syncthreads();
    const float bi = b_inst[lab], bd = b_det[lab];
    const int lane = t & 31, w = t >> 5;
    const int pend = (part + 1) * 112;
    for (int p = part*112 + w; p < pend; p += 8) {
        const float* f = g_Ft + ((size_t)n*HW_ + p)*CCH;
        float si = 0.f, sd = 0.f;
        for (int c = lane; c < CCH; c += 32) {
            float v = f[c];
            si = fmaf(v, swi[c], si);
            sd = fmaf(v, swd[c], sd);
        }
        #pragma unroll
        for (int o = 16; o; o >>= 1) {
            si += __shfl_down_sync(0xffffffffu, si, o);
            sd += __shfl_down_sync(0xffffffffu, sd, o);
        }
        if (lane == 0) {
            out[n*HW_ + p]        = si + bi;
            out[NPIX + n*HW_ + p] = sd + bd;
        }
    }
}

// ---------------- top-196 of 784 per ROI ----------------
__global__ void topk_k(const float* __restrict__ det)
{
    __shared__ float sv[1024];
    __shared__ int   si[1024];
    const int n = blockIdx.x, t = threadIdx.x;
    for (int i = t; i < 1024; i += 512) {
        sv[i] = (i < HW_) ? det[NPIX + n*HW_ + i] : -3.4e38f;
        si[i] = i;
    }
    __syncthreads();
    for (int k2 = 2; k2 <= 1024; k2 <<= 1)
        for (int j = k2 >> 1; j > 0; j >>= 1) {
            int i = 2*t - (t & (j-1));
            int r = i + j;
            bool desc = ((i & k2) == 0);
            float vl = sv[i], vr = sv[r];
            bool sw = desc ? (vl < vr) : (vl > vr);
            if (sw) {
                sv[i] = vr; sv[r] = vl;
                int tmp = si[i]; si[i] = si[r]; si[r] = tmp;
            }
            __syncthreads();
        }
    if (t < PP) g_idx[n*PP + t] = si[t];
}

// ---------------- per-point: bilinear 'fine' into X0 rows 0..255 ----------------
__global__ void gather_k(const float* __restrict__ rois)
{
    const int col = blockIdx.x;
    const int n = col / PP;
    const int c = threadIdx.x;
    const int pix = g_idx[col];
    const float x1 = __ldg(rois + n*5 + 1), y1 = __ldg(rois + n*5 + 2);
    const float x2 = __ldg(rois + n*5 + 3), y2 = __ldg(rois + n*5 + 4);
    const float relx = ((pix % MW_) + 0.5f) / (float)MW_;
    const float rely = ((pix / MW_) + 0.5f) / (float)MH_;
    const float px = (x1 + relx*(x2 - x1)) * 0.25f - 0.5f;
    const float py = (y1 + rely*(y2 - y1)) * 0.25f - 0.5f;
    const float x0f = floorf(px), y0f = floorf(py);
    const float wx = px - x0f, wy = py - y0f;
    const int ix0 = (int)x0f, iy0 = (int)y0f;
    const int x0c = min(max(ix0, 0), SW__-1),   x1c = min(max(ix0+1, 0), SW__-1);
    const int y0c = min(max(iy0, 0), SH__-1),   y1c = min(max(iy0+1, 0), SH__-1);
    const float vx0 = (ix0   >= 0 && ix0   < SW__) ? 1.f : 0.f;
    const float vx1 = (ix0+1 >= 0 && ix0+1 < SW__) ? 1.f : 0.f;
    const float vy0 = (iy0   >= 0 && iy0   < SH__) ? 1.f : 0.f;
    const float vy1 = (iy0+1 >= 0 && iy0+1 < SH__) ? 1.f : 0.f;
    const float w00 = (1.f-wx)*(1.f-wy)*vx0*vy0;
    const float w10 = wx*(1.f-wy)*vx1*vy0;
    const float w01 = (1.f-wx)*wy*vx0*vy1;
    const float w11 = wx*wy*vx1*vy1;
    float v = w00 * g_semT[(size_t)(y0c*SW__ + x0c)*CCH + c]
            + w10 * g_semT[(size_t)(y0c*SW__ + x1c)*CCH + c]
            + w01 * g_semT[(size_t)(y1c*SW__ + x0c)*CCH + c]
            + w11 * g_semT[(size_t)(y1c*SW__ + x1c)*CCH + c];
    g_X0[(size_t)col*FCIN + c] = v;
}

// ---------------- pixel -> point-column map ----------------
__global__ void mapinit_k()
{
    for (int i = blockIdx.x*blockDim.x + threadIdx.x; i < NPIX; i += gridDim.x*blockDim.x)
        g_map[i] = -1;
}
__global__ void mapset_k()
{
    int col = blockIdx.x*blockDim.x + threadIdx.x;
    if (col < NCOL) {
        int n = col / PP;
        g_map[n*HW_ + g_idx[col]] = col;
    }
}

// ---------------- x2 bilinear upsample + relu (SMEM plane cache, plane offset) ----------------
__global__ void upsample_k(float* __restrict__ out, int planeOff)
{
    __shared__ float sf[HW_];
    const int plane = blockIdx.x + planeOff;
    const int n = plane >> 8, c = plane & 255;
    const float* f = g_F + (size_t)c*NPIX + (size_t)n*HW_;
    const int t = threadIdx.x;
    for (int i = t; i < HW_; i += blockDim.x) sf[i] = f[i];
    __syncthreads();
    float* o = out + 2*(size_t)NPIX + (size_t)plane*3136;
    for (int q4 = t; q4 < 784; q4 += blockDim.x) {
        const int oy = q4 / 14;
        const int xb = (q4 - oy*14) * 4;
        const float sy = oy*0.5f - 0.25f;
        const int iy = (int)floorf(sy);
        const float fy = sy - iy;
        const int y0c = max(iy, 0), y1c = min(iy+1, MH_-1);
        float4 v;
        float* vp = &v.x;
        #pragma unroll
        for (int j = 0; j < 4; j++) {
            const int ox = xb + j;
            const float sx = ox*0.5f - 0.25f;
            const int ix = (int)floorf(sx);
            const float fx = sx - ix;
            const int x0c = max(ix, 0), x1c = min(ix+1, MW_-1);
            float v0 = sf[y0c*MW_ + x0c]*(1.f-fx) + sf[y0c*MW_ + x1c]*fx;
            float v1 = sf[y1c*MW_ + x0c]*(1.f-fx) + sf[y1c*MW_ + x1c]*fx;
            vp[j] = fmaxf(v0*(1.f-fy) + v1*fy, 0.f);
        }
        *reinterpret_cast<float4*>(o + oy*56 + xb) = v;
    }
}

// ---------------- host orchestration (stream-forked graph) ----------------
extern "C" void kernel_launch(void* const* d_in, const int* in_sizes, int n_in,
                              void* d_out, int out_size)
{
    (void)out_size;
    const bool has_np = (n_in >= 21);
    auto IN = [&](int i) -> const void* {
        int j = (i >= 5 && !has_np) ? i - 1 : i;
        return d_in[j];
    };
    const float* inst_feats = (const float*)IN(0);
    const float* sem_feat   = (const float*)IN(1);
    const float* rois       = (const float*)IN(2);
    const int*   labels     = (const int*)  IN(3);
    const float* w_sem  = (const float*)IN(5);  const float* b_sem  = (const float*)IN(6);
    const float* w_inst = (const float*)IN(7);  const float* b_inst = (const float*)IN(8);
    const float* w_det  = (const float*)IN(9);  const float* b_det  = (const float*)IN(10);
    const float* fc_w0  = (const float*)IN(11); const float* fc_b0  = (const float*)IN(12);
    const float* fc_w1  = (const float*)IN(13); const float* fc_b1  = (const float*)IN(14);
    const float* fc_w2  = (const float*)IN(15); const float* fc_b2  = (const float*)IN(16);
    const float* w_log  = (const float*)IN(17); const float* b_log  = (const float*)IN(18);
    const float* w_fuse = (const float*)IN(19); const float* b_fuse = (const float*)IN(20);
    float* out = (float*)d_out;

    float *p_semFT, *p_semT, *p_Ft, *p_X0, *p_X1, *p_P, *p_F, *p_Wid, *p_Bid;
    int *p_idx, *p_map;
    cudaGetSymbolAddress((void**)&p_semFT, g_semFT);
    cudaGetSymbolAddress((void**)&p_semT,  g_semT);
    cudaGetSymbolAddress((void**)&p_Ft,    g_Ft);
    cudaGetSymbolAddress((void**)&p_X0,    g_X0);
    cudaGetSymbolAddress((void**)&p_X1,    g_X1);
    cudaGetSymbolAddress((void**)&p_P,     g_P);
    cudaGetSymbolAddress((void**)&p_F,     g_F);
    cudaGetSymbolAddress((void**)&p_Wid,   g_Wid);
    cudaGetSymbolAddress((void**)&p_Bid,   g_Bid);
    cudaGetSymbolAddress((void**)&p_idx,   g_idx);
    cudaGetSymbolAddress((void**)&p_map,   g_map);

    cudaFuncSetAttribute(mgemm<0, true, true >, cudaFuncAttributeMaxDynamicSharedMemorySize, MG_SMEM);
    cudaFuncSetAttribute(mgemm<0, true, false>, cudaFuncAttributeMaxDynamicSharedMemorySize, MG_SMEM);
    cudaFuncSetAttribute(mgemm<2, true, false>, cudaFuncAttributeMaxDynamicSharedMemorySize, MG_SMEM);
    cudaFuncSetAttribute(mgemm<3, false, true>, cudaFuncAttributeMaxDynamicSharedMemorySize, MG_SMEM);

    cudaStream_t s1;
    cudaStreamCreateWithFlags(&s1, cudaStreamNonBlocking);
    cudaEvent_t eFork, eIdx, eG, eFA, eJoin;
    cudaEventCreateWithFlags(&eFork, cudaEventDisableTiming);
    cudaEventCreateWithFlags(&eIdx,  cudaEventDisableTiming);
    cudaEventCreateWithFlags(&eG,    cudaEventDisableTiming);
    cudaEventCreateWithFlags(&eFA,   cudaEventDisableTiming);
    cudaEventCreateWithFlags(&eJoin, cudaEventDisableTiming);

    // ---- s0: prep + instance branch ----
    wid_k<<<64, 256>>>(w_inst, b_inst, w_det, b_det);
    mapinit_k<<<392, 256>>>();
    transpose_k<<<dim3(25, 8, NB), dim3(32, 8)>>>(inst_feats, p_Ft, CCH, HW_);
    cudaEventRecord(eFork, 0);

    // ---- s1 (forked): semantic branch ----
    cudaStreamWaitEvent(s1, eFork, 0);
    transposeS_k<<<dim3(1250, 8), dim3(32, 8), 0, s1>>>(sem_feat);
    mgemm<0, true, true><<<dim3(313, 2), 256, MG_SMEM, s1>>>(w_sem, p_semFT, p_semT, nullptr, b_sem,
                                                             nullptr, nullptr, 256, 256, SPIX, 256, 256);

    // ---- s0: class select + topk (concurrent with sem GEMM) ----
    class_select_k<<<dim3(NB, 7), 256>>>(w_inst, b_inst, w_det, b_det, labels, out);
    topk_k<<<NB, 512>>>(out);
    mapset_k<<<(NCOL + 255)/256, 256>>>();
    cudaEventRecord(eIdx, 0);

    // ---- s1: bilinear fine (needs semT + idx) ----
    cudaStreamWaitEvent(s1, eIdx, 0);
    gather_k<<<NCOL, 256, 0, s1>>>(rois);
    cudaEventRecord(eG, s1);

    // ---- s0: c_inst/c_det tails (disjoint X0/X1 rows) ----
    mgemm<2, true, false><<<dim3(196, 2), 256, MG_SMEM>>>(p_Wid, p_Ft, p_X0 + 256, p_X1 + 256, p_Bid,
                                                          nullptr, p_idx, 160, 256, NCOL, 0, FCIN);
    cudaStreamWaitEvent(0, eG, 0);

    // ---- s0: MLP chain + logits ----
    mgemm<0, true, true ><<<dim3(196, 2), 256, MG_SMEM>>>(fc_w0, p_X0, p_X1, nullptr, fc_b0,
                                                          nullptr, nullptr, 256, FCIN, NCOL, FCIN, FCIN);
    mgemm<0, true, true ><<<dim3(196, 2), 256, MG_SMEM>>>(fc_w1, p_X1, p_X0, nullptr, fc_b1,
                                                          nullptr, nullptr, 256, FCIN, NCOL, FCIN, FCIN);
    mgemm<0, true, true ><<<dim3(196, 2), 256, MG_SMEM>>>(fc_w2, p_X0, p_X1, nullptr, fc_b2,
                                                          nullptr, nullptr, 256, FCIN, NCOL, FCIN, FCIN);
    mgemm<0, true, false><<<dim3(196, 2), 256, MG_SMEM>>>(w_log, p_X1, p_P, nullptr, b_log,
                                                          nullptr, nullptr, 256, FCIN, NCOL, FCIN, CCH);

    // ---- fuse split by image halves; upsample(first) overlaps fuse(second) ----
    mgemm<3, false, true><<<dim3(392, 2), 256, MG_SMEM>>>(w_fuse, p_Ft, p_F, nullptr, b_fuse,
                                                          p_P, p_map, 256, 256, HALFPIX, 0, NPIX);
    cudaEventRecord(eFA, 0);
    mgemm<3, false, true><<<dim3(392, 2), 256, MG_SMEM>>>(w_fuse, p_Ft + (size_t)HALFPIX*CCH,
                                                          p_F + HALFPIX, nullptr, b_fuse,
                                                          p_P, p_map + HALFPIX, 256, 256, HALFPIX, 0, NPIX);
    cudaStreamWaitEvent(s1, eFA, 0);
    upsample_k<<<64*CCH, 256, 0, s1>>>(out, 0);
    upsample_k<<<64*CCH, 256>>>(out, 64*CCH);

    cudaEventRecord(eJoin, s1);
    cudaStreamWaitEvent(0, eJoin, 0);
}

// round 13
// speedup vs baseline: 1.7193x; 1.2049x over previous
#include <cuda_runtime.h>
#include <cuda_fp16.h>
#include <cstdint>
#include <math.h>

// ---------------- problem constants ----------------
#define NB   128
#define CCH  256
#define MH_  28
#define MW_  28
#define HW_  784
#define KCLS 80
#define PP   196
#define SH__ 200
#define SW__ 200
#define SPIX 40000          // 200*200
#define SPIXP 40192         // >= 313*128 (N-tile pad)
#define FCIN 416            // C + 2K
#define NCOL (NB*PP)        // 25088 point-columns
#define NPIX (NB*HW_)       // 100352 instance pixels
#define HALFPIX (NPIX/2)    // 50176 (64 images)

// ---------------- scratch (static device globals; no allocation) ----------------
// fp16 buffers declared as uint4 arrays for guaranteed 16B alignment
__device__ uint4 g_semFT16[(size_t)SPIXP*CCH/8];  // transposed semantic feat [pix][c] fp16
__device__ uint4 g_semT16 [(size_t)SPIX*CCH/8];   // relu(sem conv) [pix][o] fp16
__device__ float g_Ft  [(size_t)NPIX*CCH];        // instance feats pixel-major fp32 (exact topk path)
__device__ uint4 g_Ft16[(size_t)NPIX*CCH/8];      // fp16 copy for GEMM B-operands
__device__ uint4 g_X016[(size_t)NCOL*FCIN/8];     // MLP ping fp16
__device__ uint4 g_X116[(size_t)NCOL*FCIN/8];     // MLP pong fp16
__device__ uint4 g_P16 [(size_t)NCOL*CCH/8];      // point logits fp16
__device__ uint4 g_F16 [(size_t)CCH*NPIX/8];      // fused, channel-major fp16
__device__ int   g_idx[NB*PP];
__device__ int   g_map[NPIX];
__device__ uint4 g_Wid16  [256*CCH/8];            // stacked [w_inst; w_det; zeros] fp16
__device__ float g_Bid[256];
__device__ uint4 g_Wsem16 [256*CCH/8];
__device__ uint4 g_W016   [256*FCIN/8];
__device__ uint4 g_W116   [256*FCIN/8];
__device__ uint4 g_W216   [256*FCIN/8];
__device__ uint4 g_Wlog16 [256*FCIN/8];
__device__ uint4 g_Wfuse16[256*CCH/8];

// ---------------- fp16 helpers ----------------
__device__ __forceinline__ uint32_t pack_h2(float lo, float hi) {
    uint32_t r; asm("cvt.rn.f16x2.f32 %0, %1, %2;" : "=r"(r) : "f"(hi), "f"(lo)); return r;
}
__device__ __forceinline__ void mma16(float* c,
                                      uint32_t a0, uint32_t a1, uint32_t a2, uint32_t a3,
                                      uint32_t b0, uint32_t b1) {
    asm volatile("mma.sync.aligned.m16n8k16.row.col.f32.f16.f16.f32 "
                 "{%0,%1,%2,%3}, {%4,%5,%6,%7}, {%8,%9}, {%0,%1,%2,%3};"
                 : "+f"(c[0]), "+f"(c[1]), "+f"(c[2]), "+f"(c[3])
                 : "r"(a0), "r"(a1), "r"(a2), "r"(a3), "r"(b0), "r"(b1));
}
// store 16 halves (2 raw uint4) into swizzled SMEM in permuted word order
// words w0..w7 (w = k-pair): layout [w0,w4,w1,w5 | w2,w6,w3,w7]
__device__ __forceinline__ void stperm(uint32_t* base, uint32_t xr, uint4 u0, uint4 u1) {
    *reinterpret_cast<uint4*>(base + xr)        = make_uint4(u0.x, u1.x, u0.y, u1.y);
    *reinterpret_cast<uint4*>(base + (4u ^ xr)) = make_uint4(u0.z, u1.z, u0.w, u1.w);
}

// ================= fp16 tensor-core TN GEMM v6 (fp16 in / fp16 out) =================
// CTA tile 128x128, 8 warps (2m x 4n, warp tile 64x32), BK=32, double-buffered, 2 CTAs/SM.
// A,B fp16. BMODE 0: B[col][Kd] stride ldb; 2: gathered rows (aux=g_idx, B=Ft16);
// 3: refine select (aux=g_map, P=P16, B=Ft16). Kd%32==0, M%4==0.
// STORE_T: C[n*ldc+m] fp16 (m,n guarded; C2 dup). else C[m*ldc+n] fp16 (m guarded, Ncols%128==0).
#define STG_W   1028
#define STAGE_W (4*STG_W)
#define MG_SMEM (2*STAGE_W*4)    // 32896 bytes

template<int BMODE, bool STORE_T, bool RELU>
__global__ void __launch_bounds__(256, 2)
mgemm(const __half* __restrict__ A, const __half* __restrict__ B,
      __half* __restrict__ C, __half* __restrict__ C2,
      const float* __restrict__ bias,
      const __half* __restrict__ P, const int* __restrict__ aux,
      int M, int Kd, int Ncols, int ldb, int ldc)
{
    extern __shared__ uint32_t sh[];
    const int t = threadIdx.x;
    const int rowTile = blockIdx.y * 128;
    const int colTile = blockIdx.x * 128;
    const int lane = t & 31, wid = t >> 5;
    const int wr = wid & 1, wc = wid >> 1;
    const int g = lane >> 2, q = lane & 3;
    const uint32_t xq = (uint32_t)(2*q) ^ ((uint32_t)((lane >> 4) & 1) << 2);

    const int r = t >> 1;
    const int s = t & 1;
    const uint32_t xr = ((r >> 2) & 1) << 2;
    const __half* aPtr = A + (size_t)(rowTile + r) * Kd + s * 16;
    const __half* bPtr;
    if (BMODE == 2) {
        int col = colTile + r;
        bPtr = B + ((size_t)(col / PP) * HW_ + aux[col]) * CCH + s * 16;
    } else if (BMODE == 3) {
        int px = colTile + r;
        int c2 = aux[px];
        bPtr = ((c2 >= 0) ? (P + (size_t)c2 * CCH) : (B + (size_t)px * CCH)) + s * 16;
    } else {
        bPtr = B + (size_t)(colTile + r) * ldb + s * 16;
    }

    float acc[4][4][4];
    #pragma unroll
    for (int i = 0; i < 4; i++)
        #pragma unroll
        for (int j = 0; j < 4; j++)
            #pragma unroll
            for (int rr = 0; rr < 4; rr++) acc[i][j][rr] = 0.f;

    const int nCh = Kd >> 5;   // BK = 32
    const uint32_t sOffA = (uint32_t)s * STG_W + (uint32_t)r * 8u;
    const uint32_t sOffB = 2u * STG_W + sOffA;

    uint4 ua0 = reinterpret_cast<const uint4*>(aPtr)[0];
    uint4 ua1 = reinterpret_cast<const uint4*>(aPtr)[1];
    uint4 ub0 = reinterpret_cast<const uint4*>(bPtr)[0];
    uint4 ub1 = reinterpret_cast<const uint4*>(bPtr)[1];

    stperm(sh + sOffA, xr, ua0, ua1);
    stperm(sh + sOffB, xr, ub0, ub1);
    if (nCh > 1) {
        aPtr += 32; bPtr += 32;
        ua0 = reinterpret_cast<const uint4*>(aPtr)[0];
        ua1 = reinterpret_cast<const uint4*>(aPtr)[1];
        ub0 = reinterpret_cast<const uint4*>(bPtr)[0];
        ub1 = reinterpret_cast<const uint4*>(bPtr)[1];
    }
    __syncthreads();

    for (int ch = 0; ch < nCh; ch++) {
        if (ch + 1 < nCh) {
            const uint32_t Sn = (uint32_t)((ch + 1) & 1) * STAGE_W;
            stperm(sh + Sn + sOffA, xr, ua0, ua1);
            stperm(sh + Sn + sOffB, xr, ub0, ub1);
            if (ch + 2 < nCh) {
                aPtr += 32; bPtr += 32;
                ua0 = reinterpret_cast<const uint4*>(aPtr)[0];
                ua1 = reinterpret_cast<const uint4*>(aPtr)[1];
                ub0 = reinterpret_cast<const uint4*>(bPtr)[0];
                ub1 = reinterpret_cast<const uint4*>(bPtr)[1];
            }
        }
        const uint32_t S = (uint32_t)(ch & 1) * STAGE_W;
        #pragma unroll
        for (int ss = 0; ss < 2; ss++) {
            const uint32_t* Ab = sh + S + (uint32_t)ss * STG_W;
            const uint32_t* Bb = sh + S + 2u * STG_W + (uint32_t)ss * STG_W;
            uint2 aF[4][2];
            #pragma unroll
            for (int i = 0; i < 4; i++) {
                const uint32_t r0 = (uint32_t)(wr * 64 + i * 16 + g);
                aF[i][0] = *reinterpret_cast<const uint2*>(Ab + r0 * 8u + xq);
                aF[i][1] = *reinterpret_cast<const uint2*>(Ab + (r0 + 8u) * 8u + xq);
            }
            #pragma unroll
            for (int j = 0; j < 4; j++) {
                const uint32_t n0 = (uint32_t)(wc * 32 + j * 8 + g);
                uint2 bF = *reinterpret_cast<const uint2*>(Bb + n0 * 8u + xq);
                #pragma unroll
                for (int i = 0; i < 4; i++)
                    mma16(acc[i][j], aF[i][0].x, aF[i][1].x, aF[i][0].y, aF[i][1].y,
                          bF.x, bF.y);
            }
        }
        __syncthreads();
    }

    // ---- bias + relu ----
    #pragma unroll
    for (int i = 0; i < 4; i++) {
        const int m0 = rowTile + wr * 64 + i * 16 + g;
        const float bv0 = bias[m0], bv1 = bias[m0 + 8];
        #pragma unroll
        for (int j = 0; j < 4; j++) {
            acc[i][j][0] += bv0; acc[i][j][1] += bv0;
            acc[i][j][2] += bv1; acc[i][j][3] += bv1;
            if (RELU) {
                acc[i][j][0] = fmaxf(acc[i][j][0], 0.f);
                acc[i][j][1] = fmaxf(acc[i][j][1], 0.f);
                acc[i][j][2] = fmaxf(acc[i][j][2], 0.f);
                acc[i][j][3] = fmaxf(acc[i][j][3], 0.f);
            }
        }
    }

    // ---- SMEM-staged coalesced epilogue (fp16 global stores) ----
    float* stg = reinterpret_cast<float*>(sh);
    if (STORE_T) {
        #pragma unroll
        for (int pass = 0; pass < 4; pass++) {
            __syncthreads();
            if (wc == pass) {
                #pragma unroll
                for (int j = 0; j < 4; j++) {
                    const int nl = j * 8 + 2 * q;
                    #pragma unroll
                    for (int i = 0; i < 4; i++) {
                        const int ml = wr * 64 + i * 16 + g;
                        stg[nl * 132 + ml]           = acc[i][j][0];
                        stg[(nl + 1) * 132 + ml]     = acc[i][j][1];
                        stg[nl * 132 + ml + 8]       = acc[i][j][2];
                        stg[(nl + 1) * 132 + ml + 8] = acc[i][j][3];
                    }
                }
            }
            __syncthreads();
            const int cc = t >> 3;
            const int n = colTile + pass * 32 + cc;
            if (n < Ncols) {
                #pragma unroll
                for (int it = 0; it < 4; it++) {
                    const int ml = (t & 7) * 4 + it * 32;
                    const int m = rowTile + ml;
                    if (m < M) {
                        float4 v = *reinterpret_cast<float4*>(&stg[cc * 132 + ml]);
                        uint2 h = make_uint2(pack_h2(v.x, v.y), pack_h2(v.z, v.w));
                        *reinterpret_cast<uint2*>(C + (size_t)n * ldc + m) = h;
                        if (C2) *reinterpret_cast<uint2*>(C2 + (size_t)n * ldc + m) = h;
                    }
                }
            }
        }
    } else {
        #pragma unroll
        for (int pass = 0; pass < 4; pass++) {
            __syncthreads();
            if (wr == (pass >> 1)) {
                #pragma unroll
                for (int ii = 0; ii < 2; ii++) {
                    const int i = (pass & 1) * 2 + ii;
                    const int rl = ii * 16 + g;
                    #pragma unroll
                    for (int j = 0; j < 4; j++) {
                        const int nl = wc * 32 + j * 8 + 2 * q;
                        stg[rl * 132 + nl]           = acc[i][j][0];
                        stg[rl * 132 + nl + 1]       = acc[i][j][1];
                        stg[(rl + 8) * 132 + nl]     = acc[i][j][2];
                        stg[(rl + 8) * 132 + nl + 1] = acc[i][j][3];
                    }
                }
            }
            __syncthreads();
            const int rr = t >> 3;
            const int m = rowTile + pass * 32 + rr;
            if (m < M) {
                #pragma unroll
                for (int it = 0; it < 4; it++) {
                    const int nl = (t & 7) * 4 + it * 32;
                    float4 v = *reinterpret_cast<float4*>(&stg[rr * 132 + nl]);
                    uint2 h = make_uint2(pack_h2(v.x, v.y), pack_h2(v.z, v.w));
                    *reinterpret_cast<uint2*>(C + (size_t)m * ldc + colTile + nl) = h;
                }
            }
        }
    }
}

// ---------------- weight pack: fp32 -> fp16 ----------------
__global__ void packw_k(const float* __restrict__ src, __half* __restrict__ dst, int n)
{
    int i = blockIdx.x*blockDim.x + threadIdx.x;
    if (i < n) dst[i] = __float2half_rn(src[i]);
}

// ---------------- batched 2D transpose, dual fp32+fp16 output ----------------
__global__ void transpose_k(const float* __restrict__ in, float* __restrict__ out,
                            __half* __restrict__ out16, int R, int Cc)
{
    __shared__ float tile[32][33];
    const int b = blockIdx.z;
    const float* ip = in  + (size_t)b*R*Cc;
    float*       op = out + (size_t)b*R*Cc;
    __half*      oh = out16 + (size_t)b*R*Cc;
    int x = blockIdx.x*32 + threadIdx.x;
    #pragma unroll
    for (int j = 0; j < 32; j += 8) {
        int y = blockIdx.y*32 + threadIdx.y + j;
        if (y < R && x < Cc) tile[threadIdx.y+j][threadIdx.x] = ip[(size_t)y*Cc + x];
    }
    __syncthreads();
    int x2 = blockIdx.y*32 + threadIdx.x;
    #pragma unroll
    for (int j = 0; j < 32; j += 8) {
        int y2 = blockIdx.x*32 + threadIdx.y + j;
        if (y2 < Cc && x2 < R) {
            float v = tile[threadIdx.x][threadIdx.y+j];
            op[(size_t)y2*R + x2] = v;
            oh[(size_t)y2*R + x2] = __float2half_rn(v);
        }
    }
}

// sem transpose into padded fp16 pixel-major buffer
__global__ void transposeS_k(const float* __restrict__ in, __half* __restrict__ out16)
{
    __shared__ float tile[32][33];
    int x = blockIdx.x*32 + threadIdx.x;
    #pragma unroll
    for (int j = 0; j < 32; j += 8) {
        int y = blockIdx.y*32 + threadIdx.y + j;
        if (x < SPIX) tile[threadIdx.y+j][threadIdx.x] = in[(size_t)y*SPIX + x];
    }
    __syncthreads();
    int pix = blockIdx.x*32 + threadIdx.y;
    int c   = blockIdx.y*32 + threadIdx.x;
    #pragma unroll
    for (int j = 0; j < 32; j += 8) {
        if (pix + j < SPIX)
            out16[(size_t)(pix + j)*CCH + c] = __float2half_rn(tile[threadIdx.x][threadIdx.y+j]);
    }
}

// ---------------- stack class weights -> fp16 (zero-padded to 256 rows) ----------------
__global__ void wid_k(const float* __restrict__ wi, const float* __restrict__ bi,
                      const float* __restrict__ wd, const float* __restrict__ bd,
                      __half* __restrict__ dst)
{
    for (int i = threadIdx.x + blockIdx.x*blockDim.x; i < 256*CCH; i += blockDim.x*gridDim.x) {
        int r = i >> 8, c = i & 255;
        float v = (r < KCLS) ? wi[r*CCH + c] : (r < 160 ? wd[(r-KCLS)*CCH + c] : 0.f);
        dst[i] = __float2half_rn(v);
    }
    if (blockIdx.x == 0)
        for (int i = threadIdx.x; i < 256; i += blockDim.x)
            g_Bid[i] = (i < KCLS) ? bi[i] : (i < 160 ? bd[i-KCLS] : 0.f);
}

// ---------------- per-ROI label-selected maps (fp32 exact; feeds topk) ----------------
__global__ void class_select_k(const float* __restrict__ w_inst, const float* __restrict__ b_inst,
                               const float* __restrict__ w_det,  const float* __restrict__ b_det,
                               const int* __restrict__ labels, float* __restrict__ out)
{
    __shared__ float swi[CCH], swd[CCH];
    const int n = blockIdx.x;
    const int part = blockIdx.y;
    const int lab = labels[n];
    const int t = threadIdx.x;
    if (t < CCH) { swi[t] = w_inst[lab*CCH + t]; swd[t] = w_det[lab*CCH + t]; }
    __syncthreads();
    const float bi = b_inst[lab], bd = b_det[lab];
    const int lane = t & 31, w = t >> 5;
    const int pend = (part + 1) * 112;
    for (int p = part*112 + w; p < pend; p += 8) {
        const float* f = g_Ft + ((size_t)n*HW_ + p)*CCH;
        float si = 0.f, sd = 0.f;
        for (int c = lane; c < CCH; c += 32) {
            float v = f[c];
            si = fmaf(v, swi[c], si);
            sd = fmaf(v, swd[c], sd);
        }
        #pragma unroll
        for (int o = 16; o; o >>= 1) {
            si += __shfl_down_sync(0xffffffffu, si, o);
            sd += __shfl_down_sync(0xffffffffu, sd, o);
        }
        if (lane == 0) {
            out[n*HW_ + p]        = si + bi;
            out[NPIX + n*HW_ + p] = sd + bd;
        }
    }
}

// ---------------- top-196 of 784 per ROI ----------------
__global__ void topk_k(const float* __restrict__ det)
{
    __shared__ float sv[1024];
    __shared__ int   si[1024];
    const int n = blockIdx.x, t = threadIdx.x;
    for (int i = t; i < 1024; i += 512) {
        sv[i] = (i < HW_) ? det[NPIX + n*HW_ + i] : -3.4e38f;
        si[i] = i;
    }
    __syncthreads();
    for (int k2 = 2; k2 <= 1024; k2 <<= 1)
        for (int j = k2 >> 1; j > 0; j >>= 1) {
            int i = 2*t - (t & (j-1));
            int r = i + j;
            bool desc = ((i & k2) == 0);
            float vl = sv[i], vr = sv[r];
            bool sw = desc ? (vl < vr) : (vl > vr);
            if (sw) {
                sv[i] = vr; sv[r] = vl;
                int tmp = si[i]; si[i] = si[r]; si[r] = tmp;
            }
            __syncthreads();
        }
    if (t < PP) g_idx[n*PP + t] = si[t];
}

// ---------------- per-point: bilinear 'fine' (fp16 in) -> X0 fp16 rows 0..255 ----------------
__global__ void gather_k(const float* __restrict__ rois,
                         const __half* __restrict__ semT, __half* __restrict__ X0)
{
    const int col = blockIdx.x;
    const int n = col / PP;
    const int c = threadIdx.x;
    const int pix = g_idx[col];
    const float x1 = __ldg(rois + n*5 + 1), y1 = __ldg(rois + n*5 + 2);
    const float x2 = __ldg(rois + n*5 + 3), y2 = __ldg(rois + n*5 + 4);
    const float relx = ((pix % MW_) + 0.5f) / (float)MW_;
    const float rely = ((pix / MW_) + 0.5f) / (float)MH_;
    const float px = (x1 + relx*(x2 - x1)) * 0.25f - 0.5f;
    const float py = (y1 + rely*(y2 - y1)) * 0.25f - 0.5f;
    const float x0f = floorf(px), y0f = floorf(py);
    const float wx = px - x0f, wy = py - y0f;
    const int ix0 = (int)x0f, iy0 = (int)y0f;
    const int x0c = min(max(ix0, 0), SW__-1),   x1c = min(max(ix0+1, 0), SW__-1);
    const int y0c = min(max(iy0, 0), SH__-1),   y1c = min(max(iy0+1, 0), SH__-1);
    const float vx0 = (ix0   >= 0 && ix0   < SW__) ? 1.f : 0.f;
    const float vx1 = (ix0+1 >= 0 && ix0+1 < SW__) ? 1.f : 0.f;
    const float vy0 = (iy0   >= 0 && iy0   < SH__) ? 1.f : 0.f;
    const float vy1 = (iy0+1 >= 0 && iy0+1 < SH__) ? 1.f : 0.f;
    const float w00 = (1.f-wx)*(1.f-wy)*vx0*vy0;
    const float w10 = wx*(1.f-wy)*vx1*vy0;
    const float w01 = (1.f-wx)*wy*vx0*vy1;
    const float w11 = wx*wy*vx1*vy1;
    float v = w00 * __half2float(semT[(size_t)(y0c*SW__ + x0c)*CCH + c])
            + w10 * __half2float(semT[(size_t)(y0c*SW__ + x1c)*CCH + c])
            + w01 * __half2float(semT[(size_t)(y1c*SW__ + x0c)*CCH + c])
            + w11 * __half2float(semT[(size_t)(y1c*SW__ + x1c)*CCH + c]);
    X0[(size_t)col*FCIN + c] = __float2half_rn(v);
}

// ---------------- pixel -> point-column map ----------------
__global__ void mapinit_k()
{
    for (int i = blockIdx.x*blockDim.x + threadIdx.x; i < NPIX; i += gridDim.x*blockDim.x)
        g_map[i] = -1;
}
__global__ void mapset_k()
{
    int col = blockIdx.x*blockDim.x + threadIdx.x;
    if (col < NCOL) {
        int n = col / PP;
        g_map[n*HW_ + g_idx[col]] = col;
    }
}

// ---------------- x2 bilinear upsample + relu (fp16 in, fp32 out) ----------------
__global__ void upsample_k(const __half* __restrict__ F16, float* __restrict__ out, int planeOff)
{
    __shared__ float sf[HW_];
    const int plane = blockIdx.x + planeOff;
    const int n = plane >> 8, c = plane & 255;
    const __half* f = F16 + (size_t)c*NPIX + (size_t)n*HW_;
    const int t = threadIdx.x;
    for (int i = t; i < HW_; i += blockDim.x) sf[i] = __half2float(f[i]);
    __syncthreads();
    float* o = out + 2*(size_t)NPIX + (size_t)plane*3136;
    for (int q4 = t; q4 < 784; q4 += blockDim.x) {
        const int oy = q4 / 14;
        const int xb = (q4 - oy*14) * 4;
        const float sy = oy*0.5f - 0.25f;
        const int iy = (int)floorf(sy);
        const float fy = sy - iy;
        const int y0c = max(iy, 0), y1c = min(iy+1, MH_-1);
        float4 v;
        float* vp = &v.x;
        #pragma unroll
        for (int j = 0; j < 4; j++) {
            const int ox = xb + j;
            const float sx = ox*0.5f - 0.25f;
            const int ix = (int)floorf(sx);
            const float fx = sx - ix;
            const int x0c = max(ix, 0), x1c = min(ix+1, MW_-1);
            float v0 = sf[y0c*MW_ + x0c]*(1.f-fx) + sf[y0c*MW_ + x1c]*fx;
            float v1 = sf[y1c*MW_ + x0c]*(1.f-fx) + sf[y1c*MW_ + x1c]*fx;
            vp[j] = fmaxf(v0*(1.f-fy) + v1*fy, 0.f);
        }
        *reinterpret_cast<float4*>(o + oy*56 + xb) = v;
    }
}

// ---------------- host orchestration (stream-forked graph) ----------------
extern "C" void kernel_launch(void* const* d_in, const int* in_sizes, int n_in,
                              void* d_out, int out_size)
{
    (void)out_size;
    const bool has_np = (n_in >= 21);
    auto IN = [&](int i) -> const void* {
        int j = (i >= 5 && !has_np) ? i - 1 : i;
        return d_in[j];
    };
    const float* inst_feats = (const float*)IN(0);
    const float* sem_feat   = (const float*)IN(1);
    const float* rois       = (const float*)IN(2);
    const int*   labels     = (const int*)  IN(3);
    const float* w_sem  = (const float*)IN(5);  const float* b_sem  = (const float*)IN(6);
    const float* w_inst = (const float*)IN(7);  const float* b_inst = (const float*)IN(8);
    const float* w_det  = (const float*)IN(9);  const float* b_det  = (const float*)IN(10);
    const float* fc_w0  = (const float*)IN(11); const float* fc_b0  = (const float*)IN(12);
    const float* fc_w1  = (const float*)IN(13); const float* fc_b1  = (const float*)IN(14);
    const float* fc_w2  = (const float*)IN(15); const float* fc_b2  = (const float*)IN(16);
    const float* w_log  = (const float*)IN(17); const float* b_log  = (const float*)IN(18);
    const float* w_fuse = (const float*)IN(19); const float* b_fuse = (const float*)IN(20);
    float* out = (float*)d_out;

    float *p_Ft, *p_Bid;
    __half *p_semFT, *p_semT, *p_Ft16, *p_X0, *p_X1, *p_P, *p_F;
    __half *p_Wid, *p_Wsem, *p_W0, *p_W1, *p_W2, *p_Wlog, *p_Wfuse;
    int *p_idx, *p_map;
    cudaGetSymbolAddress((void**)&p_semFT, g_semFT16);
    cudaGetSymbolAddress((void**)&p_semT,  g_semT16);
    cudaGetSymbolAddress((void**)&p_Ft,    g_Ft);
    cudaGetSymbolAddress((void**)&p_Ft16,  g_Ft16);
    cudaGetSymbolAddress((void**)&p_X0,    g_X016);
    cudaGetSymbolAddress((void**)&p_X1,    g_X116);
    cudaGetSymbolAddress((void**)&p_P,     g_P16);
    cudaGetSymbolAddress((void**)&p_F,     g_F16);
    cudaGetSymbolAddress((void**)&p_Wid,   g_Wid16);
    cudaGetSymbolAddress((void**)&p_Bid,   g_Bid);
    cudaGetSymbolAddress((void**)&p_Wsem,  g_Wsem16);
    cudaGetSymbolAddress((void**)&p_W0,    g_W016);
    cudaGetSymbolAddress((void**)&p_W1,    g_W116);
    cudaGetSymbolAddress((void**)&p_W2,    g_W216);
    cudaGetSymbolAddress((void**)&p_Wlog,  g_Wlog16);
    cudaGetSymbolAddress((void**)&p_Wfuse, g_Wfuse16);
    cudaGetSymbolAddress((void**)&p_idx,   g_idx);
    cudaGetSymbolAddress((void**)&p_map,   g_map);

    cudaFuncSetAttribute(mgemm<0, true, true >, cudaFuncAttributeMaxDynamicSharedMemorySize, MG_SMEM);
    cudaFuncSetAttribute(mgemm<0, true, false>, cudaFuncAttributeMaxDynamicSharedMemorySize, MG_SMEM);
    cudaFuncSetAttribute(mgemm<2, true, false>, cudaFuncAttributeMaxDynamicSharedMemorySize, MG_SMEM);
    cudaFuncSetAttribute(mgemm<3, false, true>, cudaFuncAttributeMaxDynamicSharedMemorySize, MG_SMEM);

    cudaStream_t s1;
    cudaStreamCreateWithFlags(&s1, cudaStreamNonBlocking);
    cudaEvent_t eFork, eIdx, eG, eFA, eJoin;
    cudaEventCreateWithFlags(&eFork, cudaEventDisableTiming);
    cudaEventCreateWithFlags(&eIdx,  cudaEventDisableTiming);
    cudaEventCreateWithFlags(&eG,    cudaEventDisableTiming);
    cudaEventCreateWithFlags(&eFA,   cudaEventDisableTiming);
    cudaEventCreateWithFlags(&eJoin, cudaEventDisableTiming);

    // ---- s0: weight packs + prep + instance branch ----
    wid_k<<<64, 256>>>(w_inst, b_inst, w_det, b_det, p_Wid);
    packw_k<<<(256*CCH + 255)/256, 256>>>(w_sem,  p_Wsem,  256*CCH);
    packw_k<<<(256*FCIN + 255)/256, 256>>>(fc_w0, p_W0,    256*FCIN);
    packw_k<<<(256*FCIN + 255)/256, 256>>>(fc_w1, p_W1,    256*FCIN);
    packw_k<<<(256*FCIN + 255)/256, 256>>>(fc_w2, p_W2,    256*FCIN);
    packw_k<<<(256*FCIN + 255)/256, 256>>>(w_log, p_Wlog,  256*FCIN);
    packw_k<<<(256*CCH + 255)/256, 256>>>(w_fuse, p_Wfuse, 256*CCH);
    mapinit_k<<<392, 256>>>();
    transpose_k<<<dim3(25, 8, NB), dim3(32, 8)>>>(inst_feats, p_Ft, p_Ft16, CCH, HW_);
    cudaEventRecord(eFork, 0);

    // ---- s1 (forked): semantic branch ----
    cudaStreamWaitEvent(s1, eFork, 0);
    transposeS_k<<<dim3(1250, 8), dim3(32, 8), 0, s1>>>(sem_feat, p_semFT);
    mgemm<0, true, true><<<dim3(313, 2), 256, MG_SMEM, s1>>>(p_Wsem, p_semFT, p_semT, nullptr, b_sem,
                                                             nullptr, nullptr, 256, 256, SPIX, 256, 256);

    // ---- s0: class select + topk (concurrent with sem GEMM) ----
    class_select_k<<<dim3(NB, 7), 256>>>(w_inst, b_inst, w_det, b_det, labels, out);
    topk_k<<<NB, 512>>>(out);
    mapset_k<<<(NCOL + 255)/256, 256>>>();
    cudaEventRecord(eIdx, 0);

    // ---- s1: bilinear fine (needs semT + idx) ----
    cudaStreamWaitEvent(s1, eIdx, 0);
    gather_k<<<NCOL, 256, 0, s1>>>(rois, p_semT, p_X0);
    cudaEventRecord(eG, s1);

    // ---- s0: c_inst/c_det tails (disjoint X0/X1 rows) ----
    mgemm<2, true, false><<<dim3(196, 2), 256, MG_SMEM>>>(p_Wid, p_Ft16, p_X0 + 256, p_X1 + 256, p_Bid,
                                                          nullptr, p_idx, 160, 256, NCOL, 0, FCIN);
    cudaStreamWaitEvent(0, eG, 0);

    // ---- s0: MLP chain + logits ----
    mgemm<0, true, true ><<<dim3(196, 2), 256, MG_SMEM>>>(p_W0, p_X0, p_X1, nullptr, fc_b0,
                                                          nullptr, nullptr, 256, FCIN, NCOL, FCIN, FCIN);
    mgemm<0, true, true ><<<dim3(196, 2), 256, MG_SMEM>>>(p_W1, p_X1, p_X0, nullptr, fc_b1,
                                                          nullptr, nullptr, 256, FCIN, NCOL, FCIN, FCIN);
    mgemm<0, true, true ><<<dim3(196, 2), 256, MG_SMEM>>>(p_W2, p_X0, p_X1, nullptr, fc_b2,
                                                          nullptr, nullptr, 256, FCIN, NCOL, FCIN, FCIN);
    mgemm<0, true, false><<<dim3(196, 2), 256, MG_SMEM>>>(p_Wlog, p_X1, p_P, nullptr, b_log,
                                                          nullptr, nullptr, 256, FCIN, NCOL, FCIN, CCH);

    // ---- fuse split by image halves; upsample(first) overlaps fuse(second) ----
    mgemm<3, false, true><<<dim3(392, 2), 256, MG_SMEM>>>(p_Wfuse, p_Ft16, p_F, nullptr, b_fuse,
                                                          p_P, p_map, 256, 256, HALFPIX, 0, NPIX);
    cudaEventRecord(eFA, 0);
    mgemm<3, false, true><<<dim3(392, 2), 256, MG_SMEM>>>(p_Wfuse, p_Ft16 + (size_t)HALFPIX*CCH,
                                                          p_F + HALFPIX, nullptr, b_fuse,
                                                          p_P, p_map + HALFPIX, 256, 256, HALFPIX, 0, NPIX);
    cudaStreamWaitEvent(s1, eFA, 0);
    upsample_k<<<64*CCH, 256, 0, s1>>>(p_F, out, 0);
    upsample_k<<<64*CCH, 256>>>(p_F, out, 64*CCH);

    cudaEventRecord(eJoin, s1);
    cudaStreamWaitEvent(0, eJoin, 0);
}

// round 14
// speedup vs baseline: 1.7952x; 1.0441x over previous
#include <cuda_runtime.h>
#include <cuda_fp16.h>
#include <cstdint>
#include <math.h>

// ---------------- problem constants ----------------
#define NB   128
#define CCH  256
#define MH_  28
#define MW_  28
#define HW_  784
#define KCLS 80
#define PP   196
#define SH__ 200
#define SW__ 200
#define SPIX 40000          // 200*200
#define SPIXP 40192         // >= 313*128 (N-tile pad)
#define FCIN 416            // C + 2K
#define NCOL (NB*PP)        // 25088 point-columns
#define NPIX (NB*HW_)       // 100352 instance pixels
#define HALFPIX (NPIX/2)    // 50176 (64 images)

// ---------------- scratch (static device globals; no allocation) ----------------
__device__ uint4 g_semFT16[(size_t)SPIXP*CCH/8];  // transposed semantic feat [pix][c] fp16
__device__ uint4 g_semT16 [(size_t)SPIX*CCH/8];   // relu(sem conv) [pix][o] fp16
__device__ uint4 g_Ft16[(size_t)NPIX*CCH/8];      // instance feats pixel-major fp16 (GEMM B)
__device__ uint4 g_X016[(size_t)NCOL*FCIN/8];     // MLP ping fp16
__device__ uint4 g_X116[(size_t)NCOL*FCIN/8];     // MLP pong fp16
__device__ uint4 g_P16 [(size_t)NCOL*CCH/8];      // point logits fp16
__device__ uint4 g_F16 [(size_t)CCH*NPIX/8];      // fused, channel-major fp16
__device__ int   g_idx[NB*PP];
__device__ int   g_map[NPIX];
__device__ uint4 g_Wid16  [256*CCH/8];            // stacked [w_inst; w_det; zeros] fp16
__device__ float g_Bid[256];
__device__ uint4 g_Wsem16 [256*CCH/8];
__device__ uint4 g_W016   [256*FCIN/8];
__device__ uint4 g_W116   [256*FCIN/8];
__device__ uint4 g_W216   [256*FCIN/8];
__device__ uint4 g_Wlog16 [256*FCIN/8];
__device__ uint4 g_Wfuse16[256*CCH/8];

// ---------------- fp16 helpers ----------------
__device__ __forceinline__ uint32_t pack_h2(float lo, float hi) {
    uint32_t r; asm("cvt.rn.f16x2.f32 %0, %1, %2;" : "=r"(r) : "f"(hi), "f"(lo)); return r;
}
__device__ __forceinline__ void mma16(float* c,
                                      uint32_t a0, uint32_t a1, uint32_t a2, uint32_t a3,
                                      uint32_t b0, uint32_t b1) {
    asm volatile("mma.sync.aligned.m16n8k16.row.col.f32.f16.f16.f32 "
                 "{%0,%1,%2,%3}, {%4,%5,%6,%7}, {%8,%9}, {%0,%1,%2,%3};"
                 : "+f"(c[0]), "+f"(c[1]), "+f"(c[2]), "+f"(c[3])
                 : "r"(a0), "r"(a1), "r"(a2), "r"(a3), "r"(b0), "r"(b1));
}
// store 16 halves (2 raw uint4) into swizzled SMEM in permuted word order
__device__ __forceinline__ void stperm(uint32_t* base, uint32_t xr, uint4 u0, uint4 u1) {
    *reinterpret_cast<uint4*>(base + xr)        = make_uint4(u0.x, u1.x, u0.y, u1.y);
    *reinterpret_cast<uint4*>(base + (4u ^ xr)) = make_uint4(u0.z, u1.z, u0.w, u1.w);
}

// ================= fp16 tensor-core TN GEMM v7 =================
// CTA tile 128x128, 8 warps (2m x 4n, warp tile 64x32), BK=32, double-buffered, 2 CTAs/SM.
// BMODE 0: B[col][Kd] stride ldb; 2: gathered rows (aux=g_idx, B=Ft16);
// 3: refine select (aux=g_map, P=P16, B=Ft16). Kd%32==0, M%4==0.
// STORE_T: C[n*ldc+m] fp16 (m,n guarded; C2 dup) — single-shot 128x132 staged epilogue
//          (needs 67584 B dynamic SMEM). else C[m*ldc+n] fp16 (4-pass epilogue; 32896 B).
#define STG_W   1028
#define STAGE_W (4*STG_W)
#define MG_SMEM_T 67584          // full-tile staging for STORE_T
#define MG_SMEM_N (2*STAGE_W*4)  // 32896

template<int BMODE, bool STORE_T, bool RELU>
__global__ void __launch_bounds__(256, 2)
mgemm(const __half* __restrict__ A, const __half* __restrict__ B,
      __half* __restrict__ C, __half* __restrict__ C2,
      const float* __restrict__ bias,
      const __half* __restrict__ P, const int* __restrict__ aux,
      int M, int Kd, int Ncols, int ldb, int ldc)
{
    extern __shared__ uint32_t sh[];
    const int t = threadIdx.x;
    const int rowTile = blockIdx.y * 128;
    const int colTile = blockIdx.x * 128;
    const int lane = t & 31, wid = t >> 5;
    const int wr = wid & 1, wc = wid >> 1;
    const int g = lane >> 2, q = lane & 3;
    const uint32_t xq = (uint32_t)(2*q) ^ ((uint32_t)((lane >> 4) & 1) << 2);

    const int r = t >> 1;
    const int s = t & 1;
    const uint32_t xr = ((r >> 2) & 1) << 2;
    const __half* aPtr = A + (size_t)(rowTile + r) * Kd + s * 16;
    const __half* bPtr;
    if (BMODE == 2) {
        int col = colTile + r;
        bPtr = B + ((size_t)(col / PP) * HW_ + aux[col]) * CCH + s * 16;
    } else if (BMODE == 3) {
        int px = colTile + r;
        int c2 = aux[px];
        bPtr = ((c2 >= 0) ? (P + (size_t)c2 * CCH) : (B + (size_t)px * CCH)) + s * 16;
    } else {
        bPtr = B + (size_t)(colTile + r) * ldb + s * 16;
    }

    float acc[4][4][4];
    #pragma unroll
    for (int i = 0; i < 4; i++)
        #pragma unroll
        for (int j = 0; j < 4; j++)
            #pragma unroll
            for (int rr = 0; rr < 4; rr++) acc[i][j][rr] = 0.f;

    const int nCh = Kd >> 5;   // BK = 32
    const uint32_t sOffA = (uint32_t)s * STG_W + (uint32_t)r * 8u;
    const uint32_t sOffB = 2u * STG_W + sOffA;

    uint4 ua0 = reinterpret_cast<const uint4*>(aPtr)[0];
    uint4 ua1 = reinterpret_cast<const uint4*>(aPtr)[1];
    uint4 ub0 = reinterpret_cast<const uint4*>(bPtr)[0];
    uint4 ub1 = reinterpret_cast<const uint4*>(bPtr)[1];

    stperm(sh + sOffA, xr, ua0, ua1);
    stperm(sh + sOffB, xr, ub0, ub1);
    if (nCh > 1) {
        aPtr += 32; bPtr += 32;
        ua0 = reinterpret_cast<const uint4*>(aPtr)[0];
        ua1 = reinterpret_cast<const uint4*>(aPtr)[1];
        ub0 = reinterpret_cast<const uint4*>(bPtr)[0];
        ub1 = reinterpret_cast<const uint4*>(bPtr)[1];
    }
    __syncthreads();

    for (int ch = 0; ch < nCh; ch++) {
        if (ch + 1 < nCh) {
            const uint32_t Sn = (uint32_t)((ch + 1) & 1) * STAGE_W;
            stperm(sh + Sn + sOffA, xr, ua0, ua1);
            stperm(sh + Sn + sOffB, xr, ub0, ub1);
            if (ch + 2 < nCh) {
                aPtr += 32; bPtr += 32;
                ua0 = reinterpret_cast<const uint4*>(aPtr)[0];
                ua1 = reinterpret_cast<const uint4*>(aPtr)[1];
                ub0 = reinterpret_cast<const uint4*>(bPtr)[0];
                ub1 = reinterpret_cast<const uint4*>(bPtr)[1];
            }
        }
        const uint32_t S = (uint32_t)(ch & 1) * STAGE_W;
        #pragma unroll
        for (int ss = 0; ss < 2; ss++) {
            const uint32_t* Ab = sh + S + (uint32_t)ss * STG_W;
            const uint32_t* Bb = sh + S + 2u * STG_W + (uint32_t)ss * STG_W;
            uint2 aF[4][2];
            #pragma unroll
            for (int i = 0; i < 4; i++) {
                const uint32_t r0 = (uint32_t)(wr * 64 + i * 16 + g);
                aF[i][0] = *reinterpret_cast<const uint2*>(Ab + r0 * 8u + xq);
                aF[i][1] = *reinterpret_cast<const uint2*>(Ab + (r0 + 8u) * 8u + xq);
            }
            #pragma unroll
            for (int j = 0; j < 4; j++) {
                const uint32_t n0 = (uint32_t)(wc * 32 + j * 8 + g);
                uint2 bF = *reinterpret_cast<const uint2*>(Bb + n0 * 8u + xq);
                #pragma unroll
                for (int i = 0; i < 4; i++)
                    mma16(acc[i][j], aF[i][0].x, aF[i][1].x, aF[i][0].y, aF[i][1].y,
                          bF.x, bF.y);
            }
        }
        __syncthreads();
    }

    // ---- bias + relu ----
    #pragma unroll
    for (int i = 0; i < 4; i++) {
        const int m0 = rowTile + wr * 64 + i * 16 + g;
        const float bv0 = bias[m0], bv1 = bias[m0 + 8];
        #pragma unroll
        for (int j = 0; j < 4; j++) {
            acc[i][j][0] += bv0; acc[i][j][1] += bv0;
            acc[i][j][2] += bv1; acc[i][j][3] += bv1;
            if (RELU) {
                acc[i][j][0] = fmaxf(acc[i][j][0], 0.f);
                acc[i][j][1] = fmaxf(acc[i][j][1], 0.f);
                acc[i][j][2] = fmaxf(acc[i][j][2], 0.f);
                acc[i][j][3] = fmaxf(acc[i][j][3], 0.f);
            }
        }
    }

    float* stg = reinterpret_cast<float*>(sh);
    if (STORE_T) {
        // ---- single-shot staged epilogue: all warps stage 128x132, 2 syncs ----
        // staging banks: addr = nl*132 + ml; within a warp (8q+g)%32 -> all distinct.
        #pragma unroll
        for (int j = 0; j < 4; j++) {
            const int nl = wc * 32 + j * 8 + 2 * q;
            #pragma unroll
            for (int i = 0; i < 4; i++) {
                const int ml = wr * 64 + i * 16 + g;
                stg[nl * 132 + ml]           = acc[i][j][0];
                stg[(nl + 1) * 132 + ml]     = acc[i][j][1];
                stg[nl * 132 + ml + 8]       = acc[i][j][2];
                stg[(nl + 1) * 132 + ml + 8] = acc[i][j][3];
            }
        }
        __syncthreads();
        const int c0 = t >> 3;             // 0..31
        const int mb = (t & 7) * 4;        // 0,4,...,28
        #pragma unroll
        for (int cg = 0; cg < 4; cg++) {
            const int cl = c0 + cg * 32;
            const int n = colTile + cl;
            if (n < Ncols) {
                #pragma unroll
                for (int it = 0; it < 4; it++) {
                    const int ml = mb + it * 32;
                    const int m = rowTile + ml;
                    if (m < M) {
                        float4 v = *reinterpret_cast<float4*>(&stg[cl * 132 + ml]);
                        uint2 h = make_uint2(pack_h2(v.x, v.y), pack_h2(v.z, v.w));
                        *reinterpret_cast<uint2*>(C + (size_t)n * ldc + m) = h;
                        if (C2) *reinterpret_cast<uint2*>(C2 + (size_t)n * ldc + m) = h;
                    }
                }
            }
        }
    } else {
        // ---- 4-pass m-major epilogue (proven; used by fuse GEMM only) ----
        #pragma unroll
        for (int pass = 0; pass < 4; pass++) {
            __syncthreads();
            if (wr == (pass >> 1)) {
                #pragma unroll
                for (int ii = 0; ii < 2; ii++) {
                    const int i = (pass & 1) * 2 + ii;
                    const int rl = ii * 16 + g;
                    #pragma unroll
                    for (int j = 0; j < 4; j++) {
                        const int nl = wc * 32 + j * 8 + 2 * q;
                        stg[rl * 132 + nl]           = acc[i][j][0];
                        stg[rl * 132 + nl + 1]       = acc[i][j][1];
                        stg[(rl + 8) * 132 + nl]     = acc[i][j][2];
                        stg[(rl + 8) * 132 + nl + 1] = acc[i][j][3];
                    }
                }
            }
            __syncthreads();
            const int rr = t >> 3;
            const int m = rowTile + pass * 32 + rr;
            if (m < M) {
                #pragma unroll
                for (int it = 0; it < 4; it++) {
                    const int nl = (t & 7) * 4 + it * 32;
                    float4 v = *reinterpret_cast<float4*>(&stg[rr * 132 + nl]);
                    uint2 h = make_uint2(pack_h2(v.x, v.y), pack_h2(v.z, v.w));
                    *reinterpret_cast<uint2*>(C + (size_t)m * ldc + colTile + nl) = h;
                }
            }
        }
    }
}

// ---------------- weight packs: fp32 -> fp16 ----------------
__global__ void packw_k(const float* __restrict__ src, __half* __restrict__ dst, int n)
{
    int i = blockIdx.x*blockDim.x + threadIdx.x;
    if (i < n) dst[i] = __float2half_rn(src[i]);
}
// pack the 5 late weights in one launch
__global__ void pack5_k(const float* w0, const float* w1, const float* w2,
                        const float* wl, const float* wf,
                        __half* d0, __half* d1, __half* d2, __half* dl, __half* df)
{
    const int NF = 256*FCIN, NC = 256*CCH;
    for (int i = blockIdx.x*blockDim.x + threadIdx.x; i < 4*NF + NC;
         i += gridDim.x*blockDim.x) {
        if (i < NF)             d0[i]        = __float2half_rn(w0[i]);
        else if (i < 2*NF)      d1[i-NF]     = __float2half_rn(w1[i-NF]);
        else if (i < 3*NF)      d2[i-2*NF]   = __float2half_rn(w2[i-2*NF]);
        else if (i < 4*NF)      dl[i-3*NF]   = __float2half_rn(wl[i-3*NF]);
        else                    df[i-4*NF]   = __float2half_rn(wf[i-4*NF]);
    }
}

// ---------------- batched 2D transpose -> fp16 pixel-major ----------------
__global__ void transpose_k(const float* __restrict__ in, __half* __restrict__ out16,
                            int R, int Cc)
{
    __shared__ float tile[32][33];
    const int b = blockIdx.z;
    const float* ip = in + (size_t)b*R*Cc;
    __half*      oh = out16 + (size_t)b*R*Cc;
    int x = blockIdx.x*32 + threadIdx.x;
    #pragma unroll
    for (int j = 0; j < 32; j += 8) {
        int y = blockIdx.y*32 + threadIdx.y + j;
        if (y < R && x < Cc) tile[threadIdx.y+j][threadIdx.x] = ip[(size_t)y*Cc + x];
    }
    __syncthreads();
    int x2 = blockIdx.y*32 + threadIdx.x;
    #pragma unroll
    for (int j = 0; j < 32; j += 8) {
        int y2 = blockIdx.x*32 + threadIdx.y + j;
        if (y2 < Cc && x2 < R)
            oh[(size_t)y2*R + x2] = __float2half_rn(tile[threadIdx.x][threadIdx.y+j]);
    }
}

// sem transpose into padded fp16 pixel-major buffer
__global__ void transposeS_k(const float* __restrict__ in, __half* __restrict__ out16)
{
    __shared__ float tile[32][33];
    int x = blockIdx.x*32 + threadIdx.x;
    #pragma unroll
    for (int j = 0; j < 32; j += 8) {
        int y = blockIdx.y*32 + threadIdx.y + j;
        if (x < SPIX) tile[threadIdx.y+j][threadIdx.x] = in[(size_t)y*SPIX + x];
    }
    __syncthreads();
    int pix = blockIdx.x*32 + threadIdx.y;
    int c   = blockIdx.y*32 + threadIdx.x;
    #pragma unroll
    for (int j = 0; j < 32; j += 8) {
        if (pix + j < SPIX)
            out16[(size_t)(pix + j)*CCH + c] = __float2half_rn(tile[threadIdx.x][threadIdx.y+j]);
    }
}

// ---------------- stack class weights -> fp16 (zero-padded to 256 rows) ----------------
__global__ void wid_k(const float* __restrict__ wi, const float* __restrict__ bi,
                      const float* __restrict__ wd, const float* __restrict__ bd,
                      __half* __restrict__ dst)
{
    for (int i = threadIdx.x + blockIdx.x*blockDim.x; i < 256*CCH; i += blockDim.x*gridDim.x) {
        int r = i >> 8, c = i & 255;
        float v = (r < KCLS) ? wi[r*CCH + c] : (r < 160 ? wd[(r-KCLS)*CCH + c] : 0.f);
        dst[i] = __float2half_rn(v);
    }
    if (blockIdx.x == 0)
        for (int i = threadIdx.x; i < 256; i += blockDim.x)
            g_Bid[i] = (i < KCLS) ? bi[i] : (i < 160 ? bd[i-KCLS] : 0.f);
}

// ---------------- per-ROI label-selected maps: direct from channel-major input ----------------
// fp32 exact (feeds topk). Coalesced: lanes cover consecutive pixels p, loop over c.
__global__ void class_select_k(const float* __restrict__ inst,
                               const float* __restrict__ w_inst, const float* __restrict__ b_inst,
                               const float* __restrict__ w_det,  const float* __restrict__ b_det,
                               const int* __restrict__ labels, float* __restrict__ out)
{
    __shared__ float swi[CCH], swd[CCH];
    const int n = blockIdx.x;
    const int p = blockIdx.y * 112 + threadIdx.x;   // 7 parts of 112
    const int lab = labels[n];
    const int t = threadIdx.x;
    for (int i = t; i < CCH; i += 128) { swi[i] = w_inst[lab*CCH + i]; swd[i] = w_det[lab*CCH + i]; }
    __syncthreads();
    if (t >= 112) return;
    const float* f = inst + (size_t)n*CCH*HW_ + p;
    float si = 0.f, sd = 0.f;
    #pragma unroll 4
    for (int c = 0; c < CCH; c++) {
        float v = f[(size_t)c*HW_];
        si = fmaf(v, swi[c], si);
        sd = fmaf(v, swd[c], sd);
    }
    out[n*HW_ + p]        = si + b_inst[lab];
    out[NPIX + n*HW_ + p] = sd + b_det[lab];
}

// ---------------- top-196 of 784 per ROI ----------------
__global__ void topk_k(const float* __restrict__ det)
{
    __shared__ float sv[1024];
    __shared__ int   si[1024];
    const int n = blockIdx.x, t = threadIdx.x;
    for (int i = t; i < 1024; i += 512) {
        sv[i] = (i < HW_) ? det[NPIX + n*HW_ + i] : -3.4e38f;
        si[i] = i;
    }
    __syncthreads();
    for (int k2 = 2; k2 <= 1024; k2 <<= 1)
        for (int j = k2 >> 1; j > 0; j >>= 1) {
            int i = 2*t - (t & (j-1));
            int r = i + j;
            bool desc = ((i & k2) == 0);
            float vl = sv[i], vr = sv[r];
            bool sw = desc ? (vl < vr) : (vl > vr);
            if (sw) {
                sv[i] = vr; sv[r] = vl;
                int tmp = si[i]; si[i] = si[r]; si[r] = tmp;
            }
            __syncthreads();
        }
    if (t < PP) g_idx[n*PP + t] = si[t];
}

// ---------------- per-point: bilinear 'fine' (fp16 in) -> X0 fp16 rows 0..255 ----------------
__global__ void gather_k(const float* __restrict__ rois,
                         const __half* __restrict__ semT, __half* __restrict__ X0)
{
    const int col = blockIdx.x;
    const int n = col / PP;
    const int c = threadIdx.x;
    const int pix = g_idx[col];
    const float x1 = __ldg(rois + n*5 + 1), y1 = __ldg(rois + n*5 + 2);
    const float x2 = __ldg(rois + n*5 + 3), y2 = __ldg(rois + n*5 + 4);
    const float relx = ((pix % MW_) + 0.5f) / (float)MW_;
    const float rely = ((pix / MW_) + 0.5f) / (float)MH_;
    const float px = (x1 + relx*(x2 - x1)) * 0.25f - 0.5f;
    const float py = (y1 + rely*(y2 - y1)) * 0.25f - 0.5f;
    const float x0f = floorf(px), y0f = floorf(py);
    const float wx = px - x0f, wy = py - y0f;
    const int ix0 = (int)x0f, iy0 = (int)y0f;
    const int x0c = min(max(ix0, 0), SW__-1),   x1c = min(max(ix0+1, 0), SW__-1);
    const int y0c = min(max(iy0, 0), SH__-1),   y1c = min(max(iy0+1, 0), SH__-1);
    const float vx0 = (ix0   >= 0 && ix0   < SW__) ? 1.f : 0.f;
    const float vx1 = (ix0+1 >= 0 && ix0+1 < SW__) ? 1.f : 0.f;
    const float vy0 = (iy0   >= 0 && iy0   < SH__) ? 1.f : 0.f;
    const float vy1 = (iy0+1 >= 0 && iy0+1 < SH__) ? 1.f : 0.f;
    const float w00 = (1.f-wx)*(1.f-wy)*vx0*vy0;
    const float w10 = wx*(1.f-wy)*vx1*vy0;
    const float w01 = (1.f-wx)*wy*vx0*vy1;
    const float w11 = wx*wy*vx1*vy1;
    float v = w00 * __half2float(semT[(size_t)(y0c*SW__ + x0c)*CCH + c])
            + w10 * __half2float(semT[(size_t)(y0c*SW__ + x1c)*CCH + c])
            + w01 * __half2float(semT[(size_t)(y1c*SW__ + x0c)*CCH + c])
            + w11 * __half2float(semT[(size_t)(y1c*SW__ + x1c)*CCH + c]);
    X0[(size_t)col*FCIN + c] = __float2half_rn(v);
}

// ---------------- pixel -> point-column map ----------------
__global__ void mapinit_k()
{
    for (int i = blockIdx.x*blockDim.x + threadIdx.x; i < NPIX; i += gridDim.x*blockDim.x)
        g_map[i] = -1;
}
__global__ void mapset_k()
{
    int col = blockIdx.x*blockDim.x + threadIdx.x;
    if (col < NCOL) {
        int n = col / PP;
        g_map[n*HW_ + g_idx[col]] = col;
    }
}

// ---------------- x2 bilinear upsample + relu (fp16 in, fp32 out) ----------------
__global__ void upsample_k(const __half* __restrict__ F16, float* __restrict__ out, int planeOff)
{
    __shared__ float sf[HW_];
    const int plane = blockIdx.x + planeOff;
    const int n = plane >> 8, c = plane & 255;
    const __half* f = F16 + (size_t)c*NPIX + (size_t)n*HW_;
    const int t = threadIdx.x;
    for (int i = t; i < HW_; i += blockDim.x) sf[i] = __half2float(f[i]);
    __syncthreads();
    float* o = out + 2*(size_t)NPIX + (size_t)plane*3136;
    for (int q4 = t; q4 < 784; q4 += blockDim.x) {
        const int oy = q4 / 14;
        const int xb = (q4 - oy*14) * 4;
        const float sy = oy*0.5f - 0.25f;
        const int iy = (int)floorf(sy);
        const float fy = sy - iy;
        const int y0c = max(iy, 0), y1c = min(iy+1, MH_-1);
        float4 v;
        float* vp = &v.x;
        #pragma unroll
        for (int j = 0; j < 4; j++) {
            const int ox = xb + j;
            const float sx = ox*0.5f - 0.25f;
            const int ix = (int)floorf(sx);
            const float fx = sx - ix;
            const int x0c = max(ix, 0), x1c = min(ix+1, MW_-1);
            float v0 = sf[y0c*MW_ + x0c]*(1.f-fx) + sf[y0c*MW_ + x1c]*fx;
            float v1 = sf[y1c*MW_ + x0c]*(1.f-fx) + sf[y1c*MW_ + x1c]*fx;
            vp[j] = fmaxf(v0*(1.f-fy) + v1*fy, 0.f);
        }
        *reinterpret_cast<float4*>(o + oy*56 + xb) = v;
    }
}

// ---------------- host orchestration (stream-forked graph) ----------------
extern "C" void kernel_launch(void* const* d_in, const int* in_sizes, int n_in,
                              void* d_out, int out_size)
{
    (void)out_size;
    const bool has_np = (n_in >= 21);
    auto IN = [&](int i) -> const void* {
        int j = (i >= 5 && !has_np) ? i - 1 : i;
        return d_in[j];
    };
    const float* inst_feats = (const float*)IN(0);
    const float* sem_feat   = (const float*)IN(1);
    const float* rois       = (const float*)IN(2);
    const int*   labels     = (const int*)  IN(3);
    const float* w_sem  = (const float*)IN(5);  const float* b_sem  = (const float*)IN(6);
    const float* w_inst = (const float*)IN(7);  const float* b_inst = (const float*)IN(8);
    const float* w_det  = (const float*)IN(9);  const float* b_det  = (const float*)IN(10);
    const float* fc_w0  = (const float*)IN(11); const float* fc_b0  = (const float*)IN(12);
    const float* fc_w1  = (const float*)IN(13); const float* fc_b1  = (const float*)IN(14);
    const float* fc_w2  = (const float*)IN(15); const float* fc_b2  = (const float*)IN(16);
    const float* w_log  = (const float*)IN(17); const float* b_log  = (const float*)IN(18);
    const float* w_fuse = (const float*)IN(19); const float* b_fuse = (const float*)IN(20);
    float* out = (float*)d_out;

    float *p_Bid;
    __half *p_semFT, *p_semT, *p_Ft16, *p_X0, *p_X1, *p_P, *p_F;
    __half *p_Wid, *p_Wsem, *p_W0, *p_W1, *p_W2, *p_Wlog, *p_Wfuse;
    int *p_idx, *p_map;
    cudaGetSymbolAddress((void**)&p_semFT, g_semFT16);
    cudaGetSymbolAddress((void**)&p_semT,  g_semT16);
    cudaGetSymbolAddress((void**)&p_Ft16,  g_Ft16);
    cudaGetSymbolAddress((void**)&p_X0,    g_X016);
    cudaGetSymbolAddress((void**)&p_X1,    g_X116);
    cudaGetSymbolAddress((void**)&p_P,     g_P16);
    cudaGetSymbolAddress((void**)&p_F,     g_F16);
    cudaGetSymbolAddress((void**)&p_Wid,   g_Wid16);
    cudaGetSymbolAddress((void**)&p_Bid,   g_Bid);
    cudaGetSymbolAddress((void**)&p_Wsem,  g_Wsem16);
    cudaGetSymbolAddress((void**)&p_W0,    g_W016);
    cudaGetSymbolAddress((void**)&p_W1,    g_W116);
    cudaGetSymbolAddress((void**)&p_W2,    g_W216);
    cudaGetSymbolAddress((void**)&p_Wlog,  g_Wlog16);
    cudaGetSymbolAddress((void**)&p_Wfuse, g_Wfuse16);
    cudaGetSymbolAddress((void**)&p_idx,   g_idx);
    cudaGetSymbolAddress((void**)&p_map,   g_map);

    cudaFuncSetAttribute(mgemm<0, true, true >, cudaFuncAttributeMaxDynamicSharedMemorySize, MG_SMEM_T);
    cudaFuncSetAttribute(mgemm<0, true, false>, cudaFuncAttributeMaxDynamicSharedMemorySize, MG_SMEM_T);
    cudaFuncSetAttribute(mgemm<2, true, false>, cudaFuncAttributeMaxDynamicSharedMemorySize, MG_SMEM_T);
    cudaFuncSetAttribute(mgemm<3, false, true>, cudaFuncAttributeMaxDynamicSharedMemorySize, MG_SMEM_N);

    cudaStream_t s1;
    cudaStreamCreateWithFlags(&s1, cudaStreamNonBlocking);
    cudaEvent_t eFork, eIdx, eG, eFA, eJoin;
    cudaEventCreateWithFlags(&eFork, cudaEventDisableTiming);
    cudaEventCreateWithFlags(&eIdx,  cudaEventDisableTiming);
    cudaEventCreateWithFlags(&eG,    cudaEventDisableTiming);
    cudaEventCreateWithFlags(&eFA,   cudaEventDisableTiming);
    cudaEventCreateWithFlags(&eJoin, cudaEventDisableTiming);

    // ---- fork immediately ----
    mapinit_k<<<392, 256>>>();
    cudaEventRecord(eFork, 0);

    // ---- s1: semantic branch (sem pack -> transpose -> sem GEMM) ----
    cudaStreamWaitEvent(s1, eFork, 0);
    packw_k<<<(256*CCH + 255)/256, 256, 0, s1>>>(w_sem, p_Wsem, 256*CCH);
    transposeS_k<<<dim3(1250, 8), dim3(32, 8), 0, s1>>>(sem_feat, p_semFT);
    mgemm<0, true, true><<<dim3(313, 2), 256, MG_SMEM_T, s1>>>(p_Wsem, p_semFT, p_semT, nullptr, b_sem,
                                                               nullptr, nullptr, 256, 256, SPIX, 256, 256);

    // ---- s0: class select (direct from input; no transpose dep) + topk ----
    class_select_k<<<dim3(NB, 7), 128>>>(inst_feats, w_inst, b_inst, w_det, b_det, labels, out);
    topk_k<<<NB, 512>>>(out);
    mapset_k<<<(NCOL + 255)/256, 256>>>();
    cudaEventRecord(eIdx, 0);

    // ---- s1: bilinear fine (needs semT + idx) ----
    cudaStreamWaitEvent(s1, eIdx, 0);
    gather_k<<<NCOL, 256, 0, s1>>>(rois, p_semT, p_X0);
    cudaEventRecord(eG, s1);

    // ---- s0: instance transpose + late weight packs + class-weight stack ----
    transpose_k<<<dim3(25, 8, NB), dim3(32, 8)>>>(inst_feats, p_Ft16, CCH, HW_);
    wid_k<<<64, 256>>>(w_inst, b_inst, w_det, b_det, p_Wid);
    pack5_k<<<592, 256>>>(fc_w0, fc_w1, fc_w2, w_log, w_fuse, p_W0, p_W1, p_W2, p_Wlog, p_Wfuse);

    // ---- s0: c_inst/c_det tails (disjoint X0/X1 rows) ----
    mgemm<2, true, false><<<dim3(196, 2), 256, MG_SMEM_T>>>(p_Wid, p_Ft16, p_X0 + 256, p_X1 + 256, p_Bid,
                                                            nullptr, p_idx, 160, 256, NCOL, 0, FCIN);
    cudaStreamWaitEvent(0, eG, 0);

    // ---- s0: MLP chain + logits ----
    mgemm<0, true, true ><<<dim3(196, 2), 256, MG_SMEM_T>>>(p_W0, p_X0, p_X1, nullptr, fc_b0,
                                                            nullptr, nullptr, 256, FCIN, NCOL, FCIN, FCIN);
    mgemm<0, true, true ><<<dim3(196, 2), 256, MG_SMEM_T>>>(p_W1, p_X1, p_X0, nullptr, fc_b1,
                                                            nullptr, nullptr, 256, FCIN, NCOL, FCIN, FCIN);
    mgemm<0, true, true ><<<dim3(196, 2), 256, MG_SMEM_T>>>(p_W2, p_X0, p_X1, nullptr, fc_b2,
                                                            nullptr, nullptr, 256, FCIN, NCOL, FCIN, FCIN);
    mgemm<0, true, false><<<dim3(196, 2), 256, MG_SMEM_T>>>(p_Wlog, p_X1, p_P, nullptr, b_log,
                                                            nullptr, nullptr, 256, FCIN, NCOL, FCIN, CCH);

    // ---- fuse split by image halves; upsample(first) overlaps fuse(second) ----
    mgemm<3, false, true><<<dim3(392, 2), 256, MG_SMEM_N>>>(p_Wfuse, p_Ft16, p_F, nullptr, b_fuse,
                                                            p_P, p_map, 256, 256, HALFPIX, 0, NPIX);
    cudaEventRecord(eFA, 0);
    mgemm<3, false, true><<<dim3(392, 2), 256, MG_SMEM_N>>>(p_Wfuse, p_Ft16 + (size_t)HALFPIX*CCH,
                                                            p_F + HALFPIX, nullptr, b_fuse,
                                                            p_P, p_map + HALFPIX, 256, 256, HALFPIX, 0, NPIX);
    cudaStreamWaitEvent(s1, eFA, 0);
    upsample_k<<<64*CCH, 256, 0, s1>>>(p_F, out, 0);
    upsample_k<<<64*CCH, 256>>>(p_F, out, 64*CCH);

    cudaEventRecord(eJoin, s1);
    cudaStreamWaitEvent(0, eJoin, 0);
}

// round 16
// speedup vs baseline: 1.8828x; 1.0488x over previous
#include <cuda_runtime.h>
#include <cuda_fp16.h>
#include <cstdint>
#include <math.h>

// ---------------- problem constants ----------------
#define NB   128
#define CCH  256
#define MH_  28
#define MW_  28
#define HW_  784
#define KCLS 80
#define PP   196
#define SH__ 200
#define SW__ 200
#define SPIX 40000          // 200*200
#define SPIXP 40192         // >= 313*128 (N-tile pad)
#define FCIN 416            // C + 2K
#define NCOL (NB*PP)        // 25088 point-columns
#define NPIX (NB*HW_)       // 100352 instance pixels
#define HALFPIX (NPIX/2)    // 50176 (64 images)

// ---------------- scratch (static device globals; no allocation) ----------------
__device__ uint4 g_semFT16[(size_t)SPIXP*CCH/8];
__device__ uint4 g_semT16 [(size_t)SPIX*CCH/8];
__device__ uint4 g_Ft16[(size_t)NPIX*CCH/8];
__device__ uint4 g_X016[(size_t)NCOL*FCIN/8];
__device__ uint4 g_X116[(size_t)NCOL*FCIN/8];
__device__ uint4 g_P16 [(size_t)NCOL*CCH/8];
__device__ uint4 g_F16 [(size_t)CCH*NPIX/8];
__device__ int   g_idx[NB*PP];
__device__ int   g_map[NPIX];
__device__ uint4 g_Wid16  [256*CCH/8];
__device__ float g_Bid[256];
__device__ uint4 g_Wsem16 [256*CCH/8];
__device__ uint4 g_W016   [256*FCIN/8];
__device__ uint4 g_W116   [256*FCIN/8];
__device__ uint4 g_W216   [256*FCIN/8];
__device__ uint4 g_Wlog16 [256*FCIN/8];
__device__ uint4 g_Wfuse16[256*CCH/8];

// ---------------- fp16 helpers ----------------
__device__ __forceinline__ uint32_t pack_h2(float lo, float hi) {
    uint32_t r; asm("cvt.rn.f16x2.f32 %0, %1, %2;" : "=r"(r) : "f"(hi), "f"(lo)); return r;
}
__device__ __forceinline__ void mma16(float* c,
                                      uint32_t a0, uint32_t a1, uint32_t a2, uint32_t a3,
                                      uint32_t b0, uint32_t b1) {
    asm volatile("mma.sync.aligned.m16n8k16.row.col.f32.f16.f16.f32 "
                 "{%0,%1,%2,%3}, {%4,%5,%6,%7}, {%8,%9}, {%0,%1,%2,%3};"
                 : "+f"(c[0]), "+f"(c[1]), "+f"(c[2]), "+f"(c[3])
                 : "r"(a0), "r"(a1), "r"(a2), "r"(a3), "r"(b0), "r"(b1));
}
__device__ __forceinline__ void stperm(uint32_t* base, uint32_t xr, uint4 u0, uint4 u1) {
    *reinterpret_cast<uint4*>(base + xr)        = make_uint4(u0.x, u1.x, u0.y, u1.y);
    *reinterpret_cast<uint4*>(base + (4u ^ xr)) = make_uint4(u0.z, u1.z, u0.w, u1.w);
}

// ================= fp16 tensor-core TN GEMM v7 (unchanged from R14 win) =================
#define STG_W   1028
#define STAGE_W (4*STG_W)
#define MG_SMEM_T 67584
#define MG_SMEM_N (2*STAGE_W*4)

template<int BMODE, bool STORE_T, bool RELU>
__global__ void __launch_bounds__(256, 2)
mgemm(const __half* __restrict__ A, const __half* __restrict__ B,
      __half* __restrict__ C, __half* __restrict__ C2,
      const float* __restrict__ bias,
      const __half* __restrict__ P, const int* __restrict__ aux,
      int M, int Kd, int Ncols, int ldb, int ldc)
{
    extern __shared__ uint32_t sh[];
    const int t = threadIdx.x;
    const int rowTile = blockIdx.y * 128;
    const int colTile = blockIdx.x * 128;
    const int lane = t & 31, wid = t >> 5;
    const int wr = wid & 1, wc = wid >> 1;
    const int g = lane >> 2, q = lane & 3;
    const uint32_t xq = (uint32_t)(2*q) ^ ((uint32_t)((lane >> 4) & 1) << 2);

    const int r = t >> 1;
    const int s = t & 1;
    const uint32_t xr = ((r >> 2) & 1) << 2;
    const __half* aPtr = A + (size_t)(rowTile + r) * Kd + s * 16;
    const __half* bPtr;
    if (BMODE == 2) {
        int col = colTile + r;
        bPtr = B + ((size_t)(col / PP) * HW_ + aux[col]) * CCH + s * 16;
    } else if (BMODE == 3) {
        int px = colTile + r;
        int c2 = aux[px];
        bPtr = ((c2 >= 0) ? (P + (size_t)c2 * CCH) : (B + (size_t)px * CCH)) + s * 16;
    } else {
        bPtr = B + (size_t)(colTile + r) * ldb + s * 16;
    }

    float acc[4][4][4];
    #pragma unroll
    for (int i = 0; i < 4; i++)
        #pragma unroll
        for (int j = 0; j < 4; j++)
            #pragma unroll
            for (int rr = 0; rr < 4; rr++) acc[i][j][rr] = 0.f;

    const int nCh = Kd >> 5;
    const uint32_t sOffA = (uint32_t)s * STG_W + (uint32_t)r * 8u;
    const uint32_t sOffB = 2u * STG_W + sOffA;

    uint4 ua0 = reinterpret_cast<const uint4*>(aPtr)[0];
    uint4 ua1 = reinterpret_cast<const uint4*>(aPtr)[1];
    uint4 ub0 = reinterpret_cast<const uint4*>(bPtr)[0];
    uint4 ub1 = reinterpret_cast<const uint4*>(bPtr)[1];

    stperm(sh + sOffA, xr, ua0, ua1);
    stperm(sh + sOffB, xr, ub0, ub1);
    if (nCh > 1) {
        aPtr += 32; bPtr += 32;
        ua0 = reinterpret_cast<const uint4*>(aPtr)[0];
        ua1 = reinterpret_cast<const uint4*>(aPtr)[1];
        ub0 = reinterpret_cast<const uint4*>(bPtr)[0];
        ub1 = reinterpret_cast<const uint4*>(bPtr)[1];
    }
    __syncthreads();

    for (int ch = 0; ch < nCh; ch++) {
        if (ch + 1 < nCh) {
            const uint32_t Sn = (uint32_t)((ch + 1) & 1) * STAGE_W;
            stperm(sh + Sn + sOffA, xr, ua0, ua1);
            stperm(sh + Sn + sOffB, xr, ub0, ub1);
            if (ch + 2 < nCh) {
                aPtr += 32; bPtr += 32;
                ua0 = reinterpret_cast<const uint4*>(aPtr)[0];
                ua1 = reinterpret_cast<const uint4*>(aPtr)[1];
                ub0 = reinterpret_cast<const uint4*>(bPtr)[0];
                ub1 = reinterpret_cast<const uint4*>(bPtr)[1];
            }
        }
        const uint32_t S = (uint32_t)(ch & 1) * STAGE_W;
        #pragma unroll
        for (int ss = 0; ss < 2; ss++) {
            const uint32_t* Ab = sh + S + (uint32_t)ss * STG_W;
            const uint32_t* Bb = sh + S + 2u * STG_W + (uint32_t)ss * STG_W;
            uint2 aF[4][2];
            #pragma unroll
            for (int i = 0; i < 4; i++) {
                const uint32_t r0 = (uint32_t)(wr * 64 + i * 16 + g);
                aF[i][0] = *reinterpret_cast<const uint2*>(Ab + r0 * 8u + xq);
                aF[i][1] = *reinterpret_cast<const uint2*>(Ab + (r0 + 8u) * 8u + xq);
            }
            #pragma unroll
            for (int j = 0; j < 4; j++) {
                const uint32_t n0 = (uint32_t)(wc * 32 + j * 8 + g);
                uint2 bF = *reinterpret_cast<const uint2*>(Bb + n0 * 8u + xq);
                #pragma unroll
                for (int i = 0; i < 4; i++)
                    mma16(acc[i][j], aF[i][0].x, aF[i][1].x, aF[i][0].y, aF[i][1].y,
                          bF.x, bF.y);
            }
        }
        __syncthreads();
    }

    #pragma unroll
    for (int i = 0; i < 4; i++) {
        const int m0 = rowTile + wr * 64 + i * 16 + g;
        const float bv0 = bias[m0], bv1 = bias[m0 + 8];
        #pragma unroll
        for (int j = 0; j < 4; j++) {
            acc[i][j][0] += bv0; acc[i][j][1] += bv0;
            acc[i][j][2] += bv1; acc[i][j][3] += bv1;
            if (RELU) {
                acc[i][j][0] = fmaxf(acc[i][j][0], 0.f);
                acc[i][j][1] = fmaxf(acc[i][j][1], 0.f);
                acc[i][j][2] = fmaxf(acc[i][j][2], 0.f);
                acc[i][j][3] = fmaxf(acc[i][j][3], 0.f);
            }
        }
    }

    float* stg = reinterpret_cast<float*>(sh);
    if (STORE_T) {
        // single-shot staged epilogue: 128x132, 2 syncs
        #pragma unroll
        for (int j = 0; j < 4; j++) {
            const int nl = wc * 32 + j * 8 + 2 * q;
            #pragma unroll
            for (int i = 0; i < 4; i++) {
                const int ml = wr * 64 + i * 16 + g;
                stg[nl * 132 + ml]           = acc[i][j][0];
                stg[(nl + 1) * 132 + ml]     = acc[i][j][1];
                stg[nl * 132 + ml + 8]       = acc[i][j][2];
                stg[(nl + 1) * 132 + ml + 8] = acc[i][j][3];
            }
        }
        __syncthreads();
        const int c0 = t >> 3;
        const int mb = (t & 7) * 4;
        #pragma unroll
        for (int cg = 0; cg < 4; cg++) {
            const int cl = c0 + cg * 32;
            const int n = colTile + cl;
            if (n < Ncols) {
                #pragma unroll
                for (int it = 0; it < 4; it++) {
                    const int ml = mb + it * 32;
                    const int m = rowTile + ml;
                    if (m < M) {
                        float4 v = *reinterpret_cast<float4*>(&stg[cl * 132 + ml]);
                        uint2 h = make_uint2(pack_h2(v.x, v.y), pack_h2(v.z, v.w));
                        *reinterpret_cast<uint2*>(C + (size_t)n * ldc + m) = h;
                        if (C2) *reinterpret_cast<uint2*>(C2 + (size_t)n * ldc + m) = h;
                    }
                }
            }
        }
    } else {
        // 4-pass m-major epilogue (fuse GEMM)
        #pragma unroll
        for (int pass = 0; pass < 4; pass++) {
            __syncthreads();
            if (wr == (pass >> 1)) {
                #pragma unroll
                for (int ii = 0; ii < 2; ii++) {
                    const int i = (pass & 1) * 2 + ii;
                    const int rl = ii * 16 + g;
                    #pragma unroll
                    for (int j = 0; j < 4; j++) {
                        const int nl = wc * 32 + j * 8 + 2 * q;
                        stg[rl * 132 + nl]           = acc[i][j][0];
                        stg[rl * 132 + nl + 1]       = acc[i][j][1];
                        stg[(rl + 8) * 132 + nl]     = acc[i][j][2];
                        stg[(rl + 8) * 132 + nl + 1] = acc[i][j][3];
                    }
                }
            }
            __syncthreads();
            const int rr = t >> 3;
            const int m = rowTile + pass * 32 + rr;
            if (m < M) {
                #pragma unroll
                for (int it = 0; it < 4; it++) {
                    const int nl = (t & 7) * 4 + it * 32;
                    float4 v = *reinterpret_cast<float4*>(&stg[rr * 132 + nl]);
                    uint2 h = make_uint2(pack_h2(v.x, v.y), pack_h2(v.z, v.w));
                    *reinterpret_cast<uint2*>(C + (size_t)m * ldc + colTile + nl) = h;
                }
            }
        }
    }
}

// ---------------- weight packs ----------------
__global__ void packw_k(const float* __restrict__ src, __half* __restrict__ dst, int n)
{
    int i = blockIdx.x*blockDim.x + threadIdx.x;
    if (i < n) dst[i] = __float2half_rn(src[i]);
}
__global__ void pack5_k(const float* w0, const float* w1, const float* w2,
                        const float* wl, const float* wf,
                        __half* d0, __half* d1, __half* d2, __half* dl, __half* df)
{
    const int NF = 256*FCIN, NC = 256*CCH;
    for (int i = blockIdx.x*blockDim.x + threadIdx.x; i < 4*NF + NC;
         i += gridDim.x*blockDim.x) {
        if (i < NF)             d0[i]        = __float2half_rn(w0[i]);
        else if (i < 2*NF)      d1[i-NF]     = __float2half_rn(w1[i-NF]);
        else if (i < 3*NF)      d2[i-2*NF]   = __float2half_rn(w2[i-2*NF]);
        else if (i < 4*NF)      dl[i-3*NF]   = __float2half_rn(wl[i-3*NF]);
        else                    df[i-4*NF]   = __float2half_rn(wf[i-4*NF]);
    }
}

// ---------------- FUSED: class_select + instance transpose (fp16) + map init ----------------
// One pass over the 100MB input. Dot accumulation order (c ascending) is identical to the
// previous class_select_k -> bit-identical maps -> identical topk indices.
__global__ void csxp_k(const float* __restrict__ inst,
                       const float* __restrict__ w_inst, const float* __restrict__ b_inst,
                       const float* __restrict__ w_det,  const float* __restrict__ b_det,
                       const int* __restrict__ labels,
                       __half* __restrict__ Ft16, float* __restrict__ out)
{
    __shared__ float tile[32][113];
    __shared__ float swi[CCH], swd[CCH];
    const int n  = blockIdx.x;
    const int p0 = blockIdx.y * 112;           // 7 parts x 112 = 784
    const int lab = labels[n];
    const int t = threadIdx.x;
    for (int i = t; i < CCH; i += 256) {
        swi[i] = w_inst[lab*CCH + i];
        swd[i] = w_det[lab*CCH + i];
    }
    float si = 0.f, sd = 0.f;
    const float* src = inst + (size_t)n*CCH*HW_ + p0;
    __half* dst = Ft16 + ((size_t)n*HW_ + p0)*CCH;

    for (int c0 = 0; c0 < CCH; c0 += 32) {
        __syncthreads();
        // load 32c x 112p tile (coalesced along p)
        for (int idx = t; idx < 32*112; idx += 256) {
            int cc = idx / 112, pp = idx - cc*112;
            tile[cc][pp] = src[(size_t)(c0 + cc)*HW_ + pp];
        }
        __syncthreads();
        // transposed fp16 write (coalesced along c; smem stride 113 -> conflict-free)
        for (int idx = t; idx < 32*112; idx += 256) {
            int cc = idx & 31, pp = idx >> 5;
            dst[(size_t)pp*CCH + c0 + cc] = __float2half_rn(tile[cc][pp]);
        }
        // dot accumulate, c ascending (order identical to previous kernel)
        if (t < 112) {
            #pragma unroll 8
            for (int cc = 0; cc < 32; cc++) {
                float v = tile[cc][t];
                si = fmaf(v, swi[c0 + cc], si);
                sd = fmaf(v, swd[c0 + cc], sd);
            }
        }
    }
    if (t < 112) {
        const int p = p0 + t;
        out[n*HW_ + p]        = si + b_inst[lab];
        out[NPIX + n*HW_ + p] = sd + b_det[lab];
        g_map[n*HW_ + p] = -1;
    }
}

// ---------------- sem transpose into padded fp16 pixel-major buffer ----------------
__global__ void transposeS_k(const float* __restrict__ in, __half* __restrict__ out16)
{
    __shared__ float tile[32][33];
    int x = blockIdx.x*32 + threadIdx.x;
    #pragma unroll
    for (int j = 0; j < 32; j += 8) {
        int y = blockIdx.y*32 + threadIdx.y + j;
        if (x < SPIX) tile[threadIdx.y+j][threadIdx.x] = in[(size_t)y*SPIX + x];
    }
    __syncthreads();
    int pix = blockIdx.x*32 + threadIdx.y;
    int c   = blockIdx.y*32 + threadIdx.x;
    #pragma unroll
    for (int j = 0; j < 32; j += 8) {
        if (pix + j < SPIX)
            out16[(size_t)(pix + j)*CCH + c] = __float2half_rn(tile[threadIdx.x][threadIdx.y+j]);
    }
}

// ---------------- stack class weights -> fp16 ----------------
__global__ void wid_k(const float* __restrict__ wi, const float* __restrict__ bi,
                      const float* __restrict__ wd, const float* __restrict__ bd,
                      __half* __restrict__ dst)
{
    for (int i = threadIdx.x + blockIdx.x*blockDim.x; i < 256*CCH; i += blockDim.x*gridDim.x) {
        int r = i >> 8, c = i & 255;
        float v = (r < KCLS) ? wi[r*CCH + c] : (r < 160 ? wd[(r-KCLS)*CCH + c] : 0.f);
        dst[i] = __float2half_rn(v);
    }
    if (blockIdx.x == 0)
        for (int i = threadIdx.x; i < 256; i += blockDim.x)
            g_Bid[i] = (i < KCLS) ? bi[i] : (i < 160 ? bd[i-KCLS] : 0.f);
}

// ---------------- top-196 of 784 per ROI ----------------
__global__ void topk_k(const float* __restrict__ det)
{
    __shared__ float sv[1024];
    __shared__ int   si[1024];
    const int n = blockIdx.x, t = threadIdx.x;
    for (int i = t; i < 1024; i += 512) {
        sv[i] = (i < HW_) ? det[NPIX + n*HW_ + i] : -3.4e38f;
        si[i] = i;
    }
    __syncthreads();
    for (int k2 = 2; k2 <= 1024; k2 <<= 1)
        for (int j = k2 >> 1; j > 0; j >>= 1) {
            int i = 2*t - (t & (j-1));
            int r = i + j;
            bool desc = ((i & k2) == 0);
            float vl = sv[i], vr = sv[r];
            bool sw = desc ? (vl < vr) : (vl > vr);
            if (sw) {
                sv[i] = vr; sv[r] = vl;
                int tmp = si[i]; si[i] = si[r]; si[r] = tmp;
            }
            __syncthreads();
        }
    if (t < PP) g_idx[n*PP + t] = si[t];
}

// ---------------- per-point bilinear 'fine' -> X0 fp16 rows 0..255 ----------------
__global__ void gather_k(const float* __restrict__ rois,
                         const __half* __restrict__ semT, __half* __restrict__ X0)
{
    const int col = blockIdx.x;
    const int n = col / PP;
    const int c = threadIdx.x;
    const int pix = g_idx[col];
    const float x1 = __ldg(rois + n*5 + 1), y1 = __ldg(rois + n*5 + 2);
    const float x2 = __ldg(rois + n*5 + 3), y2 = __ldg(rois + n*5 + 4);
    const float relx = ((pix % MW_) + 0.5f) / (float)MW_;
    const float rely = ((pix / MW_) + 0.5f) / (float)MH_;
    const float px = (x1 + relx*(x2 - x1)) * 0.25f - 0.5f;
    const float py = (y1 + rely*(y2 - y1)) * 0.25f - 0.5f;
    const float x0f = floorf(px), y0f = floorf(py);
    const float wx = px - x0f, wy = py - y0f;
    const int ix0 = (int)x0f, iy0 = (int)y0f;
    const int x0c = min(max(ix0, 0), SW__-1),   x1c = min(max(ix0+1, 0), SW__-1);
    const int y0c = min(max(iy0, 0), SH__-1),   y1c = min(max(iy0+1, 0), SH__-1);
    const float vx0 = (ix0   >= 0 && ix0   < SW__) ? 1.f : 0.f;
    const float vx1 = (ix0+1 >= 0 && ix0+1 < SW__) ? 1.f : 0.f;
    const float vy0 = (iy0   >= 0 && iy0   < SH__) ? 1.f : 0.f;
    const float vy1 = (iy0+1 >= 0 && iy0+1 < SH__) ? 1.f : 0.f;
    const float w00 = (1.f-wx)*(1.f-wy)*vx0*vy0;
    const float w10 = wx*(1.f-wy)*vx1*vy0;
    const float w01 = (1.f-wx)*wy*vx0*vy1;
    const float w11 = wx*wy*vx1*vy1;
    float v = w00 * __half2float(semT[(size_t)(y0c*SW__ + x0c)*CCH + c])
            + w10 * __half2float(semT[(size_t)(y0c*SW__ + x1c)*CCH + c])
            + w01 * __half2float(semT[(size_t)(y1c*SW__ + x0c)*CCH + c])
            + w11 * __half2float(semT[(size_t)(y1c*SW__ + x1c)*CCH + c]);
    X0[(size_t)col*FCIN + c] = __float2half_rn(v);
}

// ---------------- pixel -> point-column map ----------------
__global__ void mapset_k()
{
    int col = blockIdx.x*blockDim.x + threadIdx.x;
    if (col < NCOL) {
        int n = col / PP;
        g_map[n*HW_ + g_idx[col]] = col;
    }
}

// ---------------- x2 bilinear upsample + relu (fp16 in, fp32 out) ----------------
__global__ void upsample_k(const __half* __restrict__ F16, float* __restrict__ out, int planeOff)
{
    __shared__ float sf[HW_];
    const int plane = blockIdx.x + planeOff;
    const int n = plane >> 8, c = plane & 255;
    const __half* f = F16 + (size_t)c*NPIX + (size_t)n*HW_;
    const int t = threadIdx.x;
    for (int i = t; i < HW_; i += blockDim.x) sf[i] = __half2float(f[i]);
    __syncthreads();
    float* o = out + 2*(size_t)NPIX + (size_t)plane*3136;
    for (int q4 = t; q4 < 784; q4 += blockDim.x) {
        const int oy = q4 / 14;
        const int xb = (q4 - oy*14) * 4;
        const float sy = oy*0.5f - 0.25f;
        const int iy = (int)floorf(sy);
        const float fy = sy - iy;
        const int y0c = max(iy, 0), y1c = min(iy+1, MH_-1);
        float4 v;
        float* vp = &v.x;
        #pragma unroll
        for (int j = 0; j < 4; j++) {
            const int ox = xb + j;
            const float sx = ox*0.5f - 0.25f;
            const int ix = (int)floorf(sx);
            const float fx = sx - ix;
            const int x0c = max(ix, 0), x1c = min(ix+1, MW_-1);
            float v0 = sf[y0c*MW_ + x0c]*(1.f-fx) + sf[y0c*MW_ + x1c]*fx;
            float v1 = sf[y1c*MW_ + x0c]*(1.f-fx) + sf[y1c*MW_ + x1c]*fx;
            vp[j] = fmaxf(v0*(1.f-fy) + v1*fy, 0.f);
        }
        *reinterpret_cast<float4*>(o + oy*56 + xb) = v;
    }
}

// ---------------- host orchestration (R14 topology: one extra stream, five events) ----------------
extern "C" void kernel_launch(void* const* d_in, const int* in_sizes, int n_in,
                              void* d_out, int out_size)
{
    (void)out_size;
    const bool has_np = (n_in >= 21);
    auto IN = [&](int i) -> const void* {
        int j = (i >= 5 && !has_np) ? i - 1 : i;
        return d_in[j];
    };
    const float* inst_feats = (const float*)IN(0);
    const float* sem_feat   = (const float*)IN(1);
    const float* rois       = (const float*)IN(2);
    const int*   labels     = (const int*)  IN(3);
    const float* w_sem  = (const float*)IN(5);  const float* b_sem  = (const float*)IN(6);
    const float* w_inst = (const float*)IN(7);  const float* b_inst = (const float*)IN(8);
    const float* w_det  = (const float*)IN(9);  const float* b_det  = (const float*)IN(10);
    const float* fc_w0  = (const float*)IN(11); const float* fc_b0  = (const float*)IN(12);
    const float* fc_w1  = (const float*)IN(13); const float* fc_b1  = (const float*)IN(14);
    const float* fc_w2  = (const float*)IN(15); const float* fc_b2  = (const float*)IN(16);
    const float* w_log  = (const float*)IN(17); const float* b_log  = (const float*)IN(18);
    const float* w_fuse = (const float*)IN(19); const float* b_fuse = (const float*)IN(20);
    float* out = (float*)d_out;

    float *p_Bid;
    __half *p_semFT, *p_semT, *p_Ft16, *p_X0, *p_X1, *p_P, *p_F;
    __half *p_Wid, *p_Wsem, *p_W0, *p_W1, *p_W2, *p_Wlog, *p_Wfuse;
    int *p_idx, *p_map;
    cudaGetSymbolAddress((void**)&p_semFT, g_semFT16);
    cudaGetSymbolAddress((void**)&p_semT,  g_semT16);
    cudaGetSymbolAddress((void**)&p_Ft16,  g_Ft16);
    cudaGetSymbolAddress((void**)&p_X0,    g_X016);
    cudaGetSymbolAddress((void**)&p_X1,    g_X116);
    cudaGetSymbolAddress((void**)&p_P,     g_P16);
    cudaGetSymbolAddress((void**)&p_F,     g_F16);
    cudaGetSymbolAddress((void**)&p_Wid,   g_Wid16);
    cudaGetSymbolAddress((void**)&p_Bid,   g_Bid);
    cudaGetSymbolAddress((void**)&p_Wsem,  g_Wsem16);
    cudaGetSymbolAddress((void**)&p_W0,    g_W016);
    cudaGetSymbolAddress((void**)&p_W1,    g_W116);
    cudaGetSymbolAddress((void**)&p_W2,    g_W216);
    cudaGetSymbolAddress((void**)&p_Wlog,  g_Wlog16);
    cudaGetSymbolAddress((void**)&p_Wfuse, g_Wfuse16);
    cudaGetSymbolAddress((void**)&p_idx,   g_idx);
    cudaGetSymbolAddress((void**)&p_map,   g_map);

    cudaFuncSetAttribute(mgemm<0, true, true >, cudaFuncAttributeMaxDynamicSharedMemorySize, MG_SMEM_T);
    cudaFuncSetAttribute(mgemm<0, true, false>, cudaFuncAttributeMaxDynamicSharedMemorySize, MG_SMEM_T);
    cudaFuncSetAttribute(mgemm<2, true, false>, cudaFuncAttributeMaxDynamicSharedMemorySize, MG_SMEM_T);
    cudaFuncSetAttribute(mgemm<3, false, true>, cudaFuncAttributeMaxDynamicSharedMemorySize, MG_SMEM_N);

    cudaStream_t s1;
    cudaStreamCreateWithFlags(&s1, cudaStreamNonBlocking);
    cudaEvent_t eFork, eIdx, eG, eFA, eJoin;
    cudaEventCreateWithFlags(&eFork, cudaEventDisableTiming);
    cudaEventCreateWithFlags(&eIdx,  cudaEventDisableTiming);
    cudaEventCreateWithFlags(&eG,    cudaEventDisableTiming);
    cudaEventCreateWithFlags(&eFA,   cudaEventDisableTiming);
    cudaEventCreateWithFlags(&eJoin, cudaEventDisableTiming);

    // ---- fork ----
    cudaEventRecord(eFork, 0);

    // ---- s1: semantic branch ----
    cudaStreamWaitEvent(s1, eFork, 0);
    packw_k<<<(256*CCH + 255)/256, 256, 0, s1>>>(w_sem, p_Wsem, 256*CCH);
    transposeS_k<<<dim3(1250, 8), dim3(32, 8), 0, s1>>>(sem_feat, p_semFT);
    mgemm<0, true, true><<<dim3(313, 2), 256, MG_SMEM_T, s1>>>(p_Wsem, p_semFT, p_semT, nullptr, b_sem,
                                                               nullptr, nullptr, 256, 256, SPIX, 256, 256);

    // ---- s0: fused class_select + Ft16 transpose + map init, then topk + mapset ----
    csxp_k<<<dim3(NB, 7), 256>>>(inst_feats, w_inst, b_inst, w_det, b_det, labels, p_Ft16, out);
    topk_k<<<NB, 512>>>(out);
    mapset_k<<<(NCOL + 255)/256, 256>>>();
    cudaEventRecord(eIdx, 0);

    // ---- s1: bilinear fine (needs semT + idx) ----
    cudaStreamWaitEvent(s1, eIdx, 0);
    gather_k<<<NCOL, 256, 0, s1>>>(rois, p_semT, p_X0);
    cudaEventRecord(eG, s1);

    // ---- s0: late weight packs + class-weight stack, then GEMM6 ----
    wid_k<<<64, 256>>>(w_inst, b_inst, w_det, b_det, p_Wid);
    pack5_k<<<592, 256>>>(fc_w0, fc_w1, fc_w2, w_log, w_fuse, p_W0, p_W1, p_W2, p_Wlog, p_Wfuse);
    mgemm<2, true, false><<<dim3(196, 2), 256, MG_SMEM_T>>>(p_Wid, p_Ft16, p_X0 + 256, p_X1 + 256, p_Bid,
                                                            nullptr, p_idx, 160, 256, NCOL, 0, FCIN);
    cudaStreamWaitEvent(0, eG, 0);

    // ---- s0: MLP chain + logits ----
    mgemm<0, true, true ><<<dim3(196, 2), 256, MG_SMEM_T>>>(p_W0, p_X0, p_X1, nullptr, fc_b0,
                                                            nullptr, nullptr, 256, FCIN, NCOL, FCIN, FCIN);
    mgemm<0, true, true ><<<dim3(196, 2), 256, MG_SMEM_T>>>(p_W1, p_X1, p_X0, nullptr, fc_b1,
                                                            nullptr, nullptr, 256, FCIN, NCOL, FCIN, FCIN);
    mgemm<0, true, true ><<<dim3(196, 2), 256, MG_SMEM_T>>>(p_W2, p_X0, p_X1, nullptr, fc_b2,
                                                            nullptr, nullptr, 256, FCIN, NCOL, FCIN, FCIN);
    mgemm<0, true, false><<<dim3(196, 2), 256, MG_SMEM_T>>>(p_Wlog, p_X1, p_P, nullptr, b_log,
                                                            nullptr, nullptr, 256, FCIN, NCOL, FCIN, CCH);

    // ---- fuse split by image halves; upsample(first) overlaps fuse(second) ----
    mgemm<3, false, true><<<dim3(392, 2), 256, MG_SMEM_N>>>(p_Wfuse, p_Ft16, p_F, nullptr, b_fuse,
                                                            p_P, p_map, 256, 256, HALFPIX, 0, NPIX);
    cudaEventRecord(eFA, 0);
    mgemm<3, false, true><<<dim3(392, 2), 256, MG_SMEM_N>>>(p_Wfuse, p_Ft16 + (size_t)HALFPIX*CCH,
                                                            p_F + HALFPIX, nullptr, b_fuse,
                                                            p_P, p_map + HALFPIX, 256, 256, HALFPIX, 0, NPIX);
    cudaStreamWaitEvent(s1, eFA, 0);
    upsample_k<<<64*CCH, 256, 0, s1>>>(p_F, out, 0);
    upsample_k<<<64*CCH, 256>>>(p_F, out, 64*CCH);

    cudaEventRecord(eJoin, s1);
    cudaStreamWaitEvent(0, eJoin, 0);
}

// round 17
// speedup vs baseline: 1.9804x; 1.0519x over previous
#include <cuda_runtime.h>
#include <cuda_fp16.h>
#include <cstdint>
#include <math.h>

// ---------------- problem constants ----------------
#define NB   128
#define CCH  256
#define MH_  28
#define MW_  28
#define HW_  784
#define KCLS 80
#define PP   196
#define SH__ 200
#define SW__ 200
#define SPIX 40000          // 200*200
#define SPIXP 40192         // >= 313*128 (N-tile pad)
#define FCIN 416            // C + 2K
#define NCOL (NB*PP)        // 25088 point-columns
#define NPIX (NB*HW_)       // 100352 instance pixels
#define HALFPIX (NPIX/2)    // 50176 (64 images)

// ---------------- scratch (static device globals; no allocation) ----------------
__device__ uint4 g_semFT16[(size_t)SPIXP*CCH/8];
__device__ uint4 g_semT16 [(size_t)SPIX*CCH/8];
__device__ uint4 g_Ft16[(size_t)NPIX*CCH/8];
__device__ uint4 g_X016[(size_t)NCOL*FCIN/8];
__device__ uint4 g_X116[(size_t)NCOL*FCIN/8];
__device__ uint4 g_P16 [(size_t)NCOL*CCH/8];
__device__ uint4 g_F16 [(size_t)CCH*NPIX/8];
__device__ int   g_idx[NB*PP];
__device__ int   g_map[NPIX];
__device__ uint4 g_Wid16  [256*CCH/8];
__device__ float g_Bid[256];
__device__ uint4 g_Wsem16 [256*CCH/8];
__device__ uint4 g_W016   [256*FCIN/8];
__device__ uint4 g_W116   [256*FCIN/8];
__device__ uint4 g_W216   [256*FCIN/8];
__device__ uint4 g_Wlog16 [256*FCIN/8];
__device__ uint4 g_Wfuse16[256*CCH/8];

// ---------------- fp16 helpers ----------------
__device__ __forceinline__ uint32_t pack_h2(float lo, float hi) {
    uint32_t r; asm("cvt.rn.f16x2.f32 %0, %1, %2;" : "=r"(r) : "f"(hi), "f"(lo)); return r;
}
__device__ __forceinline__ void mma16(float* c,
                                      uint32_t a0, uint32_t a1, uint32_t a2, uint32_t a3,
                                      uint32_t b0, uint32_t b1) {
    asm volatile("mma.sync.aligned.m16n8k16.row.col.f32.f16.f16.f32 "
                 "{%0,%1,%2,%3}, {%4,%5,%6,%7}, {%8,%9}, {%0,%1,%2,%3};"
                 : "+f"(c[0]), "+f"(c[1]), "+f"(c[2]), "+f"(c[3])
                 : "r"(a0), "r"(a1), "r"(a2), "r"(a3), "r"(b0), "r"(b1));
}
__device__ __forceinline__ void stperm(uint32_t* base, uint32_t xr, uint4 u0, uint4 u1) {
    *reinterpret_cast<uint4*>(base + xr)        = make_uint4(u0.x, u1.x, u0.y, u1.y);
    *reinterpret_cast<uint4*>(base + (4u ^ xr)) = make_uint4(u0.z, u1.z, u0.w, u1.w);
}

// ================= fp16 tensor-core TN GEMM v7 (unchanged — proven) =================
#define STG_W   1028
#define STAGE_W (4*STG_W)
#define MG_SMEM_T 67584
#define MG_SMEM_N (2*STAGE_W*4)

template<int BMODE, bool STORE_T, bool RELU>
__global__ void __launch_bounds__(256, 2)
mgemm(const __half* __restrict__ A, const __half* __restrict__ B,
      __half* __restrict__ C, __half* __restrict__ C2,
      const float* __restrict__ bias,
      const __half* __restrict__ P, const int* __restrict__ aux,
      int M, int Kd, int Ncols, int ldb, int ldc)
{
    extern __shared__ uint32_t sh[];
    const int t = threadIdx.x;
    const int rowTile = blockIdx.y * 128;
    const int colTile = blockIdx.x * 128;
    const int lane = t & 31, wid = t >> 5;
    const int wr = wid & 1, wc = wid >> 1;
    const int g = lane >> 2, q = lane & 3;
    const uint32_t xq = (uint32_t)(2*q) ^ ((uint32_t)((lane >> 4) & 1) << 2);

    const int r = t >> 1;
    const int s = t & 1;
    const uint32_t xr = ((r >> 2) & 1) << 2;
    const __half* aPtr = A + (size_t)(rowTile + r) * Kd + s * 16;
    const __half* bPtr;
    if (BMODE == 2) {
        int col = colTile + r;
        bPtr = B + ((size_t)(col / PP) * HW_ + aux[col]) * CCH + s * 16;
    } else if (BMODE == 3) {
        int px = colTile + r;
        int c2 = aux[px];
        bPtr = ((c2 >= 0) ? (P + (size_t)c2 * CCH) : (B + (size_t)px * CCH)) + s * 16;
    } else {
        bPtr = B + (size_t)(colTile + r) * ldb + s * 16;
    }

    float acc[4][4][4];
    #pragma unroll
    for (int i = 0; i < 4; i++)
        #pragma unroll
        for (int j = 0; j < 4; j++)
            #pragma unroll
            for (int rr = 0; rr < 4; rr++) acc[i][j][rr] = 0.f;

    const int nCh = Kd >> 5;
    const uint32_t sOffA = (uint32_t)s * STG_W + (uint32_t)r * 8u;
    const uint32_t sOffB = 2u * STG_W + sOffA;

    uint4 ua0 = reinterpret_cast<const uint4*>(aPtr)[0];
    uint4 ua1 = reinterpret_cast<const uint4*>(aPtr)[1];
    uint4 ub0 = reinterpret_cast<const uint4*>(bPtr)[0];
    uint4 ub1 = reinterpret_cast<const uint4*>(bPtr)[1];

    stperm(sh + sOffA, xr, ua0, ua1);
    stperm(sh + sOffB, xr, ub0, ub1);
    if (nCh > 1) {
        aPtr += 32; bPtr += 32;
        ua0 = reinterpret_cast<const uint4*>(aPtr)[0];
        ua1 = reinterpret_cast<const uint4*>(aPtr)[1];
        ub0 = reinterpret_cast<const uint4*>(bPtr)[0];
        ub1 = reinterpret_cast<const uint4*>(bPtr)[1];
    }
    __syncthreads();

    for (int ch = 0; ch < nCh; ch++) {
        if (ch + 1 < nCh) {
            const uint32_t Sn = (uint32_t)((ch + 1) & 1) * STAGE_W;
            stperm(sh + Sn + sOffA, xr, ua0, ua1);
            stperm(sh + Sn + sOffB, xr, ub0, ub1);
            if (ch + 2 < nCh) {
                aPtr += 32; bPtr += 32;
                ua0 = reinterpret_cast<const uint4*>(aPtr)[0];
                ua1 = reinterpret_cast<const uint4*>(aPtr)[1];
                ub0 = reinterpret_cast<const uint4*>(bPtr)[0];
                ub1 = reinterpret_cast<const uint4*>(bPtr)[1];
            }
        }
        const uint32_t S = (uint32_t)(ch & 1) * STAGE_W;
        #pragma unroll
        for (int ss = 0; ss < 2; ss++) {
            const uint32_t* Ab = sh + S + (uint32_t)ss * STG_W;
            const uint32_t* Bb = sh + S + 2u * STG_W + (uint32_t)ss * STG_W;
            uint2 aF[4][2];
            #pragma unroll
            for (int i = 0; i < 4; i++) {
                const uint32_t r0 = (uint32_t)(wr * 64 + i * 16 + g);
                aF[i][0] = *reinterpret_cast<const uint2*>(Ab + r0 * 8u + xq);
                aF[i][1] = *reinterpret_cast<const uint2*>(Ab + (r0 + 8u) * 8u + xq);
            }
            #pragma unroll
            for (int j = 0; j < 4; j++) {
                const uint32_t n0 = (uint32_t)(wc * 32 + j * 8 + g);
                uint2 bF = *reinterpret_cast<const uint2*>(Bb + n0 * 8u + xq);
                #pragma unroll
                for (int i = 0; i < 4; i++)
                    mma16(acc[i][j], aF[i][0].x, aF[i][1].x, aF[i][0].y, aF[i][1].y,
                          bF.x, bF.y);
            }
        }
        __syncthreads();
    }

    #pragma unroll
    for (int i = 0; i < 4; i++) {
        const int m0 = rowTile + wr * 64 + i * 16 + g;
        const float bv0 = bias[m0], bv1 = bias[m0 + 8];
        #pragma unroll
        for (int j = 0; j < 4; j++) {
            acc[i][j][0] += bv0; acc[i][j][1] += bv0;
            acc[i][j][2] += bv1; acc[i][j][3] += bv1;
            if (RELU) {
                acc[i][j][0] = fmaxf(acc[i][j][0], 0.f);
                acc[i][j][1] = fmaxf(acc[i][j][1], 0.f);
                acc[i][j][2] = fmaxf(acc[i][j][2], 0.f);
                acc[i][j][3] = fmaxf(acc[i][j][3], 0.f);
            }
        }
    }

    float* stg = reinterpret_cast<float*>(sh);
    if (STORE_T) {
        // single-shot staged epilogue: 128x132, 2 syncs
        #pragma unroll
        for (int j = 0; j < 4; j++) {
            const int nl = wc * 32 + j * 8 + 2 * q;
            #pragma unroll
            for (int i = 0; i < 4; i++) {
                const int ml = wr * 64 + i * 16 + g;
                stg[nl * 132 + ml]           = acc[i][j][0];
                stg[(nl + 1) * 132 + ml]     = acc[i][j][1];
                stg[nl * 132 + ml + 8]       = acc[i][j][2];
                stg[(nl + 1) * 132 + ml + 8] = acc[i][j][3];
            }
        }
        __syncthreads();
        const int c0 = t >> 3;
        const int mb = (t & 7) * 4;
        #pragma unroll
        for (int cg = 0; cg < 4; cg++) {
            const int cl = c0 + cg * 32;
            const int n = colTile + cl;
            if (n < Ncols) {
                #pragma unroll
                for (int it = 0; it < 4; it++) {
                    const int ml = mb + it * 32;
                    const int m = rowTile + ml;
                    if (m < M) {
                        float4 v = *reinterpret_cast<float4*>(&stg[cl * 132 + ml]);
                        uint2 h = make_uint2(pack_h2(v.x, v.y), pack_h2(v.z, v.w));
                        *reinterpret_cast<uint2*>(C + (size_t)n * ldc + m) = h;
                        if (C2) *reinterpret_cast<uint2*>(C2 + (size_t)n * ldc + m) = h;
                    }
                }
            }
        }
    } else {
        // 4-pass m-major epilogue (fuse GEMM)
        #pragma unroll
        for (int pass = 0; pass < 4; pass++) {
            __syncthreads();
            if (wr == (pass >> 1)) {
                #pragma unroll
                for (int ii = 0; ii < 2; ii++) {
                    const int i = (pass & 1) * 2 + ii;
                    const int rl = ii * 16 + g;
                    #pragma unroll
                    for (int j = 0; j < 4; j++) {
                        const int nl = wc * 32 + j * 8 + 2 * q;
                        stg[rl * 132 + nl]           = acc[i][j][0];
                        stg[rl * 132 + nl + 1]       = acc[i][j][1];
                        stg[(rl + 8) * 132 + nl]     = acc[i][j][2];
                        stg[(rl + 8) * 132 + nl + 1] = acc[i][j][3];
                    }
                }
            }
            __syncthreads();
            const int rr = t >> 3;
            const int m = rowTile + pass * 32 + rr;
            if (m < M) {
                #pragma unroll
                for (int it = 0; it < 4; it++) {
                    const int nl = (t & 7) * 4 + it * 32;
                    float4 v = *reinterpret_cast<float4*>(&stg[rr * 132 + nl]);
                    uint2 h = make_uint2(pack_h2(v.x, v.y), pack_h2(v.z, v.w));
                    *reinterpret_cast<uint2*>(C + (size_t)m * ldc + colTile + nl) = h;
                }
            }
        }
    }
}

// ---------------- weight packs ----------------
__global__ void packw_k(const float* __restrict__ src, __half* __restrict__ dst, int n)
{
    int i = blockIdx.x*blockDim.x + threadIdx.x;
    if (i < n) dst[i] = __float2half_rn(src[i]);
}
__global__ void pack5_k(const float* w0, const float* w1, const float* w2,
                        const float* wl, const float* wf,
                        __half* d0, __half* d1, __half* d2, __half* dl, __half* df)
{
    const int NF = 256*FCIN, NC = 256*CCH;
    for (int i = blockIdx.x*blockDim.x + threadIdx.x; i < 4*NF + NC;
         i += gridDim.x*blockDim.x) {
        if (i < NF)             d0[i]        = __float2half_rn(w0[i]);
        else if (i < 2*NF)      d1[i-NF]     = __float2half_rn(w1[i-NF]);
        else if (i < 3*NF)      d2[i-2*NF]   = __float2half_rn(w2[i-2*NF]);
        else if (i < 4*NF)      dl[i-3*NF]   = __float2half_rn(wl[i-3*NF]);
        else                    df[i-4*NF]   = __float2half_rn(wf[i-4*NF]);
    }
}

// ---------------- FUSED: class_select + instance transpose (fp16) + map init ----------------
// Division-free indexing; half2 transposed writes. Tile contents and the c-ascending dot
// accumulation order are bit-identical to R16 -> identical maps -> identical topk indices.
__global__ void csxp_k(const float* __restrict__ inst,
                       const float* __restrict__ w_inst, const float* __restrict__ b_inst,
                       const float* __restrict__ w_det,  const float* __restrict__ b_det,
                       const int* __restrict__ labels,
                       __half* __restrict__ Ft16, float* __restrict__ out)
{
    __shared__ float tile[32][113];
    __shared__ float swi[CCH], swd[CCH];
    const int n  = blockIdx.x;
    const int p0 = blockIdx.y * 112;           // 7 parts x 112 = 784
    const int lab = labels[n];
    const int t = threadIdx.x;
    for (int i = t; i < CCH; i += 256) {
        swi[i] = w_inst[lab*CCH + i];
        swd[i] = w_det[lab*CCH + i];
    }
    float si = 0.f, sd = 0.f;
    const float* src = inst + (size_t)n*CCH*HW_ + p0;
    __half* dst = Ft16 + ((size_t)n*HW_ + p0)*CCH;

    // induction start: cc0 = t/112, pp0 = t%112 (computed once, branch-free-cheap)
    const int cc0 = (t >= 224) ? 2 : ((t >= 112) ? 1 : 0);
    const int pp0 = t - cc0 * 112;

    for (int c0 = 0; c0 < CCH; c0 += 32) {
        __syncthreads();
        // load 32c x 112p tile; idx+=256 => cc+=2, pp+=32 with one wrap fix (256 = 2*112+32)
        {
            int cc = cc0, pp = pp0;
            #pragma unroll
            for (int it = 0; it < 14; it++) {   // 32*112/256 = 14
                tile[cc][pp] = src[(size_t)(c0 + cc)*HW_ + pp];
                pp += 32; cc += 2;
                if (pp >= 112) { pp -= 112; cc += 1; }
            }
        }
        __syncthreads();
        // transposed half2 write: 32*112/2 = 1792 items, 7 iters (conflict-free LDS pairs)
        #pragma unroll
        for (int it = 0; it < 7; it++) {
            int idx = t + it * 256;
            int c2 = idx & 15, pp = idx >> 4;
            __half2 h = __floats2half2_rn(tile[2*c2][pp], tile[2*c2 + 1][pp]);
            *reinterpret_cast<__half2*>(dst + (size_t)pp*CCH + c0 + 2*c2) = h;
        }
        // dot accumulate, c ascending (order identical)
        if (t < 112) {
            #pragma unroll 8
            for (int cc = 0; cc < 32; cc++) {
                float v = tile[cc][t];
                si = fmaf(v, swi[c0 + cc], si);
                sd = fmaf(v, swd[c0 + cc], sd);
            }
        }
    }
    if (t < 112) {
        const int p = p0 + t;
        out[n*HW_ + p]        = si + b_inst[lab];
        out[NPIX + n*HW_ + p] = sd + b_det[lab];
        g_map[n*HW_ + p] = -1;
    }
}

// ---------------- sem transpose into padded fp16 pixel-major buffer ----------------
__global__ void transposeS_k(const float* __restrict__ in, __half* __restrict__ out16)
{
    __shared__ float tile[32][33];
    int x = blockIdx.x*32 + threadIdx.x;
    #pragma unroll
    for (int j = 0; j < 32; j += 8) {
        int y = blockIdx.y*32 + threadIdx.y + j;
        if (x < SPIX) tile[threadIdx.y+j][threadIdx.x] = in[(size_t)y*SPIX + x];
    }
    __syncthreads();
    int pix = blockIdx.x*32 + threadIdx.y;
    int c   = blockIdx.y*32 + threadIdx.x;
    #pragma unroll
    for (int j = 0; j < 32; j += 8) {
        if (pix + j < SPIX)
            out16[(size_t)(pix + j)*CCH + c] = __float2half_rn(tile[threadIdx.x][threadIdx.y+j]);
    }
}

// ---------------- stack class weights -> fp16 ----------------
__global__ void wid_k(const float* __restrict__ wi, const float* __restrict__ bi,
                      const float* __restrict__ wd, const float* __restrict__ bd,
                      __half* __restrict__ dst)
{
    for (int i = threadIdx.x + blockIdx.x*blockDim.x; i < 256*CCH; i += blockDim.x*gridDim.x) {
        int r = i >> 8, c = i & 255;
        float v = (r < KCLS) ? wi[r*CCH + c] : (r < 160 ? wd[(r-KCLS)*CCH + c] : 0.f);
        dst[i] = __float2half_rn(v);
    }
    if (blockIdx.x == 0)
        for (int i = threadIdx.x; i < 256; i += blockDim.x)
            g_Bid[i] = (i < KCLS) ? bi[i] : (i < 160 ? bd[i-KCLS] : 0.f);
}

// ---------------- top-196 of 784 per ROI ----------------
__global__ void topk_k(const float* __restrict__ det)
{
    __shared__ float sv[1024];
    __shared__ int   si[1024];
    const int n = blockIdx.x, t = threadIdx.x;
    for (int i = t; i < 1024; i += 512) {
        sv[i] = (i < HW_) ? det[NPIX + n*HW_ + i] : -3.4e38f;
        si[i] = i;
    }
    __syncthreads();
    for (int k2 = 2; k2 <= 1024; k2 <<= 1)
        for (int j = k2 >> 1; j > 0; j >>= 1) {
            int i = 2*t - (t & (j-1));
            int r = i + j;
            bool desc = ((i & k2) == 0);
            float vl = sv[i], vr = sv[r];
            bool sw = desc ? (vl < vr) : (vl > vr);
            if (sw) {
                sv[i] = vr; sv[r] = vl;
                int tmp = si[i]; si[i] = si[r]; si[r] = tmp;
            }
            __syncthreads();
        }
    if (t < PP) g_idx[n*PP + t] = si[t];
}

// ---------------- per-point bilinear 'fine' -> X0 fp16 (half2; 128 thr x 2 ch) ----------------
__global__ void gather_k(const float* __restrict__ rois,
                         const __half* __restrict__ semT, __half* __restrict__ X0)
{
    const int col = blockIdx.x;
    const int n = col / PP;
    const int tid = threadIdx.x;             // 0..127, covers channels 2*tid, 2*tid+1
    const int pix = g_idx[col];
    const float x1 = __ldg(rois + n*5 + 1), y1 = __ldg(rois + n*5 + 2);
    const float x2 = __ldg(rois + n*5 + 3), y2 = __ldg(rois + n*5 + 4);
    const float relx = ((pix % MW_) + 0.5f) / (float)MW_;
    const float rely = ((pix / MW_) + 0.5f) / (float)MH_;
    const float px = (x1 + relx*(x2 - x1)) * 0.25f - 0.5f;
    const float py = (y1 + rely*(y2 - y1)) * 0.25f - 0.5f;
    const float x0f = floorf(px), y0f = floorf(py);
    const float wx = px - x0f, wy = py - y0f;
    const int ix0 = (int)x0f, iy0 = (int)y0f;
    const int x0c = min(max(ix0, 0), SW__-1),   x1c = min(max(ix0+1, 0), SW__-1);
    const int y0c = min(max(iy0, 0), SH__-1),   y1c = min(max(iy0+1, 0), SH__-1);
    const float vx0 = (ix0   >= 0 && ix0   < SW__) ? 1.f : 0.f;
    const float vx1 = (ix0+1 >= 0 && ix0+1 < SW__) ? 1.f : 0.f;
    const float vy0 = (iy0   >= 0 && iy0   < SH__) ? 1.f : 0.f;
    const float vy1 = (iy0+1 >= 0 && iy0+1 < SH__) ? 1.f : 0.f;
    const float w00 = (1.f-wx)*(1.f-wy)*vx0*vy0;
    const float w10 = wx*(1.f-wy)*vx1*vy0;
    const float w01 = (1.f-wx)*wy*vx0*vy1;
    const float w11 = wx*wy*vx1*vy1;
    const __half2* s00 = reinterpret_cast<const __half2*>(semT + (size_t)(y0c*SW__ + x0c)*CCH);
    const __half2* s10 = reinterpret_cast<const __half2*>(semT + (size_t)(y0c*SW__ + x1c)*CCH);
    const __half2* s01 = reinterpret_cast<const __half2*>(semT + (size_t)(y1c*SW__ + x0c)*CCH);
    const __half2* s11 = reinterpret_cast<const __half2*>(semT + (size_t)(y1c*SW__ + x1c)*CCH);
    float2 f00 = __half22float2(s00[tid]);
    float2 f10 = __half22float2(s10[tid]);
    float2 f01 = __half22float2(s01[tid]);
    float2 f11 = __half22float2(s11[tid]);
    float vA = w00*f00.x + w10*f10.x + w01*f01.x + w11*f11.x;
    float vB = w00*f00.y + w10*f10.y + w01*f01.y + w11*f11.y;
    reinterpret_cast<__half2*>(X0 + (size_t)col*FCIN)[tid] = __floats2half2_rn(vA, vB);
}

// ---------------- pixel -> point-column map ----------------
__global__ void mapset_k()
{
    int col = blockIdx.x*blockDim.x + threadIdx.x;
    if (col < NCOL) {
        int n = col / PP;
        g_map[n*HW_ + g_idx[col]] = col;
    }
}

// ---------------- x2 bilinear upsample + relu (fp16 in, fp32 out) ----------------
__global__ void upsample_k(const __half* __restrict__ F16, float* __restrict__ out, int planeOff)
{
    __shared__ float sf[HW_];
    const int plane = blockIdx.x + planeOff;
    const int n = plane >> 8, c = plane & 255;
    const __half* f = F16 + (size_t)c*NPIX + (size_t)n*HW_;
    const int t = threadIdx.x;
    for (int i = t; i < HW_; i += blockDim.x) sf[i] = __half2float(f[i]);
    __syncthreads();
    float* o = out + 2*(size_t)NPIX + (size_t)plane*3136;
    for (int q4 = t; q4 < 784; q4 += blockDim.x) {
        const int oy = q4 / 14;
        const int xb = (q4 - oy*14) * 4;
        const float sy = oy*0.5f - 0.25f;
        const int iy = (int)floorf(sy);
        const float fy = sy - iy;
        const int y0c = max(iy, 0), y1c = min(iy+1, MH_-1);
        float4 v;
        float* vp = &v.x;
        #pragma unroll
        for (int j = 0; j < 4; j++) {
            const int ox = xb + j;
            const float sx = ox*0.5f - 0.25f;
            const int ix = (int)floorf(sx);
            const float fx = sx - ix;
            const int x0c = max(ix, 0), x1c = min(ix+1, MW_-1);
            float v0 = sf[y0c*MW_ + x0c]*(1.f-fx) + sf[y0c*MW_ + x1c]*fx;
            float v1 = sf[y1c*MW_ + x0c]*(1.f-fx) + sf[y1c*MW_ + x1c]*fx;
            vp[j] = fmaxf(v0*(1.f-fy) + v1*fy, 0.f);
        }
        *reinterpret_cast<float4*>(o + oy*56 + xb) = v;
    }
}

// ---------------- host orchestration (R14/R16 topology: one extra stream, five events) ----------------
extern "C" void kernel_launch(void* const* d_in, const int* in_sizes, int n_in,
                              void* d_out, int out_size)
{
    (void)out_size;
    const bool has_np = (n_in >= 21);
    auto IN = [&](int i) -> const void* {
        int j = (i >= 5 && !has_np) ? i - 1 : i;
        return d_in[j];
    };
    const float* inst_feats = (const float*)IN(0);
    const float* sem_feat   = (const float*)IN(1);
    const float* rois       = (const float*)IN(2);
    const int*   labels     = (const int*)  IN(3);
    const float* w_sem  = (const float*)IN(5);  const float* b_sem  = (const float*)IN(6);
    const float* w_inst = (const float*)IN(7);  const float* b_inst = (const float*)IN(8);
    const float* w_det  = (const float*)IN(9);  const float* b_det  = (const float*)IN(10);
    const float* fc_w0  = (const float*)IN(11); const float* fc_b0  = (const float*)IN(12);
    const float* fc_w1  = (const float*)IN(13); const float* fc_b1  = (const float*)IN(14);
    const float* fc_w2  = (const float*)IN(15); const float* fc_b2  = (const float*)IN(16);
    const float* w_log  = (const float*)IN(17); const float* b_log  = (const float*)IN(18);
    const float* w_fuse = (const float*)IN(19); const float* b_fuse = (const float*)IN(20);
    float* out = (float*)d_out;

    float *p_Bid;
    __half *p_semFT, *p_semT, *p_Ft16, *p_X0, *p_X1, *p_P, *p_F;
    __half *p_Wid, *p_Wsem, *p_W0, *p_W1, *p_W2, *p_Wlog, *p_Wfuse;
    int *p_idx, *p_map;
    cudaGetSymbolAddress((void**)&p_semFT, g_semFT16);
    cudaGetSymbolAddress((void**)&p_semT,  g_semT16);
    cudaGetSymbolAddress((void**)&p_Ft16,  g_Ft16);
    cudaGetSymbolAddress((void**)&p_X0,    g_X016);
    cudaGetSymbolAddress((void**)&p_X1,    g_X116);
    cudaGetSymbolAddress((void**)&p_P,     g_P16);
    cudaGetSymbolAddress((void**)&p_F,     g_F16);
    cudaGetSymbolAddress((void**)&p_Wid,   g_Wid16);
    cudaGetSymbolAddress((void**)&p_Bid,   g_Bid);
    cudaGetSymbolAddress((void**)&p_Wsem,  g_Wsem16);
    cudaGetSymbolAddress((void**)&p_W0,    g_W016);
    cudaGetSymbolAddress((void**)&p_W1,    g_W116);
    cudaGetSymbolAddress((void**)&p_W2,    g_W216);
    cudaGetSymbolAddress((void**)&p_Wlog,  g_Wlog16);
    cudaGetSymbolAddress((void**)&p_Wfuse, g_Wfuse16);
    cudaGetSymbolAddress((void**)&p_idx,   g_idx);
    cudaGetSymbolAddress((void**)&p_map,   g_map);

    cudaFuncSetAttribute(mgemm<0, true, true >, cudaFuncAttributeMaxDynamicSharedMemorySize, MG_SMEM_T);
    cudaFuncSetAttribute(mgemm<0, true, false>, cudaFuncAttributeMaxDynamicSharedMemorySize, MG_SMEM_T);
    cudaFuncSetAttribute(mgemm<2, true, false>, cudaFuncAttributeMaxDynamicSharedMemorySize, MG_SMEM_T);
    cudaFuncSetAttribute(mgemm<3, false, true>, cudaFuncAttributeMaxDynamicSharedMemorySize, MG_SMEM_N);

    cudaStream_t s1;
    cudaStreamCreateWithFlags(&s1, cudaStreamNonBlocking);
    cudaEvent_t eFork, eIdx, eG, eFA, eJoin;
    cudaEventCreateWithFlags(&eFork, cudaEventDisableTiming);
    cudaEventCreateWithFlags(&eIdx,  cudaEventDisableTiming);
    cudaEventCreateWithFlags(&eG,    cudaEventDisableTiming);
    cudaEventCreateWithFlags(&eFA,   cudaEventDisableTiming);
    cudaEventCreateWithFlags(&eJoin, cudaEventDisableTiming);

    // ---- fork ----
    cudaEventRecord(eFork, 0);

    // ---- s1: semantic branch ----
    cudaStreamWaitEvent(s1, eFork, 0);
    packw_k<<<(256*CCH + 255)/256, 256, 0, s1>>>(w_sem, p_Wsem, 256*CCH);
    transposeS_k<<<dim3(1250, 8), dim3(32, 8), 0, s1>>>(sem_feat, p_semFT);
    mgemm<0, true, true><<<dim3(313, 2), 256, MG_SMEM_T, s1>>>(p_Wsem, p_semFT, p_semT, nullptr, b_sem,
                                                               nullptr, nullptr, 256, 256, SPIX, 256, 256);

    // ---- s0: fused class_select + Ft16 transpose + map init, then topk + mapset ----
    csxp_k<<<dim3(NB, 7), 256>>>(inst_feats, w_inst, b_inst, w_det, b_det, labels, p_Ft16, out);
    topk_k<<<NB, 512>>>(out);
    mapset_k<<<(NCOL + 255)/256, 256>>>();
    cudaEventRecord(eIdx, 0);

    // ---- s1: bilinear fine (needs semT + idx) ----
    cudaStreamWaitEvent(s1, eIdx, 0);
    gather_k<<<NCOL, 128, 0, s1>>>(rois, p_semT, p_X0);
    cudaEventRecord(eG, s1);

    // ---- s0: late weight packs + class-weight stack, then GEMM6 ----
    wid_k<<<64, 256>>>(w_inst, b_inst, w_det, b_det, p_Wid);
    pack5_k<<<592, 256>>>(fc_w0, fc_w1, fc_w2, w_log, w_fuse, p_W0, p_W1, p_W2, p_Wlog, p_Wfuse);
    mgemm<2, true, false><<<dim3(196, 2), 256, MG_SMEM_T>>>(p_Wid, p_Ft16, p_X0 + 256, p_X1 + 256, p_Bid,
                                                            nullptr, p_idx, 160, 256, NCOL, 0, FCIN);
    cudaStreamWaitEvent(0, eG, 0);

    // ---- s0: MLP chain + logits ----
    mgemm<0, true, true ><<<dim3(196, 2), 256, MG_SMEM_T>>>(p_W0, p_X0, p_X1, nullptr, fc_b0,
                                                            nullptr, nullptr, 256, FCIN, NCOL, FCIN, FCIN);
    mgemm<0, true, true ><<<dim3(196, 2), 256, MG_SMEM_T>>>(p_W1, p_X1, p_X0, nullptr, fc_b1,
                                                            nullptr, nullptr, 256, FCIN, NCOL, FCIN, FCIN);
    mgemm<0, true, true ><<<dim3(196, 2), 256, MG_SMEM_T>>>(p_W2, p_X0, p_X1, nullptr, fc_b2,
                                                            nullptr, nullptr, 256, FCIN, NCOL, FCIN, FCIN);
    mgemm<0, true, false><<<dim3(196, 2), 256, MG_SMEM_T>>>(p_Wlog, p_X1, p_P, nullptr, b_log,
                                                            nullptr, nullptr, 256, FCIN, NCOL, FCIN, CCH);

    // ---- fuse split by image halves; upsample(first) overlaps fuse(second) ----
    mgemm<3, false, true><<<dim3(392, 2), 256, MG_SMEM_N>>>(p_Wfuse, p_Ft16, p_F, nullptr, b_fuse,
                                                            p_P, p_map, 256, 256, HALFPIX, 0, NPIX);
    cudaEventRecord(eFA, 0);
    mgemm<3, false, true><<<dim3(392, 2), 256, MG_SMEM_N>>>(p_Wfuse, p_Ft16 + (size_t)HALFPIX*CCH,
                                                            p_F + HALFPIX, nullptr, b_fuse,
                                                            p_P, p_map + HALFPIX, 256, 256, HALFPIX, 0, NPIX);
    cudaStreamWaitEvent(s1, eFA, 0);
    upsample_k<<<64*CCH, 256, 0, s1>>>(p_F, out, 0);
    upsample_k<<<64*CCH, 256>>>(p_F, out, 64*CCH);

    cudaEventRecord(eJoin, s1);
    cudaStreamWaitEvent(0, eJoin, 0);
}